// round 6
// baseline (speedup 1.0000x reference)
#include <cuda_runtime.h>

// Problem constants
#define BB 2
#define SS 2048
#define DD 1024
#define HH 16
#define HD 64
#define BH (BB * HH)        // 32
#define MROWS (BB * SS)     // 4096

// ---------------------------------------------------------------------------
// Device scratch (no runtime allocation allowed)
// ---------------------------------------------------------------------------
__device__ float g_q[BH * SS * HD];                 // 16 MB  [bh][s][d]
__device__ float g_k[BH * SS * HD];                 // 16 MB
__device__ float g_v[BH * SS * HD];                 // 16 MB
__device__ float g_logits[(size_t)BH * SS * SS];    // 512 MB, per-CTA-private spill
__device__ float g_ao[(size_t)MROWS * DD];          // 16 MB  attention out, [B,S,D]

// ---------------------------------------------------------------------------
// QKV projection: C[m,n] = sum_k X[m,k] * Wqkv[n,k]
// M=4096, N=3072, K=1024. 64x64 tile, 256 threads, 4x4 per thread,
// double-buffered smem (k-tile 16) with register prefetch.
// Scatters output into g_q/g_k/g_v in [bh][s][d] layout.
// ---------------------------------------------------------------------------
__global__ __launch_bounds__(256, 2)
void qkv_gemm_kernel(const float* __restrict__ X, const float* __restrict__ W) {
    __shared__ float Xs[2][64][20];
    __shared__ float Ws[2][64][20];

    const int tid = threadIdx.x;
    const int ty = tid >> 4;          // 0..15
    const int tx = tid & 15;          // 0..15
    const int m0 = blockIdx.y << 6;
    const int n0 = blockIdx.x << 6;

    const int lr = tid >> 2;          // 0..63 (row within tile)
    const int lc = (tid & 3) << 2;    // 0,4,8,12 (col quad)

    const float* Xg = X + (size_t)(m0 + lr) * DD + lc;
    const float* Wg = W + (size_t)(n0 + lr) * DD + lc;

    float4 fx = *(const float4*)(Xg);
    float4 fw = *(const float4*)(Wg);
    *(float4*)&Xs[0][lr][lc] = fx;
    *(float4*)&Ws[0][lr][lc] = fw;
    __syncthreads();

    float acc[4][4];
#pragma unroll
    for (int i = 0; i < 4; ++i)
#pragma unroll
        for (int j = 0; j < 4; ++j) acc[i][j] = 0.f;

    const int NKT = DD / 16;  // 64
    for (int kt = 0; kt < NKT; ++kt) {
        const int cur = kt & 1;
        if (kt + 1 < NKT) {
            fx = *(const float4*)(Xg + (kt + 1) * 16);
            fw = *(const float4*)(Wg + (kt + 1) * 16);
        }
#pragma unroll
        for (int kk = 0; kk < 16; kk += 4) {
            float4 A[4], Bv[4];
            A[0] = *(const float4*)&Xs[cur][ty      ][kk];
            A[1] = *(const float4*)&Xs[cur][ty + 16 ][kk];
            A[2] = *(const float4*)&Xs[cur][ty + 32 ][kk];
            A[3] = *(const float4*)&Xs[cur][ty + 48 ][kk];
            Bv[0] = *(const float4*)&Ws[cur][tx      ][kk];
            Bv[1] = *(const float4*)&Ws[cur][tx + 16 ][kk];
            Bv[2] = *(const float4*)&Ws[cur][tx + 32 ][kk];
            Bv[3] = *(const float4*)&Ws[cur][tx + 48 ][kk];
#pragma unroll
            for (int i = 0; i < 4; ++i)
#pragma unroll
                for (int j = 0; j < 4; ++j) {
                    acc[i][j] = fmaf(A[i].x, Bv[j].x, acc[i][j]);
                    acc[i][j] = fmaf(A[i].y, Bv[j].y, acc[i][j]);
                    acc[i][j] = fmaf(A[i].z, Bv[j].z, acc[i][j]);
                    acc[i][j] = fmaf(A[i].w, Bv[j].w, acc[i][j]);
                }
        }
        if (kt + 1 < NKT) {
            *(float4*)&Xs[cur ^ 1][lr][lc] = fx;
            *(float4*)&Ws[cur ^ 1][lr][lc] = fw;
            __syncthreads();
        }
    }

    // Scatter: n0 block covers exactly one (which, h), all d in [0,64)
    const int which = n0 >> 10;              // 0=q, 1=k, 2=v
    const int h = (n0 >> 6) & (HH - 1);
    float* dst = (which == 0) ? g_q : ((which == 1) ? g_k : g_v);
    const int b = m0 >> 11;                  // m0 / S
    const int s_off = m0 & (SS - 1);
    float* dbase = dst + (size_t)(b * HH + h) * SS * HD;
#pragma unroll
    for (int i = 0; i < 4; ++i) {
        const int s = s_off + ty + 16 * i;
#pragma unroll
        for (int j = 0; j < 4; ++j) {
            const int d = tx + 16 * j;
            dbase[(size_t)s * HD + d] = acc[i][j];
        }
    }
}

// ---------------------------------------------------------------------------
// stablemax3 s(x), Eq 38. x <= 0 after max subtraction but handle both.
// ---------------------------------------------------------------------------
__device__ __forceinline__ float stablemax_s(float x) {
    if (x >= 0.f) {
        return 1.f + x * (1.f + 0.5f * x * (1.f + x * (1.f / 3.f)));
    } else {
        return 1.f / (1.f - x * (1.f - 0.5f * x * (1.f - x * (1.f / 3.f))));
    }
}

// ---------------------------------------------------------------------------
// Attention: one CTA per (bh, 64-query block). Two phases:
//  P1: logit tiles (scaled) -> private global spill + running row max
//  P2: re-read logits, s(), row sum, P@V accumulate, normalize, store
// Each thread reads back exactly what it wrote (no fences needed).
// ---------------------------------------------------------------------------
__global__ __launch_bounds__(256, 2)
void attn_kernel() {
    __shared__ float bufA[64][68];   // Q in P1, S-tile in P2
    __shared__ float bufB[64][68];   // K-tile in P1, V-tile in P2

    const int tid = threadIdx.x;
    const int ty = tid >> 4;
    const int tx = tid & 15;
    const int bh = blockIdx.x >> 5;
    const int q0 = (blockIdx.x & 31) << 6;

    const float* Qg = g_q + ((size_t)bh * SS + q0) * HD;
    const float* Kg = g_k + (size_t)bh * SS * HD;
    const float* Vg = g_v + (size_t)bh * SS * HD;
    float* Ls = g_logits + (size_t)blockIdx.x * (64 * SS);

    // Load Q tile [64][64] into bufA (float4, coalesced)
#pragma unroll
    for (int p = 0; p < 4; ++p) {
        const int idx = tid + (p << 8);
        const int r = idx >> 4;
        const int c = (idx & 15) << 2;
        *(float4*)&bufA[r][c] = *(const float4*)(Qg + r * HD + c);
    }

    // Prefetch K tile 0
    float4 pre[4];
#pragma unroll
    for (int p = 0; p < 4; ++p) {
        const int idx = tid + (p << 8);
        const int r = idx >> 4;
        const int c = (idx & 15) << 2;
        pre[p] = *(const float4*)(Kg + r * HD + c);
    }

    float rmax[4] = {-1e30f, -1e30f, -1e30f, -1e30f};
    const int NT = SS / 64;  // 32

    // ----------------- Phase 1: logits + row max -----------------
    for (int ct = 0; ct < NT; ++ct) {
        __syncthreads();                       // prior readers of bufB done
#pragma unroll
        for (int p = 0; p < 4; ++p) {
            const int idx = tid + (p << 8);
            const int r = idx >> 4;
            const int c = (idx & 15) << 2;
            *(float4*)&bufB[r][c] = pre[p];
        }
        __syncthreads();
        if (ct + 1 < NT) {
            const float* Kn = Kg + (size_t)(ct + 1) * 64 * HD;
#pragma unroll
            for (int p = 0; p < 4; ++p) {
                const int idx = tid + (p << 8);
                const int r = idx >> 4;
                const int c = (idx & 15) << 2;
                pre[p] = *(const float4*)(Kn + r * HD + c);
            }
        }

        float acc[4][4];
#pragma unroll
        for (int i = 0; i < 4; ++i)
#pragma unroll
            for (int j = 0; j < 4; ++j) acc[i][j] = 0.f;

#pragma unroll
        for (int kk = 0; kk < 64; kk += 4) {
            float4 A[4], Bv[4];
            A[0] = *(const float4*)&bufA[ty      ][kk];
            A[1] = *(const float4*)&bufA[ty + 16 ][kk];
            A[2] = *(const float4*)&bufA[ty + 32 ][kk];
            A[3] = *(const float4*)&bufA[ty + 48 ][kk];
            Bv[0] = *(const float4*)&bufB[tx      ][kk];
            Bv[1] = *(const float4*)&bufB[tx + 16 ][kk];
            Bv[2] = *(const float4*)&bufB[tx + 32 ][kk];
            Bv[3] = *(const float4*)&bufB[tx + 48 ][kk];
#pragma unroll
            for (int i = 0; i < 4; ++i)
#pragma unroll
                for (int j = 0; j < 4; ++j) {
                    acc[i][j] = fmaf(A[i].x, Bv[j].x, acc[i][j]);
                    acc[i][j] = fmaf(A[i].y, Bv[j].y, acc[i][j]);
                    acc[i][j] = fmaf(A[i].z, Bv[j].z, acc[i][j]);
                    acc[i][j] = fmaf(A[i].w, Bv[j].w, acc[i][j]);
                }
        }

        // scale, spill (coalesced, thread-private layout), row max
#pragma unroll
        for (int i = 0; i < 4; ++i) {
            float4 v;
            v.x = acc[i][0] * 0.125f;
            v.y = acc[i][1] * 0.125f;
            v.z = acc[i][2] * 0.125f;
            v.w = acc[i][3] * 0.125f;
            *(float4*)(Ls + (size_t)ct * 4096 + (size_t)tid * 16 + i * 4) = v;
            float m = fmaxf(fmaxf(v.x, v.y), fmaxf(v.z, v.w));
#pragma unroll
            for (int o = 8; o >= 1; o >>= 1)
                m = fmaxf(m, __shfl_xor_sync(0xffffffffu, m, o));
            rmax[i] = fmaxf(rmax[i], m);
        }
    }

    // ----------------- Phase 2: s(), rowsum, P@V -----------------
    float osum[4][4];
#pragma unroll
    for (int i = 0; i < 4; ++i)
#pragma unroll
        for (int j = 0; j < 4; ++j) osum[i][j] = 0.f;
    float rsum[4] = {0.f, 0.f, 0.f, 0.f};

    // Prefetch V tile 0
#pragma unroll
    for (int p = 0; p < 4; ++p) {
        const int idx = tid + (p << 8);
        const int r = idx >> 4;
        const int c = (idx & 15) << 2;
        pre[p] = *(const float4*)(Vg + r * HD + c);
    }

    for (int ct = 0; ct < NT; ++ct) {
        // re-read own logits (issued early, latency covered by syncs/STS below)
        float4 lr4[4];
#pragma unroll
        for (int i = 0; i < 4; ++i)
            lr4[i] = *(const float4*)(Ls + (size_t)ct * 4096 + (size_t)tid * 16 + i * 4);

        __syncthreads();                       // prior GEMM done reading bufA/bufB
#pragma unroll
        for (int p = 0; p < 4; ++p) {
            const int idx = tid + (p << 8);
            const int r = idx >> 4;
            const int c = (idx & 15) << 2;
            *(float4*)&bufB[r][c] = pre[p];
        }
        if (ct + 1 < NT) {
            const float* Vn = Vg + (size_t)(ct + 1) * 64 * HD;
#pragma unroll
            for (int p = 0; p < 4; ++p) {
                const int idx = tid + (p << 8);
                const int r = idx >> 4;
                const int c = (idx & 15) << 2;
                pre[p] = *(const float4*)(Vn + r * HD + c);
            }
        }

        // s() + rowsum partials + store S tile to bufA
#pragma unroll
        for (int i = 0; i < 4; ++i) {
            const int r = ty + 16 * i;
            const float s0 = stablemax_s(lr4[i].x - rmax[i]);
            const float s1 = stablemax_s(lr4[i].y - rmax[i]);
            const float s2 = stablemax_s(lr4[i].z - rmax[i]);
            const float s3 = stablemax_s(lr4[i].w - rmax[i]);
            rsum[i] += (s0 + s1) + (s2 + s3);
            bufA[r][tx      ] = s0;
            bufA[r][tx + 16 ] = s1;
            bufA[r][tx + 32 ] = s2;
            bufA[r][tx + 48 ] = s3;
        }
        __syncthreads();

        // P @ V: osum[r][d] += sum_t S[r][t] * V[t][d]
#pragma unroll
        for (int t = 0; t < 64; t += 4) {
            float4 Sv[4];
            Sv[0] = *(const float4*)&bufA[ty      ][t];
            Sv[1] = *(const float4*)&bufA[ty + 16 ][t];
            Sv[2] = *(const float4*)&bufA[ty + 32 ][t];
            Sv[3] = *(const float4*)&bufA[ty + 48 ][t];
#pragma unroll
            for (int j = 0; j < 4; ++j) {
                const int d = tx + 16 * j;
                const float vv0 = bufB[t + 0][d];
                const float vv1 = bufB[t + 1][d];
                const float vv2 = bufB[t + 2][d];
                const float vv3 = bufB[t + 3][d];
#pragma unroll
                for (int i = 0; i < 4; ++i) {
                    osum[i][j] = fmaf(Sv[i].x, vv0, osum[i][j]);
                    osum[i][j] = fmaf(Sv[i].y, vv1, osum[i][j]);
                    osum[i][j] = fmaf(Sv[i].z, vv2, osum[i][j]);
                    osum[i][j] = fmaf(Sv[i].w, vv3, osum[i][j]);
                }
            }
        }
    }

    // Full row sums (16-lane butterfly)
#pragma unroll
    for (int i = 0; i < 4; ++i) {
        float r = rsum[i];
#pragma unroll
        for (int o = 8; o >= 1; o >>= 1)
            r += __shfl_xor_sync(0xffffffffu, r, o);
        rsum[i] = r;
    }

    // Normalize, write to [B,S,D] with head-concat layout for the final GEMM
    const int b = bh >> 4;
    const int h = bh & (HH - 1);
    float* Og = g_ao + ((size_t)b * SS + q0) * DD + h * HD;
#pragma unroll
    for (int i = 0; i < 4; ++i) {
        const float inv = 1.0f / rsum[i];
        const int r = ty + 16 * i;
#pragma unroll
        for (int j = 0; j < 4; ++j) {
            Og[(size_t)r * DD + tx + 16 * j] = osum[i][j] * inv;
        }
    }
}

// ---------------------------------------------------------------------------
// Output projection: out[m,n] = sum_k AO[m,k] * Wout[n,k] + bias[n]
// M=4096, N=1024, K=1024. Same GEMM structure as QKV.
// ---------------------------------------------------------------------------
__global__ __launch_bounds__(256, 2)
void proj_kernel(const float* __restrict__ Wo, const float* __restrict__ bias,
                 float* __restrict__ out) {
    __shared__ float Xs[2][64][20];
    __shared__ float Ws[2][64][20];

    const int tid = threadIdx.x;
    const int ty = tid >> 4;
    const int tx = tid & 15;
    const int m0 = blockIdx.y << 6;
    const int n0 = blockIdx.x << 6;

    const int lr = tid >> 2;
    const int lc = (tid & 3) << 2;

    const float* Xg = g_ao + (size_t)(m0 + lr) * DD + lc;
    const float* Wg = Wo + (size_t)(n0 + lr) * DD + lc;

    float4 fx = *(const float4*)(Xg);
    float4 fw = *(const float4*)(Wg);
    *(float4*)&Xs[0][lr][lc] = fx;
    *(float4*)&Ws[0][lr][lc] = fw;
    __syncthreads();

    float acc[4][4];
#pragma unroll
    for (int i = 0; i < 4; ++i)
#pragma unroll
        for (int j = 0; j < 4; ++j) acc[i][j] = 0.f;

    const int NKT = DD / 16;
    for (int kt = 0; kt < NKT; ++kt) {
        const int cur = kt & 1;
        if (kt + 1 < NKT) {
            fx = *(const float4*)(Xg + (kt + 1) * 16);
            fw = *(const float4*)(Wg + (kt + 1) * 16);
        }
#pragma unroll
        for (int kk = 0; kk < 16; kk += 4) {
            float4 A[4], Bv[4];
            A[0] = *(const float4*)&Xs[cur][ty      ][kk];
            A[1] = *(const float4*)&Xs[cur][ty + 16 ][kk];
            A[2] = *(const float4*)&Xs[cur][ty + 32 ][kk];
            A[3] = *(const float4*)&Xs[cur][ty + 48 ][kk];
            Bv[0] = *(const float4*)&Ws[cur][tx      ][kk];
            Bv[1] = *(const float4*)&Ws[cur][tx + 16 ][kk];
            Bv[2] = *(const float4*)&Ws[cur][tx + 32 ][kk];
            Bv[3] = *(const float4*)&Ws[cur][tx + 48 ][kk];
#pragma unroll
            for (int i = 0; i < 4; ++i)
#pragma unroll
                for (int j = 0; j < 4; ++j) {
                    acc[i][j] = fmaf(A[i].x, Bv[j].x, acc[i][j]);
                    acc[i][j] = fmaf(A[i].y, Bv[j].y, acc[i][j]);
                    acc[i][j] = fmaf(A[i].z, Bv[j].z, acc[i][j]);
                    acc[i][j] = fmaf(A[i].w, Bv[j].w, acc[i][j]);
                }
        }
        if (kt + 1 < NKT) {
            *(float4*)&Xs[cur ^ 1][lr][lc] = fx;
            *(float4*)&Ws[cur ^ 1][lr][lc] = fw;
            __syncthreads();
        }
    }

#pragma unroll
    for (int i = 0; i < 4; ++i) {
        const int m = m0 + ty + 16 * i;
#pragma unroll
        for (int j = 0; j < 4; ++j) {
            const int n = n0 + tx + 16 * j;
            out[(size_t)m * DD + n] = acc[i][j] + bias[n];
        }
    }
}

// ---------------------------------------------------------------------------
// Launch
// ---------------------------------------------------------------------------
extern "C" void kernel_launch(void* const* d_in, const int* in_sizes, int n_in,
                              void* d_out, int out_size) {
    (void)in_sizes; (void)n_in; (void)out_size;
    const float* x    = (const float*)d_in[0];
    const float* wqkv = (const float*)d_in[1];
    const float* wout = (const float*)d_in[2];
    const float* bout = (const float*)d_in[3];
    float* out = (float*)d_out;

    qkv_gemm_kernel<<<dim3(3 * DD / 64, MROWS / 64), 256>>>(x, wqkv);
    attn_kernel<<<BH * (SS / 64), 256>>>();
    proj_kernel<<<dim3(DD / 64, MROWS / 64), 256>>>(wout, bout, out);
}

// round 7
// speedup vs baseline: 2.2468x; 2.2468x over previous
#include <cuda_runtime.h>
#include <cuda_bf16.h>

#define BB 2
#define SS 2048
#define DD 1024
#define HH 16
#define HD 64
#define BH (BB * HH)        // 32
#define MROWS (BB * SS)     // 4096

// ---------------------------------------------------------------------------
// Device scratch. g_q/g_k/g_v hold packed bf16 (hi | lo<<16) per element.
// ---------------------------------------------------------------------------
__device__ unsigned g_q[BH * SS * HD];               // 16 MB
__device__ unsigned g_k[BH * SS * HD];               // 16 MB
__device__ unsigned g_v[BH * SS * HD];               // 16 MB
__device__ float    g_logits[(size_t)BH * SS * SS];  // 512 MB spill
__device__ float    g_ao[(size_t)MROWS * DD];        // 16 MB

// ---------------------------------------------------------------------------
// Helpers
// ---------------------------------------------------------------------------
__device__ __forceinline__ unsigned split_pack(float f) {
    __nv_bfloat16 h = __float2bfloat16(f);
    float r = f - __bfloat162float(h);
    __nv_bfloat16 l = __float2bfloat16(r);
    return (unsigned)__bfloat16_as_ushort(h) | ((unsigned)__bfloat16_as_ushort(l) << 16);
}

__device__ __forceinline__ void mma_bf16(float* c,
                                         unsigned a0, unsigned a1, unsigned a2, unsigned a3,
                                         unsigned b0, unsigned b1) {
    asm volatile(
        "mma.sync.aligned.m16n8k16.row.col.f32.bf16.bf16.f32 "
        "{%0,%1,%2,%3},{%4,%5,%6,%7},{%8,%9},{%0,%1,%2,%3};\n"
        : "+f"(c[0]), "+f"(c[1]), "+f"(c[2]), "+f"(c[3])
        : "r"(a0), "r"(a1), "r"(a2), "r"(a3), "r"(b0), "r"(b1));
}

__device__ __forceinline__ void ldsm4(unsigned& r0, unsigned& r1, unsigned& r2, unsigned& r3,
                                      const void* p) {
    unsigned a = (unsigned)__cvta_generic_to_shared(p);
    asm volatile("ldmatrix.sync.aligned.m8n8.x4.shared.b16 {%0,%1,%2,%3},[%4];\n"
                 : "=r"(r0), "=r"(r1), "=r"(r2), "=r"(r3) : "r"(a));
}

__device__ __forceinline__ void ldsm4t(unsigned& r0, unsigned& r1, unsigned& r2, unsigned& r3,
                                       const void* p) {
    unsigned a = (unsigned)__cvta_generic_to_shared(p);
    asm volatile("ldmatrix.sync.aligned.m8n8.x4.trans.shared.b16 {%0,%1,%2,%3},[%4];\n"
                 : "=r"(r0), "=r"(r1), "=r"(r2), "=r"(r3) : "r"(a));
}

__device__ __forceinline__ float stablemax_s(float x) {
    if (x >= 0.f) {
        return 1.f + x * (1.f + 0.5f * x * (1.f + x * (1.f / 3.f)));
    } else {
        return 1.f / (1.f - x * (1.f - 0.5f * x * (1.f - x * (1.f / 3.f))));
    }
}

// ---------------------------------------------------------------------------
// GEMM: C[m,n] = sum_k A[m,k]*B[n,k], both fp32 in global, split bf16 on load.
// CTA tile 128x128, kTile 32, 8 warps (2m x 4n), warp tile 64x32.
// EPI 0: QKV scatter (pack bf16x2 into g_q/g_k/g_v, pre-scale Q by 0.125)
// EPI 1: out = acc + bias  (A is g_ao)
// ---------------------------------------------------------------------------
template <int EPI>
__global__ __launch_bounds__(256)
void gemm_kernel(const float* __restrict__ Ain, const float* __restrict__ Bin,
                 const float* __restrict__ bias, float* __restrict__ Cout) {
    __shared__ __align__(16) unsigned short Ah[128][40], Al[128][40];
    __shared__ __align__(16) unsigned short Bh[128][40], Bl[128][40];

    const int tid = threadIdx.x, lane = tid & 31, warp = tid >> 5;
    const int wm = warp >> 2, wn = warp & 3;
    const int m0 = blockIdx.y << 7, n0 = blockIdx.x << 7;

    const float* Abase = (EPI == 1) ? (const float*)g_ao : Ain;

    float acc[4][4][4];
#pragma unroll
    for (int a = 0; a < 4; ++a)
#pragma unroll
        for (int b = 0; b < 4; ++b)
#pragma unroll
            for (int r = 0; r < 4; ++r) acc[a][b][r] = 0.f;

    const int arow = tid >> 3;           // 0..31
    const int acol = (tid & 7) << 2;     // 0,4,...,28
    const float* Ag = Abase + (size_t)(m0 + arow) * DD + acol;
    const float* Bg = Bin + (size_t)(n0 + arow) * DD + acol;

    float4 pa[4], pb[4];
#pragma unroll
    for (int p = 0; p < 4; ++p) {
        pa[p] = *(const float4*)(Ag + (size_t)p * 32 * DD);
        pb[p] = *(const float4*)(Bg + (size_t)p * 32 * DD);
    }

    const int NKT = DD / 32;  // 32
    for (int kt = 0; kt < NKT; ++kt) {
        __syncthreads();
#pragma unroll
        for (int p = 0; p < 4; ++p) {
            const int row = p * 32 + arow;
            unsigned q0 = split_pack(pa[p].x), q1 = split_pack(pa[p].y);
            unsigned q2 = split_pack(pa[p].z), q3 = split_pack(pa[p].w);
            *(unsigned*)&Ah[row][acol]     = (q0 & 0xffffu) | (q1 << 16);
            *(unsigned*)&Ah[row][acol + 2] = (q2 & 0xffffu) | (q3 << 16);
            *(unsigned*)&Al[row][acol]     = (q0 >> 16) | (q1 & 0xffff0000u);
            *(unsigned*)&Al[row][acol + 2] = (q2 >> 16) | (q3 & 0xffff0000u);
            unsigned w0 = split_pack(pb[p].x), w1 = split_pack(pb[p].y);
            unsigned w2 = split_pack(pb[p].z), w3 = split_pack(pb[p].w);
            *(unsigned*)&Bh[row][acol]     = (w0 & 0xffffu) | (w1 << 16);
            *(unsigned*)&Bh[row][acol + 2] = (w2 & 0xffffu) | (w3 << 16);
            *(unsigned*)&Bl[row][acol]     = (w0 >> 16) | (w1 & 0xffff0000u);
            *(unsigned*)&Bl[row][acol + 2] = (w2 >> 16) | (w3 & 0xffff0000u);
        }
        __syncthreads();
        if (kt + 1 < NKT) {
            const float* Ag2 = Ag + (kt + 1) * 32;
            const float* Bg2 = Bg + (kt + 1) * 32;
#pragma unroll
            for (int p = 0; p < 4; ++p) {
                pa[p] = *(const float4*)(Ag2 + (size_t)p * 32 * DD);
                pb[p] = *(const float4*)(Bg2 + (size_t)p * 32 * DD);
            }
        }

#pragma unroll
        for (int kb = 0; kb < 2; ++kb) {
            unsigned ah[4][4], al[4][4];
#pragma unroll
            for (int mb = 0; mb < 4; ++mb) {
                const int r = wm * 64 + mb * 16 + (lane & 15);
                const int c = kb * 16 + ((lane >> 4) << 3);
                ldsm4(ah[mb][0], ah[mb][1], ah[mb][2], ah[mb][3], &Ah[r][c]);
                ldsm4(al[mb][0], al[mb][1], al[mb][2], al[mb][3], &Al[r][c]);
            }
            unsigned bhf[2][4], blf[2][4];
#pragma unroll
            for (int pr = 0; pr < 2; ++pr) {
                const int r = wn * 32 + pr * 16 + (lane & 7) + ((lane >> 4) << 3);
                const int c = kb * 16 + (((lane >> 3) & 1) << 3);
                ldsm4(bhf[pr][0], bhf[pr][1], bhf[pr][2], bhf[pr][3], &Bh[r][c]);
                ldsm4(blf[pr][0], blf[pr][1], blf[pr][2], blf[pr][3], &Bl[r][c]);
            }
#pragma unroll
            for (int mb = 0; mb < 4; ++mb)
#pragma unroll
                for (int nb = 0; nb < 4; ++nb) {
                    const unsigned b0h = bhf[nb >> 1][(nb & 1) * 2];
                    const unsigned b1h = bhf[nb >> 1][(nb & 1) * 2 + 1];
                    const unsigned b0l = blf[nb >> 1][(nb & 1) * 2];
                    const unsigned b1l = blf[nb >> 1][(nb & 1) * 2 + 1];
                    mma_bf16(acc[mb][nb], ah[mb][0], ah[mb][1], ah[mb][2], ah[mb][3], b0h, b1h);
                    mma_bf16(acc[mb][nb], ah[mb][0], ah[mb][1], ah[mb][2], ah[mb][3], b0l, b1l);
                    mma_bf16(acc[mb][nb], al[mb][0], al[mb][1], al[mb][2], al[mb][3], b0h, b1h);
                }
        }
    }

    // Epilogue
    const int g = lane >> 2, e = lane & 3;
#pragma unroll
    for (int mb = 0; mb < 4; ++mb)
#pragma unroll
        for (int nb = 0; nb < 4; ++nb)
#pragma unroll
            for (int r = 0; r < 4; ++r) {
                const int m = m0 + wm * 64 + mb * 16 + g + ((r >> 1) << 3);
                const int n = n0 + wn * 32 + nb * 8 + 2 * e + (r & 1);
                float v = acc[mb][nb][r];
                if (EPI == 0) {
                    const int which = n >> 10;
                    const int h = (n >> 6) & 15;
                    const int d = n & 63;
                    const int b = m >> 11;
                    const int s = m & 2047;
                    if (which == 0) v *= 0.125f;  // exact pre-scale of Q
                    unsigned* dst = (which == 0) ? g_q : ((which == 1) ? g_k : g_v);
                    dst[(size_t)((b * HH + h) * SS + s) * HD + d] = split_pack(v);
                } else {
                    Cout[(size_t)m * DD + n] = v + bias[n];
                }
            }
}

// ---------------------------------------------------------------------------
// Attention: one CTA per (bh, 64-query block), 8 warps (4 q-groups x 2 k-halves).
// Phase 1: logits via HMMA -> spill + row max.  Phase 2: s(), rowsum, P@V via HMMA.
// ---------------------------------------------------------------------------
__global__ __launch_bounds__(256)
void attn_kernel() {
    __shared__ __align__(16) unsigned char smraw[18432 * 2];
    __shared__ float redA[2][64];
    __shared__ float rowred[64];

    typedef unsigned short usrow[72];
    usrow* Qhi = (usrow*)(smraw);
    usrow* Qlo = (usrow*)(smraw + 9216);
    usrow* Khi = (usrow*)(smraw + 18432);          // reused for V in phase 2
    usrow* Klo = (usrow*)(smraw + 18432 + 9216);
    typedef float frow[68];
    frow* Osm = (frow*)(smraw);                    // overlaps Q region (dead by then)

    const int tid = threadIdx.x, lane = tid & 31, warp = tid >> 5;
    const int wm = warp >> 1, wk = warp & 1;
    const int bh = blockIdx.x >> 5;
    const int q0 = (blockIdx.x & 31) << 6;

    const unsigned* Qg = g_q + ((size_t)bh * SS + q0) * HD;
    const unsigned* Kg = g_k + (size_t)bh * SS * HD;
    const unsigned* Vg = g_v + (size_t)bh * SS * HD;
    float* Ls = g_logits + (size_t)blockIdx.x * (64 * SS);

    const int trow = tid >> 4;            // 0..15
    const int tcol = (tid & 15) << 2;     // 0..60

    // Load Q (pre-split, pre-scaled) into smem
#pragma unroll
    for (int p = 0; p < 4; ++p) {
        const int row = p * 16 + trow;
        uint4 u = *(const uint4*)(Qg + (size_t)row * HD + tcol);
        *(unsigned*)&Qhi[row][tcol]     = (u.x & 0xffffu) | (u.y << 16);
        *(unsigned*)&Qhi[row][tcol + 2] = (u.z & 0xffffu) | (u.w << 16);
        *(unsigned*)&Qlo[row][tcol]     = (u.x >> 16) | (u.y & 0xffff0000u);
        *(unsigned*)&Qlo[row][tcol + 2] = (u.z >> 16) | (u.w & 0xffff0000u);
    }
    // Prefetch K tile 0
    uint4 pre[4];
#pragma unroll
    for (int p = 0; p < 4; ++p)
        pre[p] = *(const uint4*)(Kg + (size_t)(p * 16 + trow) * HD + tcol);

    __syncthreads();

    // Q fragments (live in regs for all of phase 1)
    unsigned qh[4][4], ql[4][4];
#pragma unroll
    for (int kb = 0; kb < 4; ++kb) {
        const int r = wm * 16 + (lane & 15);
        const int c = kb * 16 + ((lane >> 4) << 3);
        ldsm4(qh[kb][0], qh[kb][1], qh[kb][2], qh[kb][3], &Qhi[r][c]);
        ldsm4(ql[kb][0], ql[kb][1], ql[kb][2], ql[kb][3], &Qlo[r][c]);
    }

    float rm0 = -1e30f, rm1 = -1e30f;
    const int NT = SS / 64;  // 32

    // ----------------- Phase 1 -----------------
    for (int ct = 0; ct < NT; ++ct) {
        __syncthreads();
#pragma unroll
        for (int p = 0; p < 4; ++p) {
            const int row = p * 16 + trow;
            uint4 u = pre[p];
            *(unsigned*)&Khi[row][tcol]     = (u.x & 0xffffu) | (u.y << 16);
            *(unsigned*)&Khi[row][tcol + 2] = (u.z & 0xffffu) | (u.w << 16);
            *(unsigned*)&Klo[row][tcol]     = (u.x >> 16) | (u.y & 0xffff0000u);
            *(unsigned*)&Klo[row][tcol + 2] = (u.z >> 16) | (u.w & 0xffff0000u);
        }
        __syncthreads();
        if (ct + 1 < NT) {
            const unsigned* Kn = Kg + (size_t)(ct + 1) * 64 * HD;
#pragma unroll
            for (int p = 0; p < 4; ++p)
                pre[p] = *(const uint4*)(Kn + (size_t)(p * 16 + trow) * HD + tcol);
        }

        float c[4][4];
#pragma unroll
        for (int nb = 0; nb < 4; ++nb)
#pragma unroll
            for (int r = 0; r < 4; ++r) c[nb][r] = 0.f;

#pragma unroll
        for (int kb = 0; kb < 4; ++kb) {
            unsigned bhf[2][4], blf[2][4];
#pragma unroll
            for (int pr = 0; pr < 2; ++pr) {
                const int r = wk * 32 + pr * 16 + (lane & 7) + ((lane >> 4) << 3);
                const int cc = kb * 16 + (((lane >> 3) & 1) << 3);
                ldsm4(bhf[pr][0], bhf[pr][1], bhf[pr][2], bhf[pr][3], &Khi[r][cc]);
                ldsm4(blf[pr][0], blf[pr][1], blf[pr][2], blf[pr][3], &Klo[r][cc]);
            }
#pragma unroll
            for (int nb = 0; nb < 4; ++nb) {
                const unsigned b0h = bhf[nb >> 1][(nb & 1) * 2];
                const unsigned b1h = bhf[nb >> 1][(nb & 1) * 2 + 1];
                const unsigned b0l = blf[nb >> 1][(nb & 1) * 2];
                const unsigned b1l = blf[nb >> 1][(nb & 1) * 2 + 1];
                mma_bf16(c[nb], qh[kb][0], qh[kb][1], qh[kb][2], qh[kb][3], b0h, b1h);
                mma_bf16(c[nb], qh[kb][0], qh[kb][1], qh[kb][2], qh[kb][3], b0l, b1l);
                mma_bf16(c[nb], ql[kb][0], ql[kb][1], ql[kb][2], ql[kb][3], b0h, b1h);
            }
        }

        // Spill (thread-private, coalesced) + running row max
        float* base = Ls + (size_t)ct * 4096 + warp * 512 + lane * 4;
#pragma unroll
        for (int nb = 0; nb < 4; ++nb) {
            float4 v;
            v.x = c[nb][0]; v.y = c[nb][1]; v.z = c[nb][2]; v.w = c[nb][3];
            *(float4*)(base + nb * 128) = v;
            rm0 = fmaxf(rm0, fmaxf(v.x, v.y));
            rm1 = fmaxf(rm1, fmaxf(v.z, v.w));
        }
    }

    // Row-max reduction
    rm0 = fmaxf(rm0, __shfl_xor_sync(0xffffffffu, rm0, 1));
    rm0 = fmaxf(rm0, __shfl_xor_sync(0xffffffffu, rm0, 2));
    rm1 = fmaxf(rm1, __shfl_xor_sync(0xffffffffu, rm1, 1));
    rm1 = fmaxf(rm1, __shfl_xor_sync(0xffffffffu, rm1, 2));
    const int g = lane >> 2;
    if ((lane & 3) == 0) {
        redA[wk][wm * 16 + g] = rm0;
        redA[wk][wm * 16 + g + 8] = rm1;
    }
    __syncthreads();
    if (tid < 64) rowred[tid] = fmaxf(redA[0][tid], redA[1][tid]);
    __syncthreads();
    const float rx0 = rowred[wm * 16 + g];
    const float rx1 = rowred[wm * 16 + g + 8];

    // ----------------- Phase 2 -----------------
    float O[8][4];
#pragma unroll
    for (int nb = 0; nb < 8; ++nb)
#pragma unroll
        for (int r = 0; r < 4; ++r) O[nb][r] = 0.f;
    float rs0 = 0.f, rs1 = 0.f;

#pragma unroll
    for (int p = 0; p < 4; ++p)
        pre[p] = *(const uint4*)(Vg + (size_t)(p * 16 + trow) * HD + tcol);

    for (int ct = 0; ct < NT; ++ct) {
        float4 L[4];
        const float* sb = Ls + (size_t)ct * 4096 + warp * 512 + lane * 4;
#pragma unroll
        for (int nb = 0; nb < 4; ++nb) L[nb] = *(const float4*)(sb + nb * 128);

        __syncthreads();
#pragma unroll
        for (int p = 0; p < 4; ++p) {
            const int row = p * 16 + trow;
            uint4 u = pre[p];
            *(unsigned*)&Khi[row][tcol]     = (u.x & 0xffffu) | (u.y << 16);
            *(unsigned*)&Khi[row][tcol + 2] = (u.z & 0xffffu) | (u.w << 16);
            *(unsigned*)&Klo[row][tcol]     = (u.x >> 16) | (u.y & 0xffff0000u);
            *(unsigned*)&Klo[row][tcol + 2] = (u.z >> 16) | (u.w & 0xffff0000u);
        }
        __syncthreads();
        if (ct + 1 < NT) {
            const unsigned* Vn = Vg + (size_t)(ct + 1) * 64 * HD;
#pragma unroll
            for (int p = 0; p < 4; ++p)
                pre[p] = *(const uint4*)(Vn + (size_t)(p * 16 + trow) * HD + tcol);
        }

        // s(), rowsum partials, and build S fragments (hi/lo) in C-frag layout
        unsigned sh[2][4], sl[2][4];
#pragma unroll
        for (int nb = 0; nb < 4; ++nb) {
            const float s0 = stablemax_s(L[nb].x - rx0);
            const float s1 = stablemax_s(L[nb].y - rx0);
            const float s2 = stablemax_s(L[nb].z - rx1);
            const float s3 = stablemax_s(L[nb].w - rx1);
            rs0 += s0 + s1;
            rs1 += s2 + s3;
            const unsigned u0 = split_pack(s0), u1 = split_pack(s1);
            const unsigned u2 = split_pack(s2), u3 = split_pack(s3);
            const int kbp = nb >> 1, half = nb & 1;
            sh[kbp][half * 2]     = (u0 & 0xffffu) | ((u1 & 0xffffu) << 16);
            sh[kbp][half * 2 + 1] = (u2 & 0xffffu) | ((u3 & 0xffffu) << 16);
            sl[kbp][half * 2]     = (u0 >> 16) | (u1 & 0xffff0000u);
            sl[kbp][half * 2 + 1] = (u2 >> 16) | (u3 & 0xffff0000u);
        }

        // P @ V via HMMA: B = V loaded with ldmatrix.trans from [k][d] layout
#pragma unroll
        for (int kbp = 0; kbp < 2; ++kbp) {
            const int rbase = wk * 32 + kbp * 16 + (lane & 15);
            const int cb = ((lane >> 4) << 3);
#pragma unroll
            for (int np = 0; np < 4; ++np) {
                unsigned vh[4], vl[4];
                ldsm4t(vh[0], vh[1], vh[2], vh[3], &Khi[rbase][np * 16 + cb]);
                ldsm4t(vl[0], vl[1], vl[2], vl[3], &Klo[rbase][np * 16 + cb]);
#pragma unroll
                for (int qh2 = 0; qh2 < 2; ++qh2) {
                    const int nb = np * 2 + qh2;
                    mma_bf16(O[nb], sh[kbp][0], sh[kbp][1], sh[kbp][2], sh[kbp][3],
                             vh[qh2 * 2], vh[qh2 * 2 + 1]);
                    mma_bf16(O[nb], sh[kbp][0], sh[kbp][1], sh[kbp][2], sh[kbp][3],
                             vl[qh2 * 2], vl[qh2 * 2 + 1]);
                    mma_bf16(O[nb], sl[kbp][0], sl[kbp][1], sl[kbp][2], sl[kbp][3],
                             vh[qh2 * 2], vh[qh2 * 2 + 1]);
                }
            }
        }
    }

    // Row-sum reduction
    rs0 += __shfl_xor_sync(0xffffffffu, rs0, 1);
    rs0 += __shfl_xor_sync(0xffffffffu, rs0, 2);
    rs1 += __shfl_xor_sync(0xffffffffu, rs1, 1);
    rs1 += __shfl_xor_sync(0xffffffffu, rs1, 2);
    if ((lane & 3) == 0) {
        redA[wk][wm * 16 + g] = rs0;
        redA[wk][wm * 16 + g + 8] = rs1;
    }
    __syncthreads();
    if (tid < 64) rowred[tid] = redA[0][tid] + redA[1][tid];
    __syncthreads();

    // Combine k-half partial outputs in smem (Osm overlaps dead Q region)
    const int e = lane & 3;
    if (wk == 0) {
#pragma unroll
        for (int nb = 0; nb < 8; ++nb)
#pragma unroll
            for (int r = 0; r < 4; ++r)
                Osm[wm * 16 + g + ((r >> 1) << 3)][nb * 8 + 2 * e + (r & 1)] = O[nb][r];
    }
    __syncthreads();
    if (wk == 1) {
#pragma unroll
        for (int nb = 0; nb < 8; ++nb)
#pragma unroll
            for (int r = 0; r < 4; ++r)
                Osm[wm * 16 + g + ((r >> 1) << 3)][nb * 8 + 2 * e + (r & 1)] += O[nb][r];
    }
    __syncthreads();

    // Normalize + store to g_ao (head-concat layout)
    const int b = bh >> 4;
    const int h = bh & 15;
#pragma unroll
    for (int p = 0; p < 4; ++p) {
        const int q = p * 16 + trow;
        float4 v = *(float4*)&Osm[q][tcol];
        const float inv = 1.0f / rowred[q];
        v.x *= inv; v.y *= inv; v.z *= inv; v.w *= inv;
        *(float4*)&g_ao[(size_t)(b * SS + q0 + q) * DD + h * HD + tcol] = v;
    }
}

// ---------------------------------------------------------------------------
// Launch
// ---------------------------------------------------------------------------
extern "C" void kernel_launch(void* const* d_in, const int* in_sizes, int n_in,
                              void* d_out, int out_size) {
    (void)in_sizes; (void)n_in; (void)out_size;
    const float* x    = (const float*)d_in[0];
    const float* wqkv = (const float*)d_in[1];
    const float* wout = (const float*)d_in[2];
    const float* bout = (const float*)d_in[3];
    float* out = (float*)d_out;

    gemm_kernel<0><<<dim3(3 * DD / 128, MROWS / 128), 256>>>(x, wqkv, nullptr, nullptr);
    attn_kernel<<<BH * (SS / 64), 256>>>();
    gemm_kernel<1><<<dim3(DD / 128, MROWS / 128), 256>>>(nullptr, wout, bout, out);
}

// round 8
// speedup vs baseline: 2.2545x; 1.0034x over previous
#include <cuda_runtime.h>
#include <cuda_bf16.h>

#define BB 2
#define SS 2048
#define DD 1024
#define HH 16
#define HD 64
#define BH (BB * HH)        // 32
#define MROWS (BB * SS)     // 4096

// ---------------------------------------------------------------------------
// Device scratch: bf16 hi/lo planes + fp32 logit spill
// ---------------------------------------------------------------------------
__device__ unsigned short g_xh[MROWS * DD],  g_xl[MROWS * DD];        // X split
__device__ unsigned short g_wqh[3 * DD * DD], g_wql[3 * DD * DD];     // Wqkv split
__device__ unsigned short g_woh[DD * DD],    g_wol[DD * DD];          // Wout split
__device__ unsigned short g_qh[BH * SS * HD], g_ql[BH * SS * HD];
__device__ unsigned short g_kh[BH * SS * HD], g_kl[BH * SS * HD];
__device__ unsigned short g_vh[BH * SS * HD], g_vl[BH * SS * HD];
__device__ unsigned short g_aoh[(size_t)MROWS * DD], g_aol[(size_t)MROWS * DD];
__device__ float g_logits[(size_t)BH * SS * SS];                      // 512 MB

// ---------------------------------------------------------------------------
// Helpers
// ---------------------------------------------------------------------------
__device__ __forceinline__ void split2(float f, unsigned short& h, unsigned short& l) {
    __nv_bfloat16 hb = __float2bfloat16(f);
    float r = f - __bfloat162float(hb);
    __nv_bfloat16 lb = __float2bfloat16(r);
    h = __bfloat16_as_ushort(hb);
    l = __bfloat16_as_ushort(lb);
}

__device__ __forceinline__ unsigned split_pack(float f) {
    unsigned short h, l;
    split2(f, h, l);
    return (unsigned)h | ((unsigned)l << 16);
}

__device__ __forceinline__ void mma_bf16(float* c,
                                         unsigned a0, unsigned a1, unsigned a2, unsigned a3,
                                         unsigned b0, unsigned b1) {
    asm volatile(
        "mma.sync.aligned.m16n8k16.row.col.f32.bf16.bf16.f32 "
        "{%0,%1,%2,%3},{%4,%5,%6,%7},{%8,%9},{%0,%1,%2,%3};\n"
        : "+f"(c[0]), "+f"(c[1]), "+f"(c[2]), "+f"(c[3])
        : "r"(a0), "r"(a1), "r"(a2), "r"(a3), "r"(b0), "r"(b1));
}

__device__ __forceinline__ void ldsm4(unsigned& r0, unsigned& r1, unsigned& r2, unsigned& r3,
                                      const void* p) {
    unsigned a = (unsigned)__cvta_generic_to_shared(p);
    asm volatile("ldmatrix.sync.aligned.m8n8.x4.shared.b16 {%0,%1,%2,%3},[%4];\n"
                 : "=r"(r0), "=r"(r1), "=r"(r2), "=r"(r3) : "r"(a));
}

__device__ __forceinline__ void ldsm4t(unsigned& r0, unsigned& r1, unsigned& r2, unsigned& r3,
                                       const void* p) {
    unsigned a = (unsigned)__cvta_generic_to_shared(p);
    asm volatile("ldmatrix.sync.aligned.m8n8.x4.trans.shared.b16 {%0,%1,%2,%3},[%4];\n"
                 : "=r"(r0), "=r"(r1), "=r"(r2), "=r"(r3) : "r"(a));
}

__device__ __forceinline__ void cp16(void* dst, const void* src) {
    unsigned d = (unsigned)__cvta_generic_to_shared(dst);
    asm volatile("cp.async.cg.shared.global [%0],[%1],16;\n" :: "r"(d), "l"(src));
}
__device__ __forceinline__ void cp_commit() { asm volatile("cp.async.commit_group;\n"); }
template <int N>
__device__ __forceinline__ void cp_wait() { asm volatile("cp.async.wait_group %0;\n" :: "n"(N)); }

__device__ __forceinline__ float stablemax_s(float x) {
    if (x >= 0.f) {
        return 1.f + x * (1.f + 0.5f * x * (1.f + x * (1.f / 3.f)));
    } else {
        return 1.f / (1.f - x * (1.f - 0.5f * x * (1.f - x * (1.f / 3.f))));
    }
}

// ---------------------------------------------------------------------------
// One-time split: fp32 -> bf16 hi/lo planes. which: 0=X, 1=Wqkv, 2=Wout
// ---------------------------------------------------------------------------
__global__ void split_kernel(const float* __restrict__ src, int which, int n4) {
    int i = blockIdx.x * blockDim.x + threadIdx.x;
    if (i >= n4) return;
    unsigned short *hi, *lo;
    if (which == 0)      { hi = g_xh;  lo = g_xl;  }
    else if (which == 1) { hi = g_wqh; lo = g_wql; }
    else                 { hi = g_woh; lo = g_wol; }
    float4 v = ((const float4*)src)[i];
    unsigned short h0, h1, h2, h3, l0, l1, l2, l3;
    split2(v.x, h0, l0); split2(v.y, h1, l1);
    split2(v.z, h2, l2); split2(v.w, h3, l3);
    uint2 ph, pl;
    ph.x = (unsigned)h0 | ((unsigned)h1 << 16); ph.y = (unsigned)h2 | ((unsigned)h3 << 16);
    pl.x = (unsigned)l0 | ((unsigned)l1 << 16); pl.y = (unsigned)l2 | ((unsigned)l3 << 16);
    ((uint2*)hi)[i] = ph;
    ((uint2*)lo)[i] = pl;
}

// ---------------------------------------------------------------------------
// GEMM: C[m,n] = sum_k A[m,k]*B[n,k], pre-split bf16 planes, 2-stage cp.async.
// CTA 128x128, kTile 32, 8 warps (2m x 4n), warp tile 64x32.
// smem per stage: 4 planes (Ah,Al,Bh,Bl) x 128 rows x 64B, XOR swizzled.
// EPI 0: scatter to q/k/v planes (Q pre-scaled 0.125). EPI 1: +bias -> Cout.
// ---------------------------------------------------------------------------
template <int EPI>
__global__ __launch_bounds__(256)
void gemm_kernel(const float* __restrict__ bias, float* __restrict__ Cout) {
    extern __shared__ unsigned char dynsm[];

    const int tid = threadIdx.x, lane = tid & 31, warp = tid >> 5;
    const int wm = warp >> 2, wn = warp & 3;
    const int m0 = blockIdx.y << 7, n0 = blockIdx.x << 7;

    const unsigned short* AH = (EPI == 0) ? g_xh : g_aoh;
    const unsigned short* AL = (EPI == 0) ? g_xl : g_aol;
    const unsigned short* BH_ = (EPI == 0) ? g_wqh : g_woh;
    const unsigned short* BL_ = (EPI == 0) ? g_wql : g_wol;

    const int lr = tid >> 1;            // 0..127
    const int cb = (tid & 1) * 2;       // chunk base 0 or 2
    const unsigned short* srcs[4] = {
        AH + (size_t)(m0 + lr) * DD, AL + (size_t)(m0 + lr) * DD,
        BH_ + (size_t)(n0 + lr) * DD, BL_ + (size_t)(n0 + lr) * DD };

    const int rsw = (lr >> 1) & 3;      // writer swizzle term

    float acc[4][4][4];
#pragma unroll
    for (int a = 0; a < 4; ++a)
#pragma unroll
        for (int b = 0; b < 4; ++b)
#pragma unroll
            for (int r = 0; r < 4; ++r) acc[a][b][r] = 0.f;

    // issue stage loads (8 cp.async per thread)
    auto issue = [&](int stage, int kt) {
        unsigned char* sb = dynsm + stage * 32768 + lr * 64;
#pragma unroll
        for (int p = 0; p < 4; ++p) {
            const unsigned short* s = srcs[p] + kt * 32;
#pragma unroll
            for (int cc = 0; cc < 2; ++cc) {
                const int c = cb + cc;
                cp16(sb + p * 8192 + ((c ^ rsw) << 4), s + c * 8);
            }
        }
    };

    const int NKT = DD / 32;  // 32
    issue(0, 0);
    cp_commit();

    for (int kt = 0; kt < NKT; ++kt) {
        if (kt + 1 < NKT) { issue((kt + 1) & 1, kt + 1); cp_commit(); }
        if (kt + 1 < NKT) cp_wait<1>(); else cp_wait<0>();
        __syncthreads();

        const unsigned char* sb = dynsm + (kt & 1) * 32768;
        auto frag_addr = [&](int plane, int r, int halfcol) -> const void* {
            const int chunk = halfcol >> 3;
            return (const void*)(sb + plane * 8192 + r * 64 +
                                 ((chunk ^ ((r >> 1) & 3)) << 4));
        };

#pragma unroll
        for (int kb = 0; kb < 2; ++kb) {
            unsigned ah[4][4], al[4][4];
#pragma unroll
            for (int mb = 0; mb < 4; ++mb) {
                const int r = wm * 64 + mb * 16 + (lane & 15);
                const int c = kb * 16 + ((lane >> 4) << 3);
                ldsm4(ah[mb][0], ah[mb][1], ah[mb][2], ah[mb][3], frag_addr(0, r, c));
                ldsm4(al[mb][0], al[mb][1], al[mb][2], al[mb][3], frag_addr(1, r, c));
            }
            unsigned bhf[2][4], blf[2][4];
#pragma unroll
            for (int pr = 0; pr < 2; ++pr) {
                const int r = wn * 32 + pr * 16 + (lane & 7) + ((lane >> 4) << 3);
                const int c = kb * 16 + (((lane >> 3) & 1) << 3);
                ldsm4(bhf[pr][0], bhf[pr][1], bhf[pr][2], bhf[pr][3], frag_addr(2, r, c));
                ldsm4(blf[pr][0], blf[pr][1], blf[pr][2], blf[pr][3], frag_addr(3, r, c));
            }
#pragma unroll
            for (int mb = 0; mb < 4; ++mb)
#pragma unroll
                for (int nb = 0; nb < 4; ++nb) {
                    const unsigned b0h = bhf[nb >> 1][(nb & 1) * 2];
                    const unsigned b1h = bhf[nb >> 1][(nb & 1) * 2 + 1];
                    const unsigned b0l = blf[nb >> 1][(nb & 1) * 2];
                    const unsigned b1l = blf[nb >> 1][(nb & 1) * 2 + 1];
                    mma_bf16(acc[mb][nb], ah[mb][0], ah[mb][1], ah[mb][2], ah[mb][3], b0h, b1h);
                    mma_bf16(acc[mb][nb], ah[mb][0], ah[mb][1], ah[mb][2], ah[mb][3], b0l, b1l);
                    mma_bf16(acc[mb][nb], al[mb][0], al[mb][1], al[mb][2], al[mb][3], b0h, b1h);
                }
        }
        __syncthreads();
    }

    // Epilogue
    const int g = lane >> 2, e = lane & 3;
#pragma unroll
    for (int mb = 0; mb < 4; ++mb)
#pragma unroll
        for (int nb = 0; nb < 4; ++nb)
#pragma unroll
            for (int r = 0; r < 4; ++r) {
                const int m = m0 + wm * 64 + mb * 16 + g + ((r >> 1) << 3);
                const int n = n0 + wn * 32 + nb * 8 + 2 * e + (r & 1);
                float v = acc[mb][nb][r];
                if (EPI == 0) {
                    const int which = n >> 10;
                    const int h = (n >> 6) & 15;
                    const int d = n & 63;
                    const int b = m >> 11;
                    const int s = m & 2047;
                    if (which == 0) v *= 0.125f;  // exact pre-scale of Q
                    unsigned short* dh = (which == 0) ? g_qh : ((which == 1) ? g_kh : g_vh);
                    unsigned short* dl = (which == 0) ? g_ql : ((which == 1) ? g_kl : g_vl);
                    const size_t idx = (size_t)((b * HH + h) * SS + s) * HD + d;
                    unsigned short hh, ll;
                    split2(v, hh, ll);
                    dh[idx] = hh;
                    dl[idx] = ll;
                } else {
                    Cout[(size_t)m * DD + n] = v + bias[n];
                }
            }
}

// ---------------------------------------------------------------------------
// Attention: one CTA per (bh, 64-query block), 8 warps (4 q-groups x 2 k-halves).
// Phase 1: QK^T (HMMA, bf16x2 split) -> fp32 spill (+streaming hints) + row max.
// Phase 2: s(), rowsum, P@V (HMMA). Epilogue writes split ao planes.
// ---------------------------------------------------------------------------
__global__ __launch_bounds__(256)
void attn_kernel() {
    __shared__ __align__(16) unsigned char smraw[36864];
    __shared__ float redA[2][64];
    __shared__ float rowred[64];

    typedef unsigned short usrow[72];
    usrow* Qhi = (usrow*)(smraw);
    usrow* Qlo = (usrow*)(smraw + 9216);
    usrow* Khi = (usrow*)(smraw + 18432);   // V in phase 2
    usrow* Klo = (usrow*)(smraw + 27648);
    typedef float frow[68];
    frow* Osm = (frow*)(smraw);             // overlaps dead Q region

    const int tid = threadIdx.x, lane = tid & 31, warp = tid >> 5;
    const int wm = warp >> 1, wk = warp & 1;
    const int bh = blockIdx.x >> 5;
    const int q0 = (blockIdx.x & 31) << 6;

    const size_t qbase = ((size_t)bh * SS + q0) * HD;
    const size_t kbase = (size_t)bh * SS * HD;
    float* Ls = g_logits + (size_t)blockIdx.x * (64 * SS);

    // plane-load mapping: row = tid>>2 (0..63), halfcol = (tid&3)*8 and +32
    const int prow = tid >> 2;
    const int pcol = (tid & 3) << 3;

    // Load Q planes into smem
    {
        const unsigned short* sh = g_qh + qbase + (size_t)prow * HD + pcol;
        const unsigned short* sl = g_ql + qbase + (size_t)prow * HD + pcol;
        *(uint4*)&Qhi[prow][pcol]      = *(const uint4*)(sh);
        *(uint4*)&Qhi[prow][pcol + 32] = *(const uint4*)(sh + 32);
        *(uint4*)&Qlo[prow][pcol]      = *(const uint4*)(sl);
        *(uint4*)&Qlo[prow][pcol + 32] = *(const uint4*)(sl + 32);
    }
    // Prefetch K tile 0
    uint4 pre[4];
    {
        const unsigned short* sh = g_kh + kbase + (size_t)prow * HD + pcol;
        const unsigned short* sl = g_kl + kbase + (size_t)prow * HD + pcol;
        pre[0] = *(const uint4*)(sh);
        pre[1] = *(const uint4*)(sh + 32);
        pre[2] = *(const uint4*)(sl);
        pre[3] = *(const uint4*)(sl + 32);
    }
    __syncthreads();

    // Q fragments live in regs for all of phase 1
    unsigned qh[4][4], ql[4][4];
#pragma unroll
    for (int kb = 0; kb < 4; ++kb) {
        const int r = wm * 16 + (lane & 15);
        const int c = kb * 16 + ((lane >> 4) << 3);
        ldsm4(qh[kb][0], qh[kb][1], qh[kb][2], qh[kb][3], &Qhi[r][c]);
        ldsm4(ql[kb][0], ql[kb][1], ql[kb][2], ql[kb][3], &Qlo[r][c]);
    }

    float rm0 = -1e30f, rm1 = -1e30f;
    const int NT = SS / 64;  // 32

    // ----------------- Phase 1 -----------------
    for (int ct = 0; ct < NT; ++ct) {
        __syncthreads();
        *(uint4*)&Khi[prow][pcol]      = pre[0];
        *(uint4*)&Khi[prow][pcol + 32] = pre[1];
        *(uint4*)&Klo[prow][pcol]      = pre[2];
        *(uint4*)&Klo[prow][pcol + 32] = pre[3];
        __syncthreads();
        if (ct + 1 < NT) {
            const unsigned short* sh = g_kh + kbase + (size_t)((ct + 1) * 64 + prow) * HD + pcol;
            const unsigned short* sl = g_kl + kbase + (size_t)((ct + 1) * 64 + prow) * HD + pcol;
            pre[0] = *(const uint4*)(sh);
            pre[1] = *(const uint4*)(sh + 32);
            pre[2] = *(const uint4*)(sl);
            pre[3] = *(const uint4*)(sl + 32);
        }

        float c[4][4];
#pragma unroll
        for (int nb = 0; nb < 4; ++nb)
#pragma unroll
            for (int r = 0; r < 4; ++r) c[nb][r] = 0.f;

#pragma unroll
        for (int kb = 0; kb < 4; ++kb) {
            unsigned bhf[2][4], blf[2][4];
#pragma unroll
            for (int pr = 0; pr < 2; ++pr) {
                const int r = wk * 32 + pr * 16 + (lane & 7) + ((lane >> 4) << 3);
                const int cc = kb * 16 + (((lane >> 3) & 1) << 3);
                ldsm4(bhf[pr][0], bhf[pr][1], bhf[pr][2], bhf[pr][3], &Khi[r][cc]);
                ldsm4(blf[pr][0], blf[pr][1], blf[pr][2], blf[pr][3], &Klo[r][cc]);
            }
#pragma unroll
            for (int nb = 0; nb < 4; ++nb) {
                const unsigned b0h = bhf[nb >> 1][(nb & 1) * 2];
                const unsigned b1h = bhf[nb >> 1][(nb & 1) * 2 + 1];
                const unsigned b0l = blf[nb >> 1][(nb & 1) * 2];
                const unsigned b1l = blf[nb >> 1][(nb & 1) * 2 + 1];
                mma_bf16(c[nb], qh[kb][0], qh[kb][1], qh[kb][2], qh[kb][3], b0h, b1h);
                mma_bf16(c[nb], qh[kb][0], qh[kb][1], qh[kb][2], qh[kb][3], b0l, b1l);
                mma_bf16(c[nb], ql[kb][0], ql[kb][1], ql[kb][2], ql[kb][3], b0h, b1h);
            }
        }

        // Spill (thread-private, coalesced, streaming) + running row max
        float* base = Ls + (size_t)ct * 4096 + warp * 512 + lane * 4;
#pragma unroll
        for (int nb = 0; nb < 4; ++nb) {
            float4 v;
            v.x = c[nb][0]; v.y = c[nb][1]; v.z = c[nb][2]; v.w = c[nb][3];
            __stcs((float4*)(base + nb * 128), v);
            rm0 = fmaxf(rm0, fmaxf(v.x, v.y));
            rm1 = fmaxf(rm1, fmaxf(v.z, v.w));
        }
    }

    // Row-max reduction
    rm0 = fmaxf(rm0, __shfl_xor_sync(0xffffffffu, rm0, 1));
    rm0 = fmaxf(rm0, __shfl_xor_sync(0xffffffffu, rm0, 2));
    rm1 = fmaxf(rm1, __shfl_xor_sync(0xffffffffu, rm1, 1));
    rm1 = fmaxf(rm1, __shfl_xor_sync(0xffffffffu, rm1, 2));
    const int g = lane >> 2;
    if ((lane & 3) == 0) {
        redA[wk][wm * 16 + g] = rm0;
        redA[wk][wm * 16 + g + 8] = rm1;
    }
    __syncthreads();
    if (tid < 64) rowred[tid] = fmaxf(redA[0][tid], redA[1][tid]);
    __syncthreads();
    const float rx0 = rowred[wm * 16 + g];
    const float rx1 = rowred[wm * 16 + g + 8];

    // ----------------- Phase 2 -----------------
    float O[8][4];
#pragma unroll
    for (int nb = 0; nb < 8; ++nb)
#pragma unroll
        for (int r = 0; r < 4; ++r) O[nb][r] = 0.f;
    float rs0 = 0.f, rs1 = 0.f;

    {
        const unsigned short* sh = g_vh + kbase + (size_t)prow * HD + pcol;
        const unsigned short* sl = g_vl + kbase + (size_t)prow * HD + pcol;
        pre[0] = *(const uint4*)(sh);
        pre[1] = *(const uint4*)(sh + 32);
        pre[2] = *(const uint4*)(sl);
        pre[3] = *(const uint4*)(sl + 32);
    }

    for (int ct = 0; ct < NT; ++ct) {
        float4 L[4];
        const float* sb = Ls + (size_t)ct * 4096 + warp * 512 + lane * 4;
#pragma unroll
        for (int nb = 0; nb < 4; ++nb) L[nb] = __ldcs((const float4*)(sb + nb * 128));

        __syncthreads();
        *(uint4*)&Khi[prow][pcol]      = pre[0];
        *(uint4*)&Khi[prow][pcol + 32] = pre[1];
        *(uint4*)&Klo[prow][pcol]      = pre[2];
        *(uint4*)&Klo[prow][pcol + 32] = pre[3];
        __syncthreads();
        if (ct + 1 < NT) {
            const unsigned short* sh = g_vh + kbase + (size_t)((ct + 1) * 64 + prow) * HD + pcol;
            const unsigned short* sl = g_vl + kbase + (size_t)((ct + 1) * 64 + prow) * HD + pcol;
            pre[0] = *(const uint4*)(sh);
            pre[1] = *(const uint4*)(sh + 32);
            pre[2] = *(const uint4*)(sl);
            pre[3] = *(const uint4*)(sl + 32);
        }

        // s(), rowsum partials, build S fragments (hi/lo) in A-frag layout
        unsigned sh2[2][4], sl2[2][4];
#pragma unroll
        for (int nb = 0; nb < 4; ++nb) {
            const float s0 = stablemax_s(L[nb].x - rx0);
            const float s1 = stablemax_s(L[nb].y - rx0);
            const float s2 = stablemax_s(L[nb].z - rx1);
            const float s3 = stablemax_s(L[nb].w - rx1);
            rs0 += s0 + s1;
            rs1 += s2 + s3;
            const unsigned u0 = split_pack(s0), u1 = split_pack(s1);
            const unsigned u2 = split_pack(s2), u3 = split_pack(s3);
            const int kbp = nb >> 1, half = nb & 1;
            sh2[kbp][half * 2]     = (u0 & 0xffffu) | ((u1 & 0xffffu) << 16);
            sh2[kbp][half * 2 + 1] = (u2 & 0xffffu) | ((u3 & 0xffffu) << 16);
            sl2[kbp][half * 2]     = (u0 >> 16) | (u1 & 0xffff0000u);
            sl2[kbp][half * 2 + 1] = (u2 >> 16) | (u3 & 0xffff0000u);
        }

        // P @ V via HMMA: V loaded with ldmatrix.trans from [k][d] layout
#pragma unroll
        for (int kbp = 0; kbp < 2; ++kbp) {
            const int rbase = wk * 32 + kbp * 16 + (lane & 15);
            const int cbv = ((lane >> 4) << 3);
#pragma unroll
            for (int np = 0; np < 4; ++np) {
                unsigned vh[4], vl[4];
                ldsm4t(vh[0], vh[1], vh[2], vh[3], &Khi[rbase][np * 16 + cbv]);
                ldsm4t(vl[0], vl[1], vl[2], vl[3], &Klo[rbase][np * 16 + cbv]);
#pragma unroll
                for (int qh2 = 0; qh2 < 2; ++qh2) {
                    const int nb = np * 2 + qh2;
                    mma_bf16(O[nb], sh2[kbp][0], sh2[kbp][1], sh2[kbp][2], sh2[kbp][3],
                             vh[qh2 * 2], vh[qh2 * 2 + 1]);
                    mma_bf16(O[nb], sh2[kbp][0], sh2[kbp][1], sh2[kbp][2], sh2[kbp][3],
                             vl[qh2 * 2], vl[qh2 * 2 + 1]);
                    mma_bf16(O[nb], sl2[kbp][0], sl2[kbp][1], sl2[kbp][2], sl2[kbp][3],
                             vh[qh2 * 2], vh[qh2 * 2 + 1]);
                }
            }
        }
    }

    // Row-sum reduction
    rs0 += __shfl_xor_sync(0xffffffffu, rs0, 1);
    rs0 += __shfl_xor_sync(0xffffffffu, rs0, 2);
    rs1 += __shfl_xor_sync(0xffffffffu, rs1, 1);
    rs1 += __shfl_xor_sync(0xffffffffu, rs1, 2);
    if ((lane & 3) == 0) {
        redA[wk][wm * 16 + g] = rs0;
        redA[wk][wm * 16 + g + 8] = rs1;
    }
    __syncthreads();
    if (tid < 64) rowred[tid] = redA[0][tid] + redA[1][tid];
    __syncthreads();

    // Combine the two k-half partials in smem (Osm overlaps dead Q region)
    const int e = lane & 3;
    if (wk == 0) {
#pragma unroll
        for (int nb = 0; nb < 8; ++nb)
#pragma unroll
            for (int r = 0; r < 4; ++r)
                Osm[wm * 16 + g + ((r >> 1) << 3)][nb * 8 + 2 * e + (r & 1)] = O[nb][r];
    }
    __syncthreads();
    if (wk == 1) {
#pragma unroll
        for (int nb = 0; nb < 8; ++nb)
#pragma unroll
            for (int r = 0; r < 4; ++r)
                Osm[wm * 16 + g + ((r >> 1) << 3)][nb * 8 + 2 * e + (r & 1)] += O[nb][r];
    }
    __syncthreads();

    // Normalize + write split ao planes (head-concat layout for proj GEMM)
    const int b = bh >> 4;
    const int h = bh & 15;
    const int trow = tid >> 4;
    const int tcol = (tid & 15) << 2;
#pragma unroll
    for (int p = 0; p < 4; ++p) {
        const int q = p * 16 + trow;
        float4 v = *(float4*)&Osm[q][tcol];
        const float inv = 1.0f / rowred[q];
        v.x *= inv; v.y *= inv; v.z *= inv; v.w *= inv;
        unsigned short h0, h1, h2, h3, l0, l1, l2, l3;
        split2(v.x, h0, l0); split2(v.y, h1, l1);
        split2(v.z, h2, l2); split2(v.w, h3, l3);
        const size_t idx = (size_t)(b * SS + q0 + q) * DD + h * HD + tcol;
        uint2 ph, pl;
        ph.x = (unsigned)h0 | ((unsigned)h1 << 16); ph.y = (unsigned)h2 | ((unsigned)h3 << 16);
        pl.x = (unsigned)l0 | ((unsigned)l1 << 16); pl.y = (unsigned)l2 | ((unsigned)l3 << 16);
        *(uint2*)(g_aoh + idx) = ph;
        *(uint2*)(g_aol + idx) = pl;
    }
}

// ---------------------------------------------------------------------------
// Launch
// ---------------------------------------------------------------------------
extern "C" void kernel_launch(void* const* d_in, const int* in_sizes, int n_in,
                              void* d_out, int out_size) {
    (void)in_sizes; (void)n_in; (void)out_size;
    const float* x    = (const float*)d_in[0];
    const float* wqkv = (const float*)d_in[1];
    const float* wout = (const float*)d_in[2];
    const float* bout = (const float*)d_in[3];
    float* out = (float*)d_out;

    cudaFuncSetAttribute(gemm_kernel<0>, cudaFuncAttributeMaxDynamicSharedMemorySize, 65536);
    cudaFuncSetAttribute(gemm_kernel<1>, cudaFuncAttributeMaxDynamicSharedMemorySize, 65536);

    split_kernel<<<(MROWS * DD / 4 + 255) / 256, 256>>>(x, 0, MROWS * DD / 4);
    split_kernel<<<(3 * DD * DD / 4 + 255) / 256, 256>>>(wqkv, 1, 3 * DD * DD / 4);
    split_kernel<<<(DD * DD / 4 + 255) / 256, 256>>>(wout, 2, DD * DD / 4);

    gemm_kernel<0><<<dim3(3 * DD / 128, MROWS / 128), 256, 65536>>>(nullptr, nullptr);
    attn_kernel<<<BH * (SS / 64), 256>>>();
    gemm_kernel<1><<<dim3(DD / 128, MROWS / 128), 256, 65536>>>(bout, out);
}

// round 10
// speedup vs baseline: 2.2561x; 1.0007x over previous
#include <cuda_runtime.h>
#include <cuda_bf16.h>

#define BB 2
#define SS 2048
#define DD 1024
#define HH 16
#define HD 64
#define BH (BB * HH)        // 32
#define MROWS (BB * SS)     // 4096

// ---------------------------------------------------------------------------
// Device scratch: bf16 hi/lo planes + fp32 logit spill
// ---------------------------------------------------------------------------
__device__ unsigned short g_xh[MROWS * DD],  g_xl[MROWS * DD];        // X split
__device__ unsigned short g_wqh[3 * DD * DD], g_wql[3 * DD * DD];     // Wqkv split
__device__ unsigned short g_woh[DD * DD],    g_wol[DD * DD];          // Wout split
__device__ unsigned short g_qh[BH * SS * HD], g_ql[BH * SS * HD];
__device__ unsigned short g_kh[BH * SS * HD], g_kl[BH * SS * HD];
__device__ unsigned short g_vh[BH * SS * HD], g_vl[BH * SS * HD];
__device__ unsigned short g_aoh[(size_t)MROWS * DD], g_aol[(size_t)MROWS * DD];
__device__ float g_logits[(size_t)BH * SS * SS];                      // 512 MB

// ---------------------------------------------------------------------------
// Helpers
// ---------------------------------------------------------------------------
__device__ __forceinline__ void split2(float f, unsigned short& h, unsigned short& l) {
    __nv_bfloat16 hb = __float2bfloat16(f);
    float r = f - __bfloat162float(hb);
    __nv_bfloat16 lb = __float2bfloat16(r);
    h = __bfloat16_as_ushort(hb);
    l = __bfloat16_as_ushort(lb);
}

__device__ __forceinline__ unsigned split_pack(float f) {
    unsigned short h, l;
    split2(f, h, l);
    return (unsigned)h | ((unsigned)l << 16);
}

__device__ __forceinline__ void mma_bf16(float* c,
                                         unsigned a0, unsigned a1, unsigned a2, unsigned a3,
                                         unsigned b0, unsigned b1) {
    asm volatile(
        "mma.sync.aligned.m16n8k16.row.col.f32.bf16.bf16.f32 "
        "{%0,%1,%2,%3},{%4,%5,%6,%7},{%8,%9},{%0,%1,%2,%3};\n"
        : "+f"(c[0]), "+f"(c[1]), "+f"(c[2]), "+f"(c[3])
        : "r"(a0), "r"(a1), "r"(a2), "r"(a3), "r"(b0), "r"(b1));
}

__device__ __forceinline__ void ldsm4(unsigned& r0, unsigned& r1, unsigned& r2, unsigned& r3,
                                      const void* p) {
    unsigned a = (unsigned)__cvta_generic_to_shared(p);
    asm volatile("ldmatrix.sync.aligned.m8n8.x4.shared.b16 {%0,%1,%2,%3},[%4];\n"
                 : "=r"(r0), "=r"(r1), "=r"(r2), "=r"(r3) : "r"(a));
}

__device__ __forceinline__ void ldsm4t(unsigned& r0, unsigned& r1, unsigned& r2, unsigned& r3,
                                       const void* p) {
    unsigned a = (unsigned)__cvta_generic_to_shared(p);
    asm volatile("ldmatrix.sync.aligned.m8n8.x4.trans.shared.b16 {%0,%1,%2,%3},[%4];\n"
                 : "=r"(r0), "=r"(r1), "=r"(r2), "=r"(r3) : "r"(a));
}

__device__ __forceinline__ void cp16(void* dst, const void* src) {
    unsigned d = (unsigned)__cvta_generic_to_shared(dst);
    asm volatile("cp.async.cg.shared.global [%0],[%1],16;\n" :: "r"(d), "l"(src));
}
__device__ __forceinline__ void cp_commit() { asm volatile("cp.async.commit_group;\n"); }
template <int N>
__device__ __forceinline__ void cp_wait() { asm volatile("cp.async.wait_group %0;\n" :: "n"(N)); }

__device__ __forceinline__ float stablemax_s(float x) {
    if (x >= 0.f) {
        return 1.f + x * (1.f + 0.5f * x * (1.f + x * (1.f / 3.f)));
    } else {
        return 1.f / (1.f - x * (1.f - 0.5f * x * (1.f - x * (1.f / 3.f))));
    }
}

// ---------------------------------------------------------------------------
// One-time split: fp32 -> bf16 hi/lo planes. which: 0=X, 1=Wqkv, 2=Wout
// ---------------------------------------------------------------------------
__global__ void split_kernel(const float* __restrict__ src, int which, int n4) {
    int i = blockIdx.x * blockDim.x + threadIdx.x;
    if (i >= n4) return;
    unsigned short *hi, *lo;
    if (which == 0)      { hi = g_xh;  lo = g_xl;  }
    else if (which == 1) { hi = g_wqh; lo = g_wql; }
    else                 { hi = g_woh; lo = g_wol; }
    float4 v = ((const float4*)src)[i];
    unsigned short h0, h1, h2, h3, l0, l1, l2, l3;
    split2(v.x, h0, l0); split2(v.y, h1, l1);
    split2(v.z, h2, l2); split2(v.w, h3, l3);
    uint2 ph, pl;
    ph.x = (unsigned)h0 | ((unsigned)h1 << 16); ph.y = (unsigned)h2 | ((unsigned)h3 << 16);
    pl.x = (unsigned)l0 | ((unsigned)l1 << 16); pl.y = (unsigned)l2 | ((unsigned)l3 << 16);
    ((uint2*)hi)[i] = ph;
    ((uint2*)lo)[i] = pl;
}

// ---------------------------------------------------------------------------
// GEMM: C[m,n] = sum_k A[m,k]*B[n,k], pre-split bf16 planes, 2-stage cp.async.
// CTA 128x128, kTile 32, 8 warps (2m x 4n), warp tile 64x32.
// Split-term MMAs issued term-outer: same-accumulator reuse distance = 16.
// EPI 0: scatter to q/k/v planes (Q pre-scaled 0.125). EPI 1: +bias -> Cout.
// ---------------------------------------------------------------------------
template <int EPI>
__global__ __launch_bounds__(256)
void gemm_kernel(const float* __restrict__ bias, float* __restrict__ Cout) {
    extern __shared__ unsigned char dynsm[];

    const int tid = threadIdx.x, lane = tid & 31, warp = tid >> 5;
    const int wm = warp >> 2, wn = warp & 3;
    const int m0 = blockIdx.y << 7, n0 = blockIdx.x << 7;

    const unsigned short* AH = (EPI == 0) ? g_xh : g_aoh;
    const unsigned short* AL = (EPI == 0) ? g_xl : g_aol;
    const unsigned short* BH_ = (EPI == 0) ? g_wqh : g_woh;
    const unsigned short* BL_ = (EPI == 0) ? g_wql : g_wol;

    const int lr = tid >> 1;            // 0..127
    const int cb = (tid & 1) * 2;       // chunk base 0 or 2
    const unsigned short* srcs[4] = {
        AH + (size_t)(m0 + lr) * DD, AL + (size_t)(m0 + lr) * DD,
        BH_ + (size_t)(n0 + lr) * DD, BL_ + (size_t)(n0 + lr) * DD };

    const int rsw = (lr >> 1) & 3;      // writer swizzle term

    float acc[4][4][4];
#pragma unroll
    for (int a = 0; a < 4; ++a)
#pragma unroll
        for (int b = 0; b < 4; ++b)
#pragma unroll
            for (int r = 0; r < 4; ++r) acc[a][b][r] = 0.f;

    auto issue = [&](int stage, int kt) {
        unsigned char* sb = dynsm + stage * 32768 + lr * 64;
#pragma unroll
        for (int p = 0; p < 4; ++p) {
            const unsigned short* s = srcs[p] + kt * 32;
#pragma unroll
            for (int cc = 0; cc < 2; ++cc) {
                const int c = cb + cc;
                cp16(sb + p * 8192 + ((c ^ rsw) << 4), s + c * 8);
            }
        }
    };

    const int NKT = DD / 32;  // 32
    issue(0, 0);
    cp_commit();

    for (int kt = 0; kt < NKT; ++kt) {
        if (kt + 1 < NKT) { issue((kt + 1) & 1, kt + 1); cp_commit(); }
        if (kt + 1 < NKT) cp_wait<1>(); else cp_wait<0>();
        __syncthreads();

        const unsigned char* sb = dynsm + (kt & 1) * 32768;
        auto frag_addr = [&](int plane, int r, int halfcol) -> const void* {
            const int chunk = halfcol >> 3;
            return (const void*)(sb + plane * 8192 + r * 64 +
                                 ((chunk ^ ((r >> 1) & 3)) << 4));
        };

#pragma unroll
        for (int kb = 0; kb < 2; ++kb) {
            unsigned ah[4][4], al[4][4];
#pragma unroll
            for (int mb = 0; mb < 4; ++mb) {
                const int r = wm * 64 + mb * 16 + (lane & 15);
                const int c = kb * 16 + ((lane >> 4) << 3);
                ldsm4(ah[mb][0], ah[mb][1], ah[mb][2], ah[mb][3], frag_addr(0, r, c));
                ldsm4(al[mb][0], al[mb][1], al[mb][2], al[mb][3], frag_addr(1, r, c));
            }
            unsigned bhf[2][4], blf[2][4];
#pragma unroll
            for (int pr = 0; pr < 2; ++pr) {
                const int r = wn * 32 + pr * 16 + (lane & 7) + ((lane >> 4) << 3);
                const int c = kb * 16 + (((lane >> 3) & 1) << 3);
                ldsm4(bhf[pr][0], bhf[pr][1], bhf[pr][2], bhf[pr][3], frag_addr(2, r, c));
                ldsm4(blf[pr][0], blf[pr][1], blf[pr][2], blf[pr][3], frag_addr(3, r, c));
            }
            // term-outer: reuse distance 16 between HMMAs on the same accumulator
#pragma unroll
            for (int mb = 0; mb < 4; ++mb)
#pragma unroll
                for (int nb = 0; nb < 4; ++nb)
                    mma_bf16(acc[mb][nb], ah[mb][0], ah[mb][1], ah[mb][2], ah[mb][3],
                             bhf[nb >> 1][(nb & 1) * 2], bhf[nb >> 1][(nb & 1) * 2 + 1]);
#pragma unroll
            for (int mb = 0; mb < 4; ++mb)
#pragma unroll
                for (int nb = 0; nb < 4; ++nb)
                    mma_bf16(acc[mb][nb], ah[mb][0], ah[mb][1], ah[mb][2], ah[mb][3],
                             blf[nb >> 1][(nb & 1) * 2], blf[nb >> 1][(nb & 1) * 2 + 1]);
#pragma unroll
            for (int mb = 0; mb < 4; ++mb)
#pragma unroll
                for (int nb = 0; nb < 4; ++nb)
                    mma_bf16(acc[mb][nb], al[mb][0], al[mb][1], al[mb][2], al[mb][3],
                             bhf[nb >> 1][(nb & 1) * 2], bhf[nb >> 1][(nb & 1) * 2 + 1]);
        }
        __syncthreads();
    }

    // Epilogue
    const int g = lane >> 2, e = lane & 3;
#pragma unroll
    for (int mb = 0; mb < 4; ++mb)
#pragma unroll
        for (int nb = 0; nb < 4; ++nb)
#pragma unroll
            for (int r = 0; r < 4; ++r) {
                const int m = m0 + wm * 64 + mb * 16 + g + ((r >> 1) << 3);
                const int n = n0 + wn * 32 + nb * 8 + 2 * e + (r & 1);
                float v = acc[mb][nb][r];
                if (EPI == 0) {
                    const int which = n >> 10;
                    const int h = (n >> 6) & 15;
                    const int d = n & 63;
                    const int b = m >> 11;
                    const int s = m & 2047;
                    if (which == 0) v *= 0.125f;  // exact pre-scale of Q
                    unsigned short* dh = (which == 0) ? g_qh : ((which == 1) ? g_kh : g_vh);
                    unsigned short* dl = (which == 0) ? g_ql : ((which == 1) ? g_kl : g_vl);
                    const size_t idx = (size_t)((b * HH + h) * SS + s) * HD + d;
                    unsigned short hh, ll;
                    split2(v, hh, ll);
                    dh[idx] = hh;
                    dl[idx] = ll;
                } else {
                    Cout[(size_t)m * DD + n] = v + bias[n];
                }
            }
}

// ---------------------------------------------------------------------------
// Attention: one CTA per (bh, 64-query block), 8 warps (4 q-groups x 2 k-halves).
// Phase 1: QK^T (HMMA, term-outer, dist 4) -> fp32 spill + row max.
// Phase 2: s(), rowsum, P@V (HMMA, np-paired term-outer, dist 4).
// ---------------------------------------------------------------------------
__global__ __launch_bounds__(256)
void attn_kernel() {
    __shared__ __align__(16) unsigned char smraw[36864];
    __shared__ float redA[2][64];
    __shared__ float rowred[64];

    typedef unsigned short usrow[72];
    usrow* Qhi = (usrow*)(smraw);
    usrow* Qlo = (usrow*)(smraw + 9216);
    usrow* Khi = (usrow*)(smraw + 18432);   // V in phase 2
    usrow* Klo = (usrow*)(smraw + 27648);
    typedef float frow[68];
    frow* Osm = (frow*)(smraw);             // overlaps dead Q region

    const int tid = threadIdx.x, lane = tid & 31, warp = tid >> 5;
    const int wm = warp >> 1, wk = warp & 1;
    const int bh = blockIdx.x >> 5;
    const int q0 = (blockIdx.x & 31) << 6;

    const size_t qbase = ((size_t)bh * SS + q0) * HD;
    const size_t kbase = (size_t)bh * SS * HD;
    float* Ls = g_logits + (size_t)blockIdx.x * (64 * SS);

    const int prow = tid >> 2;
    const int pcol = (tid & 3) << 3;

    // Load Q planes into smem
    {
        const unsigned short* sh = g_qh + qbase + (size_t)prow * HD + pcol;
        const unsigned short* sl = g_ql + qbase + (size_t)prow * HD + pcol;
        *(uint4*)&Qhi[prow][pcol]      = *(const uint4*)(sh);
        *(uint4*)&Qhi[prow][pcol + 32] = *(const uint4*)(sh + 32);
        *(uint4*)&Qlo[prow][pcol]      = *(const uint4*)(sl);
        *(uint4*)&Qlo[prow][pcol + 32] = *(const uint4*)(sl + 32);
    }
    // Prefetch K tile 0
    uint4 pre[4];
    {
        const unsigned short* sh = g_kh + kbase + (size_t)prow * HD + pcol;
        const unsigned short* sl = g_kl + kbase + (size_t)prow * HD + pcol;
        pre[0] = *(const uint4*)(sh);
        pre[1] = *(const uint4*)(sh + 32);
        pre[2] = *(const uint4*)(sl);
        pre[3] = *(const uint4*)(sl + 32);
    }
    __syncthreads();

    // Q fragments live in regs for all of phase 1
    unsigned qh[4][4], ql[4][4];
#pragma unroll
    for (int kb = 0; kb < 4; ++kb) {
        const int r = wm * 16 + (lane & 15);
        const int c = kb * 16 + ((lane >> 4) << 3);
        ldsm4(qh[kb][0], qh[kb][1], qh[kb][2], qh[kb][3], &Qhi[r][c]);
        ldsm4(ql[kb][0], ql[kb][1], ql[kb][2], ql[kb][3], &Qlo[r][c]);
    }

    float rm0 = -1e30f, rm1 = -1e30f;
    const int NT = SS / 64;  // 32

    // ----------------- Phase 1 -----------------
    for (int ct = 0; ct < NT; ++ct) {
        __syncthreads();
        *(uint4*)&Khi[prow][pcol]      = pre[0];
        *(uint4*)&Khi[prow][pcol + 32] = pre[1];
        *(uint4*)&Klo[prow][pcol]      = pre[2];
        *(uint4*)&Klo[prow][pcol + 32] = pre[3];
        __syncthreads();
        if (ct + 1 < NT) {
            const unsigned short* sh = g_kh + kbase + (size_t)((ct + 1) * 64 + prow) * HD + pcol;
            const unsigned short* sl = g_kl + kbase + (size_t)((ct + 1) * 64 + prow) * HD + pcol;
            pre[0] = *(const uint4*)(sh);
            pre[1] = *(const uint4*)(sh + 32);
            pre[2] = *(const uint4*)(sl);
            pre[3] = *(const uint4*)(sl + 32);
        }

        float c[4][4];
#pragma unroll
        for (int nb = 0; nb < 4; ++nb)
#pragma unroll
            for (int r = 0; r < 4; ++r) c[nb][r] = 0.f;

#pragma unroll
        for (int kb = 0; kb < 4; ++kb) {
            unsigned bhf[2][4], blf[2][4];
#pragma unroll
            for (int pr = 0; pr < 2; ++pr) {
                const int r = wk * 32 + pr * 16 + (lane & 7) + ((lane >> 4) << 3);
                const int cc = kb * 16 + (((lane >> 3) & 1) << 3);
                ldsm4(bhf[pr][0], bhf[pr][1], bhf[pr][2], bhf[pr][3], &Khi[r][cc]);
                ldsm4(blf[pr][0], blf[pr][1], blf[pr][2], blf[pr][3], &Klo[r][cc]);
            }
            // term-outer: reuse distance 4
#pragma unroll
            for (int nb = 0; nb < 4; ++nb)
                mma_bf16(c[nb], qh[kb][0], qh[kb][1], qh[kb][2], qh[kb][3],
                         bhf[nb >> 1][(nb & 1) * 2], bhf[nb >> 1][(nb & 1) * 2 + 1]);
#pragma unroll
            for (int nb = 0; nb < 4; ++nb)
                mma_bf16(c[nb], qh[kb][0], qh[kb][1], qh[kb][2], qh[kb][3],
                         blf[nb >> 1][(nb & 1) * 2], blf[nb >> 1][(nb & 1) * 2 + 1]);
#pragma unroll
            for (int nb = 0; nb < 4; ++nb)
                mma_bf16(c[nb], ql[kb][0], ql[kb][1], ql[kb][2], ql[kb][3],
                         bhf[nb >> 1][(nb & 1) * 2], bhf[nb >> 1][(nb & 1) * 2 + 1]);
        }

        // Spill (thread-private, coalesced, streaming) + running row max
        float* base = Ls + (size_t)ct * 4096 + warp * 512 + lane * 4;
#pragma unroll
        for (int nb = 0; nb < 4; ++nb) {
            float4 v;
            v.x = c[nb][0]; v.y = c[nb][1]; v.z = c[nb][2]; v.w = c[nb][3];
            __stcs((float4*)(base + nb * 128), v);
            rm0 = fmaxf(rm0, fmaxf(v.x, v.y));
            rm1 = fmaxf(rm1, fmaxf(v.z, v.w));
        }
    }

    // Row-max reduction
    rm0 = fmaxf(rm0, __shfl_xor_sync(0xffffffffu, rm0, 1));
    rm0 = fmaxf(rm0, __shfl_xor_sync(0xffffffffu, rm0, 2));
    rm1 = fmaxf(rm1, __shfl_xor_sync(0xffffffffu, rm1, 1));
    rm1 = fmaxf(rm1, __shfl_xor_sync(0xffffffffu, rm1, 2));
    const int g = lane >> 2;
    if ((lane & 3) == 0) {
        redA[wk][wm * 16 + g] = rm0;
        redA[wk][wm * 16 + g + 8] = rm1;
    }
    __syncthreads();
    if (tid < 64) rowred[tid] = fmaxf(redA[0][tid], redA[1][tid]);
    __syncthreads();
    const float rx0 = rowred[wm * 16 + g];
    const float rx1 = rowred[wm * 16 + g + 8];

    // ----------------- Phase 2 -----------------
    float O[8][4];
#pragma unroll
    for (int nb = 0; nb < 8; ++nb)
#pragma unroll
        for (int r = 0; r < 4; ++r) O[nb][r] = 0.f;
    float rs0 = 0.f, rs1 = 0.f;

    {
        const unsigned short* sh = g_vh + kbase + (size_t)prow * HD + pcol;
        const unsigned short* sl = g_vl + kbase + (size_t)prow * HD + pcol;
        pre[0] = *(const uint4*)(sh);
        pre[1] = *(const uint4*)(sh + 32);
        pre[2] = *(const uint4*)(sl);
        pre[3] = *(const uint4*)(sl + 32);
    }

    for (int ct = 0; ct < NT; ++ct) {
        float4 L[4];
        const float* sb = Ls + (size_t)ct * 4096 + warp * 512 + lane * 4;
#pragma unroll
        for (int nb = 0; nb < 4; ++nb) L[nb] = __ldcs((const float4*)(sb + nb * 128));

        __syncthreads();
        *(uint4*)&Khi[prow][pcol]      = pre[0];
        *(uint4*)&Khi[prow][pcol + 32] = pre[1];
        *(uint4*)&Klo[prow][pcol]      = pre[2];
        *(uint4*)&Klo[prow][pcol + 32] = pre[3];
        __syncthreads();
        if (ct + 1 < NT) {
            const unsigned short* sh = g_vh + kbase + (size_t)((ct + 1) * 64 + prow) * HD + pcol;
            const unsigned short* sl = g_vl + kbase + (size_t)((ct + 1) * 64 + prow) * HD + pcol;
            pre[0] = *(const uint4*)(sh);
            pre[1] = *(const uint4*)(sh + 32);
            pre[2] = *(const uint4*)(sl);
            pre[3] = *(const uint4*)(sl + 32);
        }

        // s(), rowsum partials, build S fragments (hi/lo) in A-frag layout
        unsigned sh2[2][4], sl2[2][4];
#pragma unroll
        for (int nb = 0; nb < 4; ++nb) {
            const float s0 = stablemax_s(L[nb].x - rx0);
            const float s1 = stablemax_s(L[nb].y - rx0);
            const float s2 = stablemax_s(L[nb].z - rx1);
            const float s3 = stablemax_s(L[nb].w - rx1);
            rs0 += s0 + s1;
            rs1 += s2 + s3;
            const unsigned u0 = split_pack(s0), u1 = split_pack(s1);
            const unsigned u2 = split_pack(s2), u3 = split_pack(s3);
            const int kbp = nb >> 1, half = nb & 1;
            sh2[kbp][half * 2]     = (u0 & 0xffffu) | ((u1 & 0xffffu) << 16);
            sh2[kbp][half * 2 + 1] = (u2 & 0xffffu) | ((u3 & 0xffffu) << 16);
            sl2[kbp][half * 2]     = (u0 >> 16) | (u1 & 0xffff0000u);
            sl2[kbp][half * 2 + 1] = (u2 >> 16) | (u3 & 0xffff0000u);
        }

        // P @ V via HMMA: V column pairs held live; term-outer -> dist 4
#pragma unroll
        for (int kbp = 0; kbp < 2; ++kbp) {
            const int rbase = wk * 32 + kbp * 16 + (lane & 15);
            const int cbv = ((lane >> 4) << 3);
#pragma unroll
            for (int npp = 0; npp < 4; npp += 2) {
                unsigned vh[2][4], vl[2][4];
#pragma unroll
                for (int pi = 0; pi < 2; ++pi) {
                    ldsm4t(vh[pi][0], vh[pi][1], vh[pi][2], vh[pi][3],
                           &Khi[rbase][(npp + pi) * 16 + cbv]);
                    ldsm4t(vl[pi][0], vl[pi][1], vl[pi][2], vl[pi][3],
                           &Klo[rbase][(npp + pi) * 16 + cbv]);
                }
#pragma unroll
                for (int pi = 0; pi < 2; ++pi)
#pragma unroll
                    for (int q2 = 0; q2 < 2; ++q2)
                        mma_bf16(O[(npp + pi) * 2 + q2],
                                 sh2[kbp][0], sh2[kbp][1], sh2[kbp][2], sh2[kbp][3],
                                 vh[pi][q2 * 2], vh[pi][q2 * 2 + 1]);
#pragma unroll
                for (int pi = 0; pi < 2; ++pi)
#pragma unroll
                    for (int q2 = 0; q2 < 2; ++q2)
                        mma_bf16(O[(npp + pi) * 2 + q2],
                                 sh2[kbp][0], sh2[kbp][1], sh2[kbp][2], sh2[kbp][3],
                                 vl[pi][q2 * 2], vl[pi][q2 * 2 + 1]);
#pragma unroll
                for (int pi = 0; pi < 2; ++pi)
#pragma unroll
                    for (int q2 = 0; q2 < 2; ++q2)
                        mma_bf16(O[(npp + pi) * 2 + q2],
                                 sl2[kbp][0], sl2[kbp][1], sl2[kbp][2], sl2[kbp][3],
                                 vh[pi][q2 * 2], vh[pi][q2 * 2 + 1]);
            }
        }
    }

    // Row-sum reduction
    rs0 += __shfl_xor_sync(0xffffffffu, rs0, 1);
    rs0 += __shfl_xor_sync(0xffffffffu, rs0, 2);
    rs1 += __shfl_xor_sync(0xffffffffu, rs1, 1);
    rs1 += __shfl_xor_sync(0xffffffffu, rs1, 2);
    if ((lane & 3) == 0) {
        redA[wk][wm * 16 + g] = rs0;
        redA[wk][wm * 16 + g + 8] = rs1;
    }
    __syncthreads();
    if (tid < 64) rowred[tid] = redA[0][tid] + redA[1][tid];
    __syncthreads();

    // Combine the two k-half partials in smem (Osm overlaps dead Q region)
    const int e = lane & 3;
    if (wk == 0) {
#pragma unroll
        for (int nb = 0; nb < 8; ++nb)
#pragma unroll
            for (int r = 0; r < 4; ++r)
                Osm[wm * 16 + g + ((r >> 1) << 3)][nb * 8 + 2 * e + (r & 1)] = O[nb][r];
    }
    __syncthreads();
    if (wk == 1) {
#pragma unroll
        for (int nb = 0; nb < 8; ++nb)
#pragma unroll
            for (int r = 0; r < 4; ++r)
                Osm[wm * 16 + g + ((r >> 1) << 3)][nb * 8 + 2 * e + (r & 1)] += O[nb][r];
    }
    __syncthreads();

    // Normalize + write split ao planes (head-concat layout for proj GEMM)
    const int b = bh >> 4;
    const int h = bh & 15;
    const int trow = tid >> 4;
    const int tcol = (tid & 15) << 2;
#pragma unroll
    for (int p = 0; p < 4; ++p) {
        const int q = p * 16 + trow;
        float4 v = *(float4*)&Osm[q][tcol];
        const float inv = 1.0f / rowred[q];
        v.x *= inv; v.y *= inv; v.z *= inv; v.w *= inv;
        unsigned short h0, h1, h2, h3, l0, l1, l2, l3;
        split2(v.x, h0, l0); split2(v.y, h1, l1);
        split2(v.z, h2, l2); split2(v.w, h3, l3);
        const size_t idx = (size_t)(b * SS + q0 + q) * DD + h * HD + tcol;
        uint2 ph, pl;
        ph.x = (unsigned)h0 | ((unsigned)h1 << 16); ph.y = (unsigned)h2 | ((unsigned)h3 << 16);
        pl.x = (unsigned)l0 | ((unsigned)l1 << 16); pl.y = (unsigned)l2 | ((unsigned)l3 << 16);
        *(uint2*)(g_aoh + idx) = ph;
        *(uint2*)(g_aol + idx) = pl;
    }
}

// ---------------------------------------------------------------------------
// Launch
// ---------------------------------------------------------------------------
extern "C" void kernel_launch(void* const* d_in, const int* in_sizes, int n_in,
                              void* d_out, int out_size) {
    (void)in_sizes; (void)n_in; (void)out_size;
    const float* x    = (const float*)d_in[0];
    const float* wqkv = (const float*)d_in[1];
    const float* wout = (const float*)d_in[2];
    const float* bout = (const float*)d_in[3];
    float* out = (float*)d_out;

    cudaFuncSetAttribute(gemm_kernel<0>, cudaFuncAttributeMaxDynamicSharedMemorySize, 65536);
    cudaFuncSetAttribute(gemm_kernel<1>, cudaFuncAttributeMaxDynamicSharedMemorySize, 65536);

    split_kernel<<<(MROWS * DD / 4 + 255) / 256, 256>>>(x, 0, MROWS * DD / 4);
    split_kernel<<<(3 * DD * DD / 4 + 255) / 256, 256>>>(wqkv, 1, 3 * DD * DD / 4);
    split_kernel<<<(DD * DD / 4 + 255) / 256, 256>>>(wout, 2, DD * DD / 4);

    gemm_kernel<0><<<dim3(3 * DD / 128, MROWS / 128), 256, 65536>>>(nullptr, nullptr);
    attn_kernel<<<BH * (SS / 64), 256>>>();
    gemm_kernel<1><<<dim3(DD / 128, MROWS / 128), 256, 65536>>>(bout, out);
}

// round 11
// speedup vs baseline: 2.2663x; 1.0045x over previous
#include <cuda_runtime.h>
#include <cuda_bf16.h>

#define BB 2
#define SS 2048
#define DD 1024
#define HH 16
#define HD 64
#define BH (BB * HH)        // 32
#define MROWS (BB * SS)     // 4096

// ---------------------------------------------------------------------------
// Device scratch: bf16 hi/lo planes + fp32 logit spill
// ---------------------------------------------------------------------------
__device__ unsigned short g_xh[MROWS * DD],  g_xl[MROWS * DD];        // X split
__device__ unsigned short g_wqh[3 * DD * DD], g_wql[3 * DD * DD];     // Wqkv split
__device__ unsigned short g_woh[DD * DD],    g_wol[DD * DD];          // Wout split
__device__ unsigned short g_qh[BH * SS * HD], g_ql[BH * SS * HD];
__device__ unsigned short g_kh[BH * SS * HD], g_kl[BH * SS * HD];
__device__ unsigned short g_vh[BH * SS * HD], g_vl[BH * SS * HD];
__device__ unsigned short g_aoh[(size_t)MROWS * DD], g_aol[(size_t)MROWS * DD];
__device__ float g_logits[(size_t)BH * SS * SS];                      // 512 MB

// ---------------------------------------------------------------------------
// Helpers
// ---------------------------------------------------------------------------
__device__ __forceinline__ void split2(float f, unsigned short& h, unsigned short& l) {
    __nv_bfloat16 hb = __float2bfloat16(f);
    float r = f - __bfloat162float(hb);
    __nv_bfloat16 lb = __float2bfloat16(r);
    h = __bfloat16_as_ushort(hb);
    l = __bfloat16_as_ushort(lb);
}

__device__ __forceinline__ unsigned split_pack(float f) {
    unsigned short h, l;
    split2(f, h, l);
    return (unsigned)h | ((unsigned)l << 16);
}

__device__ __forceinline__ void mma_bf16(float* c,
                                         unsigned a0, unsigned a1, unsigned a2, unsigned a3,
                                         unsigned b0, unsigned b1) {
    asm volatile(
        "mma.sync.aligned.m16n8k16.row.col.f32.bf16.bf16.f32 "
        "{%0,%1,%2,%3},{%4,%5,%6,%7},{%8,%9},{%0,%1,%2,%3};\n"
        : "+f"(c[0]), "+f"(c[1]), "+f"(c[2]), "+f"(c[3])
        : "r"(a0), "r"(a1), "r"(a2), "r"(a3), "r"(b0), "r"(b1));
}

__device__ __forceinline__ void ldsm4(unsigned& r0, unsigned& r1, unsigned& r2, unsigned& r3,
                                      const void* p) {
    unsigned a = (unsigned)__cvta_generic_to_shared(p);
    asm volatile("ldmatrix.sync.aligned.m8n8.x4.shared.b16 {%0,%1,%2,%3},[%4];\n"
                 : "=r"(r0), "=r"(r1), "=r"(r2), "=r"(r3) : "r"(a));
}

__device__ __forceinline__ void ldsm4t(unsigned& r0, unsigned& r1, unsigned& r2, unsigned& r3,
                                       const void* p) {
    unsigned a = (unsigned)__cvta_generic_to_shared(p);
    asm volatile("ldmatrix.sync.aligned.m8n8.x4.trans.shared.b16 {%0,%1,%2,%3},[%4];\n"
                 : "=r"(r0), "=r"(r1), "=r"(r2), "=r"(r3) : "r"(a));
}

__device__ __forceinline__ void cp16(void* dst, const void* src) {
    unsigned d = (unsigned)__cvta_generic_to_shared(dst);
    asm volatile("cp.async.cg.shared.global [%0],[%1],16;\n" :: "r"(d), "l"(src));
}
__device__ __forceinline__ void cp_commit() { asm volatile("cp.async.commit_group;\n"); }
template <int N>
__device__ __forceinline__ void cp_wait() { asm volatile("cp.async.wait_group %0;\n" :: "n"(N)); }

__device__ __forceinline__ float stablemax_s(float x) {
    if (x >= 0.f) {
        return 1.f + x * (1.f + 0.5f * x * (1.f + x * (1.f / 3.f)));
    } else {
        return 1.f / (1.f - x * (1.f - 0.5f * x * (1.f - x * (1.f / 3.f))));
    }
}

// ---------------------------------------------------------------------------
// One-time split: fp32 -> bf16 hi/lo planes. which: 0=X, 1=Wqkv, 2=Wout
// ---------------------------------------------------------------------------
__global__ void split_kernel(const float* __restrict__ src, int which, int n4) {
    int i = blockIdx.x * blockDim.x + threadIdx.x;
    if (i >= n4) return;
    unsigned short *hi, *lo;
    if (which == 0)      { hi = g_xh;  lo = g_xl;  }
    else if (which == 1) { hi = g_wqh; lo = g_wql; }
    else                 { hi = g_woh; lo = g_wol; }
    float4 v = ((const float4*)src)[i];
    unsigned short h0, h1, h2, h3, l0, l1, l2, l3;
    split2(v.x, h0, l0); split2(v.y, h1, l1);
    split2(v.z, h2, l2); split2(v.w, h3, l3);
    uint2 ph, pl;
    ph.x = (unsigned)h0 | ((unsigned)h1 << 16); ph.y = (unsigned)h2 | ((unsigned)h3 << 16);
    pl.x = (unsigned)l0 | ((unsigned)l1 << 16); pl.y = (unsigned)l2 | ((unsigned)l3 << 16);
    ((uint2*)hi)[i] = ph;
    ((uint2*)lo)[i] = pl;
}

// ---------------------------------------------------------------------------
// GEMM: C[m,n] = sum_k A[m,k]*B[n,k], pre-split bf16 planes.
// CTA tile 128x64, 128 threads, 4 warps (2m x 2n), warp tile 64x32.
// 3-stage cp.async pipeline, ONE barrier per k-tile. 3 CTAs/SM.
// Stage layout (24576 B): Ah[128x64B] @0, Al @8192, Bh[64x64B] @16384, Bl @20480.
// 16B-chunk XOR swizzle: chunk' = chunk ^ ((row>>1)&3)  (conflict-free for
// both the cp.async writers and ldmatrix readers).
// EPI 0: scatter to q/k/v planes (Q pre-scaled 0.125). EPI 1: +bias -> Cout.
// ---------------------------------------------------------------------------
template <int EPI>
__global__ __launch_bounds__(128)
void gemm_kernel(const float* __restrict__ bias, float* __restrict__ Cout) {
    extern __shared__ unsigned char dynsm[];

    const int tid = threadIdx.x, lane = tid & 31, warp = tid >> 5;
    const int wm = warp >> 1, wn = warp & 1;
    const int m0 = blockIdx.y << 7, n0 = blockIdx.x << 6;

    const unsigned short* AH = (EPI == 0) ? g_xh : g_aoh;
    const unsigned short* AL = (EPI == 0) ? g_xl : g_aol;
    const unsigned short* BHp = (EPI == 0) ? g_wqh : g_woh;
    const unsigned short* BLp = (EPI == 0) ? g_wql : g_wol;

    // writer mapping: A row = tid (all 4 chunks, both planes);
    //                 B row = tid>>1, chunk pair = (tid&1)*2
    const unsigned short* a_h = AH + (size_t)(m0 + tid) * DD;
    const unsigned short* a_l = AL + (size_t)(m0 + tid) * DD;
    const int brow = tid >> 1, bco = (tid & 1) * 2;
    const unsigned short* b_h = BHp + (size_t)(n0 + brow) * DD;
    const unsigned short* b_l = BLp + (size_t)(n0 + brow) * DD;
    const int rswA = (tid >> 1) & 3;
    const int rswB = (brow >> 1) & 3;

    auto issue = [&](int stage, int kt) {
        unsigned char* sb = dynsm + stage * 24576;
#pragma unroll
        for (int c = 0; c < 4; ++c) {
            cp16(sb + tid * 64 + ((c ^ rswA) << 4), a_h + kt * 32 + c * 8);
            cp16(sb + 8192 + tid * 64 + ((c ^ rswA) << 4), a_l + kt * 32 + c * 8);
        }
#pragma unroll
        for (int cc = 0; cc < 2; ++cc) {
            const int c = bco + cc;
            cp16(sb + 16384 + brow * 64 + ((c ^ rswB) << 4), b_h + kt * 32 + c * 8);
            cp16(sb + 20480 + brow * 64 + ((c ^ rswB) << 4), b_l + kt * 32 + c * 8);
        }
    };

    float acc[4][4][4];
#pragma unroll
    for (int a = 0; a < 4; ++a)
#pragma unroll
        for (int b = 0; b < 4; ++b)
#pragma unroll
            for (int r = 0; r < 4; ++r) acc[a][b][r] = 0.f;

    const int NKT = DD / 32;  // 32
    issue(0, 0); cp_commit();
    issue(1, 1); cp_commit();

    for (int kt = 0; kt < NKT; ++kt) {
        cp_wait<1>();
        __syncthreads();   // stage kt published to all; stage (kt+2)%3 free to overwrite
        if (kt + 2 < NKT) { issue((kt + 2) % 3, kt + 2); cp_commit(); }

        const unsigned char* sb = dynsm + (kt % 3) * 24576;

#pragma unroll
        for (int kb = 0; kb < 2; ++kb) {
            unsigned ah[4][4], al[4][4];
#pragma unroll
            for (int mb = 0; mb < 4; ++mb) {
                const int r = wm * 64 + mb * 16 + (lane & 15);
                const int chunk = kb * 2 + (lane >> 4);
                const unsigned char* ad = sb + r * 64 + ((chunk ^ ((r >> 1) & 3)) << 4);
                ldsm4(ah[mb][0], ah[mb][1], ah[mb][2], ah[mb][3], ad);
                ldsm4(al[mb][0], al[mb][1], al[mb][2], al[mb][3], ad + 8192);
            }
            unsigned bhf[2][4], blf[2][4];
#pragma unroll
            for (int pr = 0; pr < 2; ++pr) {
                const int r = wn * 32 + pr * 16 + (lane & 7) + ((lane >> 4) << 3);
                const int chunk = kb * 2 + ((lane >> 3) & 1);
                const unsigned char* bd = sb + 16384 + r * 64 + ((chunk ^ ((r >> 1) & 3)) << 4);
                ldsm4(bhf[pr][0], bhf[pr][1], bhf[pr][2], bhf[pr][3], bd);
                ldsm4(blf[pr][0], blf[pr][1], blf[pr][2], blf[pr][3], bd + 4096);
            }
#pragma unroll
            for (int mb = 0; mb < 4; ++mb)
#pragma unroll
                for (int nb = 0; nb < 4; ++nb)
                    mma_bf16(acc[mb][nb], ah[mb][0], ah[mb][1], ah[mb][2], ah[mb][3],
                             bhf[nb >> 1][(nb & 1) * 2], bhf[nb >> 1][(nb & 1) * 2 + 1]);
#pragma unroll
            for (int mb = 0; mb < 4; ++mb)
#pragma unroll
                for (int nb = 0; nb < 4; ++nb)
                    mma_bf16(acc[mb][nb], ah[mb][0], ah[mb][1], ah[mb][2], ah[mb][3],
                             blf[nb >> 1][(nb & 1) * 2], blf[nb >> 1][(nb & 1) * 2 + 1]);
#pragma unroll
            for (int mb = 0; mb < 4; ++mb)
#pragma unroll
                for (int nb = 0; nb < 4; ++nb)
                    mma_bf16(acc[mb][nb], al[mb][0], al[mb][1], al[mb][2], al[mb][3],
                             bhf[nb >> 1][(nb & 1) * 2], bhf[nb >> 1][(nb & 1) * 2 + 1]);
        }
    }

    // Epilogue
    const int g = lane >> 2, e = lane & 3;
#pragma unroll
    for (int mb = 0; mb < 4; ++mb)
#pragma unroll
        for (int nb = 0; nb < 4; ++nb)
#pragma unroll
            for (int r = 0; r < 4; ++r) {
                const int m = m0 + wm * 64 + mb * 16 + g + ((r >> 1) << 3);
                const int n = n0 + wn * 32 + nb * 8 + 2 * e + (r & 1);
                float v = acc[mb][nb][r];
                if (EPI == 0) {
                    const int which = n >> 10;
                    const int h = (n >> 6) & 15;
                    const int d = n & 63;
                    const int b = m >> 11;
                    const int s = m & 2047;
                    if (which == 0) v *= 0.125f;  // exact pre-scale of Q
                    unsigned short* dh = (which == 0) ? g_qh : ((which == 1) ? g_kh : g_vh);
                    unsigned short* dl = (which == 0) ? g_ql : ((which == 1) ? g_kl : g_vl);
                    const size_t idx = (size_t)((b * HH + h) * SS + s) * HD + d;
                    unsigned short hh, ll;
                    split2(v, hh, ll);
                    dh[idx] = hh;
                    dl[idx] = ll;
                } else {
                    Cout[(size_t)m * DD + n] = v + bias[n];
                }
            }
}

// ---------------------------------------------------------------------------
// Attention: one CTA per (bh, 64-query block), 8 warps (4 q-groups x 2 k-halves).
// K/V tiles now stream through a 2-stage cp.async pipeline: ONE barrier/tile.
// Phase 1: QK^T (HMMA) -> fp32 spill + row max. Phase 2: s(), rowsum, P@V.
// Dynamic smem (55296 B): Qhi@0, Qlo@9216, stage s: hi@18432+s*18432, lo=+9216.
// ---------------------------------------------------------------------------
__global__ __launch_bounds__(256)
void attn_kernel() {
    extern __shared__ unsigned char dynsm[];
    __shared__ float redA[2][64];
    __shared__ float rowred[64];

    typedef unsigned short usrow[72];
    usrow* Qhi = (usrow*)(dynsm);
    usrow* Qlo = (usrow*)(dynsm + 9216);
    typedef float frow[68];
    frow* Osm = (frow*)(dynsm);             // overlaps dead Q region at the end

    const int tid = threadIdx.x, lane = tid & 31, warp = tid >> 5;
    const int wm = warp >> 1, wk = warp & 1;
    const int bh = blockIdx.x >> 5;
    const int q0 = (blockIdx.x & 31) << 6;

    const size_t qbase = ((size_t)bh * SS + q0) * HD;
    const size_t kbase = (size_t)bh * SS * HD;
    float* Ls = g_logits + (size_t)blockIdx.x * (64 * SS);

    const int prow = tid >> 2;              // 0..63
    const int pcol = (tid & 3) << 3;        // 0,8,16,24

    // cp.async a K/V tile (2 planes) into pipeline stage
    auto issueKV = [&](const unsigned short* baseH, const unsigned short* baseL,
                       int tile, int stage) {
        unsigned char* sb = dynsm + 18432 + stage * 18432;
        const unsigned short* sh = baseH + (size_t)(tile * 64 + prow) * HD + pcol;
        const unsigned short* sl = baseL + (size_t)(tile * 64 + prow) * HD + pcol;
        cp16(sb + prow * 144 + pcol * 2, sh);
        cp16(sb + prow * 144 + pcol * 2 + 64, sh + 32);
        cp16(sb + 9216 + prow * 144 + pcol * 2, sl);
        cp16(sb + 9216 + prow * 144 + pcol * 2 + 64, sl + 32);
    };

    // Load Q planes into smem (direct)
    {
        const unsigned short* sh = g_qh + qbase + (size_t)prow * HD + pcol;
        const unsigned short* sl = g_ql + qbase + (size_t)prow * HD + pcol;
        *(uint4*)&Qhi[prow][pcol]      = *(const uint4*)(sh);
        *(uint4*)&Qhi[prow][pcol + 32] = *(const uint4*)(sh + 32);
        *(uint4*)&Qlo[prow][pcol]      = *(const uint4*)(sl);
        *(uint4*)&Qlo[prow][pcol + 32] = *(const uint4*)(sl + 32);
    }
    issueKV(g_kh + kbase, g_kl + kbase, 0, 0); cp_commit();
    __syncthreads();   // Q ready

    // Q fragments live in regs for all of phase 1
    unsigned qh[4][4], ql[4][4];
#pragma unroll
    for (int kb = 0; kb < 4; ++kb) {
        const int r = wm * 16 + (lane & 15);
        const int c = kb * 16 + ((lane >> 4) << 3);
        ldsm4(qh[kb][0], qh[kb][1], qh[kb][2], qh[kb][3], &Qhi[r][c]);
        ldsm4(ql[kb][0], ql[kb][1], ql[kb][2], ql[kb][3], &Qlo[r][c]);
    }

    float rm0 = -1e30f, rm1 = -1e30f;
    const int NT = SS / 64;  // 32

    // ----------------- Phase 1 -----------------
    for (int ct = 0; ct < NT; ++ct) {
        cp_wait<0>();
        __syncthreads();   // stage ct published; stage (ct+1)&1 free
        if (ct + 1 < NT) { issueKV(g_kh + kbase, g_kl + kbase, ct + 1, (ct + 1) & 1); cp_commit(); }

        usrow* KH = (usrow*)(dynsm + 18432 + (ct & 1) * 18432);
        usrow* KL = (usrow*)(dynsm + 18432 + (ct & 1) * 18432 + 9216);

        float c[4][4];
#pragma unroll
        for (int nb = 0; nb < 4; ++nb)
#pragma unroll
            for (int r = 0; r < 4; ++r) c[nb][r] = 0.f;

#pragma unroll
        for (int kb = 0; kb < 4; ++kb) {
            unsigned bhf[2][4], blf[2][4];
#pragma unroll
            for (int pr = 0; pr < 2; ++pr) {
                const int r = wk * 32 + pr * 16 + (lane & 7) + ((lane >> 4) << 3);
                const int cc = kb * 16 + (((lane >> 3) & 1) << 3);
                ldsm4(bhf[pr][0], bhf[pr][1], bhf[pr][2], bhf[pr][3], &KH[r][cc]);
                ldsm4(blf[pr][0], blf[pr][1], blf[pr][2], blf[pr][3], &KL[r][cc]);
            }
#pragma unroll
            for (int nb = 0; nb < 4; ++nb)
                mma_bf16(c[nb], qh[kb][0], qh[kb][1], qh[kb][2], qh[kb][3],
                         bhf[nb >> 1][(nb & 1) * 2], bhf[nb >> 1][(nb & 1) * 2 + 1]);
#pragma unroll
            for (int nb = 0; nb < 4; ++nb)
                mma_bf16(c[nb], qh[kb][0], qh[kb][1], qh[kb][2], qh[kb][3],
                         blf[nb >> 1][(nb & 1) * 2], blf[nb >> 1][(nb & 1) * 2 + 1]);
#pragma unroll
            for (int nb = 0; nb < 4; ++nb)
                mma_bf16(c[nb], ql[kb][0], ql[kb][1], ql[kb][2], ql[kb][3],
                         bhf[nb >> 1][(nb & 1) * 2], bhf[nb >> 1][(nb & 1) * 2 + 1]);
        }

        // Spill (thread-private, coalesced, streaming) + running row max
        float* base = Ls + (size_t)ct * 4096 + warp * 512 + lane * 4;
#pragma unroll
        for (int nb = 0; nb < 4; ++nb) {
            float4 v;
            v.x = c[nb][0]; v.y = c[nb][1]; v.z = c[nb][2]; v.w = c[nb][3];
            __stcs((float4*)(base + nb * 128), v);
            rm0 = fmaxf(rm0, fmaxf(v.x, v.y));
            rm1 = fmaxf(rm1, fmaxf(v.z, v.w));
        }
    }

    // Phase-2 V prologue overlaps the reductions (stage 0 was last read at ct=30)
    issueKV(g_vh + kbase, g_vl + kbase, 0, 0); cp_commit();

    // Row-max reduction
    rm0 = fmaxf(rm0, __shfl_xor_sync(0xffffffffu, rm0, 1));
    rm0 = fmaxf(rm0, __shfl_xor_sync(0xffffffffu, rm0, 2));
    rm1 = fmaxf(rm1, __shfl_xor_sync(0xffffffffu, rm1, 1));
    rm1 = fmaxf(rm1, __shfl_xor_sync(0xffffffffu, rm1, 2));
    const int g = lane >> 2;
    if ((lane & 3) == 0) {
        redA[wk][wm * 16 + g] = rm0;
        redA[wk][wm * 16 + g + 8] = rm1;
    }
    __syncthreads();
    if (tid < 64) rowred[tid] = fmaxf(redA[0][tid], redA[1][tid]);
    __syncthreads();
    const float rx0 = rowred[wm * 16 + g];
    const float rx1 = rowred[wm * 16 + g + 8];

    // ----------------- Phase 2 -----------------
    float O[8][4];
#pragma unroll
    for (int nb = 0; nb < 8; ++nb)
#pragma unroll
        for (int r = 0; r < 4; ++r) O[nb][r] = 0.f;
    float rs0 = 0.f, rs1 = 0.f;

    for (int ct = 0; ct < NT; ++ct) {
        float4 L[4];
        const float* sb = Ls + (size_t)ct * 4096 + warp * 512 + lane * 4;
#pragma unroll
        for (int nb = 0; nb < 4; ++nb) L[nb] = __ldcs((const float4*)(sb + nb * 128));

        cp_wait<0>();
        __syncthreads();
        if (ct + 1 < NT) { issueKV(g_vh + kbase, g_vl + kbase, ct + 1, (ct + 1) & 1); cp_commit(); }

        usrow* VH = (usrow*)(dynsm + 18432 + (ct & 1) * 18432);
        usrow* VL = (usrow*)(dynsm + 18432 + (ct & 1) * 18432 + 9216);

        // s(), rowsum partials, build S fragments (hi/lo) in A-frag layout
        unsigned sh2[2][4], sl2[2][4];
#pragma unroll
        for (int nb = 0; nb < 4; ++nb) {
            const float s0 = stablemax_s(L[nb].x - rx0);
            const float s1 = stablemax_s(L[nb].y - rx0);
            const float s2 = stablemax_s(L[nb].z - rx1);
            const float s3 = stablemax_s(L[nb].w - rx1);
            rs0 += s0 + s1;
            rs1 += s2 + s3;
            const unsigned u0 = split_pack(s0), u1 = split_pack(s1);
            const unsigned u2 = split_pack(s2), u3 = split_pack(s3);
            const int kbp = nb >> 1, half = nb & 1;
            sh2[kbp][half * 2]     = (u0 & 0xffffu) | ((u1 & 0xffffu) << 16);
            sh2[kbp][half * 2 + 1] = (u2 & 0xffffu) | ((u3 & 0xffffu) << 16);
            sl2[kbp][half * 2]     = (u0 >> 16) | (u1 & 0xffff0000u);
            sl2[kbp][half * 2 + 1] = (u2 >> 16) | (u3 & 0xffff0000u);
        }

        // P @ V via HMMA: V loaded with ldmatrix.trans from [k][d] layout
#pragma unroll
        for (int kbp = 0; kbp < 2; ++kbp) {
            const int rbase = wk * 32 + kbp * 16 + (lane & 15);
            const int cbv = ((lane >> 4) << 3);
#pragma unroll
            for (int npp = 0; npp < 4; npp += 2) {
                unsigned vh[2][4], vl[2][4];
#pragma unroll
                for (int pi = 0; pi < 2; ++pi) {
                    ldsm4t(vh[pi][0], vh[pi][1], vh[pi][2], vh[pi][3],
                           &VH[rbase][(npp + pi) * 16 + cbv]);
                    ldsm4t(vl[pi][0], vl[pi][1], vl[pi][2], vl[pi][3],
                           &VL[rbase][(npp + pi) * 16 + cbv]);
                }
#pragma unroll
                for (int pi = 0; pi < 2; ++pi)
#pragma unroll
                    for (int q2 = 0; q2 < 2; ++q2)
                        mma_bf16(O[(npp + pi) * 2 + q2],
                                 sh2[kbp][0], sh2[kbp][1], sh2[kbp][2], sh2[kbp][3],
                                 vh[pi][q2 * 2], vh[pi][q2 * 2 + 1]);
#pragma unroll
                for (int pi = 0; pi < 2; ++pi)
#pragma unroll
                    for (int q2 = 0; q2 < 2; ++q2)
                        mma_bf16(O[(npp + pi) * 2 + q2],
                                 sh2[kbp][0], sh2[kbp][1], sh2[kbp][2], sh2[kbp][3],
                                 vl[pi][q2 * 2], vl[pi][q2 * 2 + 1]);
#pragma unroll
                for (int pi = 0; pi < 2; ++pi)
#pragma unroll
                    for (int q2 = 0; q2 < 2; ++q2)
                        mma_bf16(O[(npp + pi) * 2 + q2],
                                 sl2[kbp][0], sl2[kbp][1], sl2[kbp][2], sl2[kbp][3],
                                 vh[pi][q2 * 2], vh[pi][q2 * 2 + 1]);
            }
        }
    }

    // Row-sum reduction
    rs0 += __shfl_xor_sync(0xffffffffu, rs0, 1);
    rs0 += __shfl_xor_sync(0xffffffffu, rs0, 2);
    rs1 += __shfl_xor_sync(0xffffffffu, rs1, 1);
    rs1 += __shfl_xor_sync(0xffffffffu, rs1, 2);
    if ((lane & 3) == 0) {
        redA[wk][wm * 16 + g] = rs0;
        redA[wk][wm * 16 + g + 8] = rs1;
    }
    __syncthreads();
    if (tid < 64) rowred[tid] = redA[0][tid] + redA[1][tid];
    __syncthreads();

    // Combine the two k-half partials in smem (Osm overlaps dead Q region)
    const int e = lane & 3;
    if (wk == 0) {
#pragma unroll
        for (int nb = 0; nb < 8; ++nb)
#pragma unroll
            for (int r = 0; r < 4; ++r)
                Osm[wm * 16 + g + ((r >> 1) << 3)][nb * 8 + 2 * e + (r & 1)] = O[nb][r];
    }
    __syncthreads();
    if (wk == 1) {
#pragma unroll
        for (int nb = 0; nb < 8; ++nb)
#pragma unroll
            for (int r = 0; r < 4; ++r)
                Osm[wm * 16 + g + ((r >> 1) << 3)][nb * 8 + 2 * e + (r & 1)] += O[nb][r];
    }
    __syncthreads();

    // Normalize + write split ao planes (head-concat layout for proj GEMM)
    const int b = bh >> 4;
    const int h = bh & 15;
    const int trow = tid >> 4;
    const int tcol = (tid & 15) << 2;
#pragma unroll
    for (int p = 0; p < 4; ++p) {
        const int q = p * 16 + trow;
        float4 v = *(float4*)&Osm[q][tcol];
        const float inv = 1.0f / rowred[q];
        v.x *= inv; v.y *= inv; v.z *= inv; v.w *= inv;
        unsigned short h0, h1, h2, h3, l0, l1, l2, l3;
        split2(v.x, h0, l0); split2(v.y, h1, l1);
        split2(v.z, h2, l2); split2(v.w, h3, l3);
        const size_t idx = (size_t)(b * SS + q0 + q) * DD + h * HD + tcol;
        uint2 ph, pl;
        ph.x = (unsigned)h0 | ((unsigned)h1 << 16); ph.y = (unsigned)h2 | ((unsigned)h3 << 16);
        pl.x = (unsigned)l0 | ((unsigned)l1 << 16); pl.y = (unsigned)l2 | ((unsigned)l3 << 16);
        *(uint2*)(g_aoh + idx) = ph;
        *(uint2*)(g_aol + idx) = pl;
    }
}

// ---------------------------------------------------------------------------
// Launch
// ---------------------------------------------------------------------------
extern "C" void kernel_launch(void* const* d_in, const int* in_sizes, int n_in,
                              void* d_out, int out_size) {
    (void)in_sizes; (void)n_in; (void)out_size;
    const float* x    = (const float*)d_in[0];
    const float* wqkv = (const float*)d_in[1];
    const float* wout = (const float*)d_in[2];
    const float* bout = (const float*)d_in[3];
    float* out = (float*)d_out;

    cudaFuncSetAttribute(gemm_kernel<0>, cudaFuncAttributeMaxDynamicSharedMemorySize, 73728);
    cudaFuncSetAttribute(gemm_kernel<1>, cudaFuncAttributeMaxDynamicSharedMemorySize, 73728);
    cudaFuncSetAttribute(attn_kernel, cudaFuncAttributeMaxDynamicSharedMemorySize, 55296);

    split_kernel<<<(MROWS * DD / 4 + 255) / 256, 256>>>(x, 0, MROWS * DD / 4);
    split_kernel<<<(3 * DD * DD / 4 + 255) / 256, 256>>>(wqkv, 1, 3 * DD * DD / 4);
    split_kernel<<<(DD * DD / 4 + 255) / 256, 256>>>(wout, 2, DD * DD / 4);

    gemm_kernel<0><<<dim3(3 * DD / 64, MROWS / 128), 128, 73728>>>(nullptr, nullptr);
    attn_kernel<<<BH * (SS / 64), 256, 55296>>>();
    gemm_kernel<1><<<dim3(DD / 64, MROWS / 128), 128, 73728>>>(bout, out);
}

// round 14
// speedup vs baseline: 2.4837x; 1.0959x over previous
#include <cuda_runtime.h>
#include <cuda_bf16.h>

#define BB 2
#define SS 2048
#define DD 1024
#define HH 16
#define HD 64
#define BH (BB * HH)        // 32
#define MROWS (BB * SS)     // 4096

// ---------------------------------------------------------------------------
// Device scratch: bf16 hi/lo planes + fp32 logit spill
// ---------------------------------------------------------------------------
__device__ unsigned short g_xh[MROWS * DD],  g_xl[MROWS * DD];        // X split
__device__ unsigned short g_wqh[3 * DD * DD], g_wql[3 * DD * DD];     // Wqkv split
__device__ unsigned short g_woh[DD * DD],    g_wol[DD * DD];          // Wout split
__device__ unsigned short g_qh[BH * SS * HD], g_ql[BH * SS * HD];
__device__ unsigned short g_kh[BH * SS * HD], g_kl[BH * SS * HD];
__device__ unsigned short g_vh[BH * SS * HD], g_vl[BH * SS * HD];
__device__ unsigned short g_aoh[(size_t)MROWS * DD], g_aol[(size_t)MROWS * DD];
__device__ float g_logits[(size_t)BH * SS * SS];                      // 512 MB

// ---------------------------------------------------------------------------
// Helpers
// ---------------------------------------------------------------------------
__device__ __forceinline__ void split2(float f, unsigned short& h, unsigned short& l) {
    __nv_bfloat16 hb = __float2bfloat16(f);
    float r = f - __bfloat162float(hb);
    __nv_bfloat16 lb = __float2bfloat16(r);
    h = __bfloat16_as_ushort(hb);
    l = __bfloat16_as_ushort(lb);
}

__device__ __forceinline__ unsigned split_pack(float f) {
    unsigned short h, l;
    split2(f, h, l);
    return (unsigned)h | ((unsigned)l << 16);
}

__device__ __forceinline__ void mma_bf16(float* c,
                                         unsigned a0, unsigned a1, unsigned a2, unsigned a3,
                                         unsigned b0, unsigned b1) {
    asm volatile(
        "mma.sync.aligned.m16n8k16.row.col.f32.bf16.bf16.f32 "
        "{%0,%1,%2,%3},{%4,%5,%6,%7},{%8,%9},{%0,%1,%2,%3};\n"
        : "+f"(c[0]), "+f"(c[1]), "+f"(c[2]), "+f"(c[3])
        : "r"(a0), "r"(a1), "r"(a2), "r"(a3), "r"(b0), "r"(b1));
}

__device__ __forceinline__ void ldsm4(unsigned& r0, unsigned& r1, unsigned& r2, unsigned& r3,
                                      const void* p) {
    unsigned a = (unsigned)__cvta_generic_to_shared(p);
    asm volatile("ldmatrix.sync.aligned.m8n8.x4.shared.b16 {%0,%1,%2,%3},[%4];\n"
                 : "=r"(r0), "=r"(r1), "=r"(r2), "=r"(r3) : "r"(a));
}

__device__ __forceinline__ void ldsm4t(unsigned& r0, unsigned& r1, unsigned& r2, unsigned& r3,
                                       const void* p) {
    unsigned a = (unsigned)__cvta_generic_to_shared(p);
    asm volatile("ldmatrix.sync.aligned.m8n8.x4.trans.shared.b16 {%0,%1,%2,%3},[%4];\n"
                 : "=r"(r0), "=r"(r1), "=r"(r2), "=r"(r3) : "r"(a));
}

__device__ __forceinline__ void cp16(void* dst, const void* src) {
    unsigned d = (unsigned)__cvta_generic_to_shared(dst);
    asm volatile("cp.async.cg.shared.global [%0],[%1],16;\n" :: "r"(d), "l"(src));
}
__device__ __forceinline__ void cp_commit() { asm volatile("cp.async.commit_group;\n"); }
template <int N>
__device__ __forceinline__ void cp_wait() { asm volatile("cp.async.wait_group %0;\n" :: "n"(N)); }

__device__ __forceinline__ float stablemax_s(float x) {
    if (x >= 0.f) {
        return 1.f + x * (1.f + 0.5f * x * (1.f + x * (1.f / 3.f)));
    } else {
        return 1.f / (1.f - x * (1.f - 0.5f * x * (1.f - x * (1.f / 3.f))));
    }
}

// ---------------------------------------------------------------------------
// One-time split of ALL fp32 inputs -> bf16 hi/lo planes, single launch.
// Ranges (in float4 units): X [0, 1048576), Wqkv [.., +786432), Wout [.., +262144)
// ---------------------------------------------------------------------------
__global__ void split_all_kernel(const float* __restrict__ x,
                                 const float* __restrict__ wqkv,
                                 const float* __restrict__ wout) {
    int i = blockIdx.x * blockDim.x + threadIdx.x;
    const float* src;
    unsigned short *hi, *lo;
    int j;
    if (i < 1048576) {
        src = x; hi = g_xh; lo = g_xl; j = i;
    } else if (i < 1048576 + 786432) {
        src = wqkv; hi = g_wqh; lo = g_wql; j = i - 1048576;
    } else if (i < 1048576 + 786432 + 262144) {
        src = wout; hi = g_woh; lo = g_wol; j = i - (1048576 + 786432);
    } else {
        return;
    }
    float4 v = ((const float4*)src)[j];
    unsigned short h0, h1, h2, h3, l0, l1, l2, l3;
    split2(v.x, h0, l0); split2(v.y, h1, l1);
    split2(v.z, h2, l2); split2(v.w, h3, l3);
    uint2 ph, pl;
    ph.x = (unsigned)h0 | ((unsigned)h1 << 16); ph.y = (unsigned)h2 | ((unsigned)h3 << 16);
    pl.x = (unsigned)l0 | ((unsigned)l1 << 16); pl.y = (unsigned)l2 | ((unsigned)l3 << 16);
    ((uint2*)hi)[j] = ph;
    ((uint2*)lo)[j] = pl;
}

// ---------------------------------------------------------------------------
// GEMM: C[m,n] = sum_k A[m,k]*B[n,k], pre-split bf16 planes, 2-stage cp.async.
// CTA tile 128x128, 256 threads, 8 warps (2m x 4n), warp tile 64x32.
// (R8/R10 configuration — measured fastest at the mma.sync hardware ceiling.)
// EPI 0: scatter to q/k/v planes (Q pre-scaled 0.125). EPI 1: +bias -> Cout.
// ---------------------------------------------------------------------------
template <int EPI>
__global__ __launch_bounds__(256)
void gemm_kernel(const float* __restrict__ bias, float* __restrict__ Cout) {
    extern __shared__ unsigned char dynsm[];

    const int tid = threadIdx.x, lane = tid & 31, warp = tid >> 5;
    const int wm = warp >> 2, wn = warp & 3;
    const int m0 = blockIdx.y << 7, n0 = blockIdx.x << 7;

    const unsigned short* AH = (EPI == 0) ? g_xh : g_aoh;
    const unsigned short* AL = (EPI == 0) ? g_xl : g_aol;
    const unsigned short* BH_ = (EPI == 0) ? g_wqh : g_woh;
    const unsigned short* BL_ = (EPI == 0) ? g_wql : g_wol;

    const int lr = tid >> 1;            // 0..127
    const int cb = (tid & 1) * 2;       // chunk base 0 or 2
    const unsigned short* srcs[4] = {
        AH + (size_t)(m0 + lr) * DD, AL + (size_t)(m0 + lr) * DD,
        BH_ + (size_t)(n0 + lr) * DD, BL_ + (size_t)(n0 + lr) * DD };

    const int rsw = (lr >> 1) & 3;      // writer swizzle term

    float acc[4][4][4];
#pragma unroll
    for (int a = 0; a < 4; ++a)
#pragma unroll
        for (int b = 0; b < 4; ++b)
#pragma unroll
            for (int r = 0; r < 4; ++r) acc[a][b][r] = 0.f;

    auto issue = [&](int stage, int kt) {
        unsigned char* sb = dynsm + stage * 32768 + lr * 64;
#pragma unroll
        for (int p = 0; p < 4; ++p) {
            const unsigned short* s = srcs[p] + kt * 32;
#pragma unroll
            for (int cc = 0; cc < 2; ++cc) {
                const int c = cb + cc;
                cp16(sb + p * 8192 + ((c ^ rsw) << 4), s + c * 8);
            }
        }
    };

    const int NKT = DD / 32;  // 32
    issue(0, 0);
    cp_commit();

    for (int kt = 0; kt < NKT; ++kt) {
        if (kt + 1 < NKT) { issue((kt + 1) & 1, kt + 1); cp_commit(); }
        if (kt + 1 < NKT) cp_wait<1>(); else cp_wait<0>();
        __syncthreads();

        const unsigned char* sb = dynsm + (kt & 1) * 32768;
        auto frag_addr = [&](int plane, int r, int halfcol) -> const void* {
            const int chunk = halfcol >> 3;
            return (const void*)(sb + plane * 8192 + r * 64 +
                                 ((chunk ^ ((r >> 1) & 3)) << 4));
        };

#pragma unroll
        for (int kb = 0; kb < 2; ++kb) {
            unsigned ah[4][4], al[4][4];
#pragma unroll
            for (int mb = 0; mb < 4; ++mb) {
                const int r = wm * 64 + mb * 16 + (lane & 15);
                const int c = kb * 16 + ((lane >> 4) << 3);
                ldsm4(ah[mb][0], ah[mb][1], ah[mb][2], ah[mb][3], frag_addr(0, r, c));
                ldsm4(al[mb][0], al[mb][1], al[mb][2], al[mb][3], frag_addr(1, r, c));
            }
            unsigned bhf[2][4], blf[2][4];
#pragma unroll
            for (int pr = 0; pr < 2; ++pr) {
                const int r = wn * 32 + pr * 16 + (lane & 7) + ((lane >> 4) << 3);
                const int c = kb * 16 + (((lane >> 3) & 1) << 3);
                ldsm4(bhf[pr][0], bhf[pr][1], bhf[pr][2], bhf[pr][3], frag_addr(2, r, c));
                ldsm4(blf[pr][0], blf[pr][1], blf[pr][2], blf[pr][3], frag_addr(3, r, c));
            }
#pragma unroll
            for (int mb = 0; mb < 4; ++mb)
#pragma unroll
                for (int nb = 0; nb < 4; ++nb)
                    mma_bf16(acc[mb][nb], ah[mb][0], ah[mb][1], ah[mb][2], ah[mb][3],
                             bhf[nb >> 1][(nb & 1) * 2], bhf[nb >> 1][(nb & 1) * 2 + 1]);
#pragma unroll
            for (int mb = 0; mb < 4; ++mb)
#pragma unroll
                for (int nb = 0; nb < 4; ++nb)
                    mma_bf16(acc[mb][nb], ah[mb][0], ah[mb][1], ah[mb][2], ah[mb][3],
                             blf[nb >> 1][(nb & 1) * 2], blf[nb >> 1][(nb & 1) * 2 + 1]);
#pragma unroll
            for (int mb = 0; mb < 4; ++mb)
#pragma unroll
                for (int nb = 0; nb < 4; ++nb)
                    mma_bf16(acc[mb][nb], al[mb][0], al[mb][1], al[mb][2], al[mb][3],
                             bhf[nb >> 1][(nb & 1) * 2], bhf[nb >> 1][(nb & 1) * 2 + 1]);
        }
        __syncthreads();
    }

    // Epilogue
    const int g = lane >> 2, e = lane & 3;
#pragma unroll
    for (int mb = 0; mb < 4; ++mb)
#pragma unroll
        for (int nb = 0; nb < 4; ++nb)
#pragma unroll
            for (int r = 0; r < 4; ++r) {
                const int m = m0 + wm * 64 + mb * 16 + g + ((r >> 1) << 3);
                const int n = n0 + wn * 32 + nb * 8 + 2 * e + (r & 1);
                float v = acc[mb][nb][r];
                if (EPI == 0) {
                    const int which = n >> 10;
                    const int h = (n >> 6) & 15;
                    const int d = n & 63;
                    const int b = m >> 11;
                    const int s = m & 2047;
                    if (which == 0) v *= 0.125f;  // exact pre-scale of Q
                    unsigned short* dh = (which == 0) ? g_qh : ((which == 1) ? g_kh : g_vh);
                    unsigned short* dl = (which == 0) ? g_ql : ((which == 1) ? g_kl : g_vl);
                    const size_t idx = (size_t)((b * HH + h) * SS + s) * HD + d;
                    unsigned short hh, ll;
                    split2(v, hh, ll);
                    dh[idx] = hh;
                    dl[idx] = ll;
                } else {
                    Cout[(size_t)m * DD + n] = v + bias[n];
                }
            }
}

// ---------------------------------------------------------------------------
// Attention: one CTA per (bh, 64-query block), 8 warps (4 q-groups x 2 k-halves).
// K/V tiles stream through a 2-stage cp.async pipeline: ONE barrier/tile.
// Phase 1: QK^T (HMMA) -> fp32 spill + row max. Phase 2: s(), rowsum, P@V.
// Dynamic smem (55296 B): Qhi@0, Qlo@9216, stage s: hi@18432+s*18432, lo=+9216.
// (R11 configuration — measured best attention variant.)
// ---------------------------------------------------------------------------
__global__ __launch_bounds__(256)
void attn_kernel() {
    extern __shared__ unsigned char dynsm[];
    __shared__ float redA[2][64];
    __shared__ float rowred[64];

    typedef unsigned short usrow[72];
    usrow* Qhi = (usrow*)(dynsm);
    usrow* Qlo = (usrow*)(dynsm + 9216);
    typedef float frow[68];
    frow* Osm = (frow*)(dynsm);             // overlaps dead Q region at the end

    const int tid = threadIdx.x, lane = tid & 31, warp = tid >> 5;
    const int wm = warp >> 1, wk = warp & 1;
    const int bh = blockIdx.x >> 5;
    const int q0 = (blockIdx.x & 31) << 6;

    const size_t qbase = ((size_t)bh * SS + q0) * HD;
    const size_t kbase = (size_t)bh * SS * HD;
    float* Ls = g_logits + (size_t)blockIdx.x * (64 * SS);

    const int prow = tid >> 2;              // 0..63
    const int pcol = (tid & 3) << 3;        // 0,8,16,24

    auto issueKV = [&](const unsigned short* baseH, const unsigned short* baseL,
                       int tile, int stage) {
        unsigned char* sb = dynsm + 18432 + stage * 18432;
        const unsigned short* sh = baseH + (size_t)(tile * 64 + prow) * HD + pcol;
        const unsigned short* sl = baseL + (size_t)(tile * 64 + prow) * HD + pcol;
        cp16(sb + prow * 144 + pcol * 2, sh);
        cp16(sb + prow * 144 + pcol * 2 + 64, sh + 32);
        cp16(sb + 9216 + prow * 144 + pcol * 2, sl);
        cp16(sb + 9216 + prow * 144 + pcol * 2 + 64, sl + 32);
    };

    {
        const unsigned short* sh = g_qh + qbase + (size_t)prow * HD + pcol;
        const unsigned short* sl = g_ql + qbase + (size_t)prow * HD + pcol;
        *(uint4*)&Qhi[prow][pcol]      = *(const uint4*)(sh);
        *(uint4*)&Qhi[prow][pcol + 32] = *(const uint4*)(sh + 32);
        *(uint4*)&Qlo[prow][pcol]      = *(const uint4*)(sl);
        *(uint4*)&Qlo[prow][pcol + 32] = *(const uint4*)(sl + 32);
    }
    issueKV(g_kh + kbase, g_kl + kbase, 0, 0); cp_commit();
    __syncthreads();

    unsigned qh[4][4], ql[4][4];
#pragma unroll
    for (int kb = 0; kb < 4; ++kb) {
        const int r = wm * 16 + (lane & 15);
        const int c = kb * 16 + ((lane >> 4) << 3);
        ldsm4(qh[kb][0], qh[kb][1], qh[kb][2], qh[kb][3], &Qhi[r][c]);
        ldsm4(ql[kb][0], ql[kb][1], ql[kb][2], ql[kb][3], &Qlo[r][c]);
    }

    float rm0 = -1e30f, rm1 = -1e30f;
    const int NT = SS / 64;  // 32

    // ----------------- Phase 1 -----------------
    for (int ct = 0; ct < NT; ++ct) {
        cp_wait<0>();
        __syncthreads();
        if (ct + 1 < NT) { issueKV(g_kh + kbase, g_kl + kbase, ct + 1, (ct + 1) & 1); cp_commit(); }

        usrow* KH = (usrow*)(dynsm + 18432 + (ct & 1) * 18432);
        usrow* KL = (usrow*)(dynsm + 18432 + (ct & 1) * 18432 + 9216);

        float c[4][4];
#pragma unroll
        for (int nb = 0; nb < 4; ++nb)
#pragma unroll
            for (int r = 0; r < 4; ++r) c[nb][r] = 0.f;

#pragma unroll
        for (int kb = 0; kb < 4; ++kb) {
            unsigned bhf[2][4], blf[2][4];
#pragma unroll
            for (int pr = 0; pr < 2; ++pr) {
                const int r = wk * 32 + pr * 16 + (lane & 7) + ((lane >> 4) << 3);
                const int cc = kb * 16 + (((lane >> 3) & 1) << 3);
                ldsm4(bhf[pr][0], bhf[pr][1], bhf[pr][2], bhf[pr][3], &KH[r][cc]);
                ldsm4(blf[pr][0], blf[pr][1], blf[pr][2], blf[pr][3], &KL[r][cc]);
            }
#pragma unroll
            for (int nb = 0; nb < 4; ++nb)
                mma_bf16(c[nb], qh[kb][0], qh[kb][1], qh[kb][2], qh[kb][3],
                         bhf[nb >> 1][(nb & 1) * 2], bhf[nb >> 1][(nb & 1) * 2 + 1]);
#pragma unroll
            for (int nb = 0; nb < 4; ++nb)
                mma_bf16(c[nb], qh[kb][0], qh[kb][1], qh[kb][2], qh[kb][3],
                         blf[nb >> 1][(nb & 1) * 2], blf[nb >> 1][(nb & 1) * 2 + 1]);
#pragma unroll
            for (int nb = 0; nb < 4; ++nb)
                mma_bf16(c[nb], ql[kb][0], ql[kb][1], ql[kb][2], ql[kb][3],
                         bhf[nb >> 1][(nb & 1) * 2], bhf[nb >> 1][(nb & 1) * 2 + 1]);
        }

        float* base = Ls + (size_t)ct * 4096 + warp * 512 + lane * 4;
#pragma unroll
        for (int nb = 0; nb < 4; ++nb) {
            float4 v;
            v.x = c[nb][0]; v.y = c[nb][1]; v.z = c[nb][2]; v.w = c[nb][3];
            __stcs((float4*)(base + nb * 128), v);
            rm0 = fmaxf(rm0, fmaxf(v.x, v.y));
            rm1 = fmaxf(rm1, fmaxf(v.z, v.w));
        }
    }

    issueKV(g_vh + kbase, g_vl + kbase, 0, 0); cp_commit();

    rm0 = fmaxf(rm0, __shfl_xor_sync(0xffffffffu, rm0, 1));
    rm0 = fmaxf(rm0, __shfl_xor_sync(0xffffffffu, rm0, 2));
    rm1 = fmaxf(rm1, __shfl_xor_sync(0xffffffffu, rm1, 1));
    rm1 = fmaxf(rm1, __shfl_xor_sync(0xffffffffu, rm1, 2));
    const int g = lane >> 2;
    if ((lane & 3) == 0) {
        redA[wk][wm * 16 + g] = rm0;
        redA[wk][wm * 16 + g + 8] = rm1;
    }
    __syncthreads();
    if (tid < 64) rowred[tid] = fmaxf(redA[0][tid], redA[1][tid]);
    __syncthreads();
    const float rx0 = rowred[wm * 16 + g];
    const float rx1 = rowred[wm * 16 + g + 8];

    // ----------------- Phase 2 -----------------
    float O[8][4];
#pragma unroll
    for (int nb = 0; nb < 8; ++nb)
#pragma unroll
        for (int r = 0; r < 4; ++r) O[nb][r] = 0.f;
    float rs0 = 0.f, rs1 = 0.f;

    for (int ct = 0; ct < NT; ++ct) {
        float4 L[4];
        const float* sb = Ls + (size_t)ct * 4096 + warp * 512 + lane * 4;
#pragma unroll
        for (int nb = 0; nb < 4; ++nb) L[nb] = __ldcs((const float4*)(sb + nb * 128));

        cp_wait<0>();
        __syncthreads();
        if (ct + 1 < NT) { issueKV(g_vh + kbase, g_vl + kbase, ct + 1, (ct + 1) & 1); cp_commit(); }

        usrow* VH = (usrow*)(dynsm + 18432 + (ct & 1) * 18432);
        usrow* VL = (usrow*)(dynsm + 18432 + (ct & 1) * 18432 + 9216);

        unsigned sh2[2][4], sl2[2][4];
#pragma unroll
        for (int nb = 0; nb < 4; ++nb) {
            const float s0 = stablemax_s(L[nb].x - rx0);
            const float s1 = stablemax_s(L[nb].y - rx0);
            const float s2 = stablemax_s(L[nb].z - rx1);
            const float s3 = stablemax_s(L[nb].w - rx1);
            rs0 += s0 + s1;
            rs1 += s2 + s3;
            const unsigned u0 = split_pack(s0), u1 = split_pack(s1);
            const unsigned u2 = split_pack(s2), u3 = split_pack(s3);
            const int kbp = nb >> 1, half = nb & 1;
            sh2[kbp][half * 2]     = (u0 & 0xffffu) | ((u1 & 0xffffu) << 16);
            sh2[kbp][half * 2 + 1] = (u2 & 0xffffu) | ((u3 & 0xffffu) << 16);
            sl2[kbp][half * 2]     = (u0 >> 16) | (u1 & 0xffff0000u);
            sl2[kbp][half * 2 + 1] = (u2 >> 16) | (u3 & 0xffff0000u);
        }

#pragma unroll
        for (int kbp = 0; kbp < 2; ++kbp) {
            const int rbase = wk * 32 + kbp * 16 + (lane & 15);
            const int cbv = ((lane >> 4) << 3);
#pragma unroll
            for (int npp = 0; npp < 4; npp += 2) {
                unsigned vh[2][4], vl[2][4];
#pragma unroll
                for (int pi = 0; pi < 2; ++pi) {
                    ldsm4t(vh[pi][0], vh[pi][1], vh[pi][2], vh[pi][3],
                           &VH[rbase][(npp + pi) * 16 + cbv]);
                    ldsm4t(vl[pi][0], vl[pi][1], vl[pi][2], vl[pi][3],
                           &VL[rbase][(npp + pi) * 16 + cbv]);
                }
#pragma unroll
                for (int pi = 0; pi < 2; ++pi)
#pragma unroll
                    for (int q2 = 0; q2 < 2; ++q2)
                        mma_bf16(O[(npp + pi) * 2 + q2],
                                 sh2[kbp][0], sh2[kbp][1], sh2[kbp][2], sh2[kbp][3],
                                 vh[pi][q2 * 2], vh[pi][q2 * 2 + 1]);
#pragma unroll
                for (int pi = 0; pi < 2; ++pi)
#pragma unroll
                    for (int q2 = 0; q2 < 2; ++q2)
                        mma_bf16(O[(npp + pi) * 2 + q2],
                                 sh2[kbp][0], sh2[kbp][1], sh2[kbp][2], sh2[kbp][3],
                                 vl[pi][q2 * 2], vl[pi][q2 * 2 + 1]);
#pragma unroll
                for (int pi = 0; pi < 2; ++pi)
#pragma unroll
                    for (int q2 = 0; q2 < 2; ++q2)
                        mma_bf16(O[(npp + pi) * 2 + q2],
                                 sl2[kbp][0], sl2[kbp][1], sl2[kbp][2], sl2[kbp][3],
                                 vh[pi][q2 * 2], vh[pi][q2 * 2 + 1]);
            }
        }
    }

    rs0 += __shfl_xor_sync(0xffffffffu, rs0, 1);
    rs0 += __shfl_xor_sync(0xffffffffu, rs0, 2);
    rs1 += __shfl_xor_sync(0xffffffffu, rs1, 1);
    rs1 += __shfl_xor_sync(0xffffffffu, rs1, 2);
    if ((lane & 3) == 0) {
        redA[wk][wm * 16 + g] = rs0;
        redA[wk][wm * 16 + g + 8] = rs1;
    }
    __syncthreads();
    if (tid < 64) rowred[tid] = redA[0][tid] + redA[1][tid];
    __syncthreads();

    const int e = lane & 3;
    if (wk == 0) {
#pragma unroll
        for (int nb = 0; nb < 8; ++nb)
#pragma unroll
            for (int r = 0; r < 4; ++r)
                Osm[wm * 16 + g + ((r >> 1) << 3)][nb * 8 + 2 * e + (r & 1)] = O[nb][r];
    }
    __syncthreads();
    if (wk == 1) {
#pragma unroll
        for (int nb = 0; nb < 8; ++nb)
#pragma unroll
            for (int r = 0; r < 4; ++r)
                Osm[wm * 16 + g + ((r >> 1) << 3)][nb * 8 + 2 * e + (r & 1)] += O[nb][r];
    }
    __syncthreads();

    const int b = bh >> 4;
    const int h = bh & 15;
    const int trow = tid >> 4;
    const int tcol = (tid & 15) << 2;
#pragma unroll
    for (int p = 0; p < 4; ++p) {
        const int q = p * 16 + trow;
        float4 v = *(float4*)&Osm[q][tcol];
        const float inv = 1.0f / rowred[q];
        v.x *= inv; v.y *= inv; v.z *= inv; v.w *= inv;
        unsigned short h0, h1, h2, h3, l0, l1, l2, l3;
        split2(v.x, h0, l0); split2(v.y, h1, l1);
        split2(v.z, h2, l2); split2(v.w, h3, l3);
        const size_t idx = (size_t)(b * SS + q0 + q) * DD + h * HD + tcol;
        uint2 ph, pl;
        ph.x = (unsigned)h0 | ((unsigned)h1 << 16); ph.y = (unsigned)h2 | ((unsigned)h3 << 16);
        pl.x = (unsigned)l0 | ((unsigned)l1 << 16); pl.y = (unsigned)l2 | ((unsigned)l3 << 16);
        *(uint2*)(g_aoh + idx) = ph;
        *(uint2*)(g_aol + idx) = pl;
    }
}

// ---------------------------------------------------------------------------
// Launch
// ---------------------------------------------------------------------------
extern "C" void kernel_launch(void* const* d_in, const int* in_sizes, int n_in,
                              void* d_out, int out_size) {
    (void)in_sizes; (void)n_in; (void)out_size;
    const float* x    = (const float*)d_in[0];
    const float* wqkv = (const float*)d_in[1];
    const float* wout = (const float*)d_in[2];
    const float* bout = (const float*)d_in[3];
    float* out = (float*)d_out;

    cudaFuncSetAttribute(gemm_kernel<0>, cudaFuncAttributeMaxDynamicSharedMemorySize, 65536);
    cudaFuncSetAttribute(gemm_kernel<1>, cudaFuncAttributeMaxDynamicSharedMemorySize, 65536);
    cudaFuncSetAttribute(attn_kernel, cudaFuncAttributeMaxDynamicSharedMemorySize, 55296);

    const int total4 = 1048576 + 786432 + 262144;   // 2,097,152 float4 elements
    split_all_kernel<<<(total4 + 255) / 256, 256>>>(x, wqkv, wout);

    gemm_kernel<0><<<dim3(3 * DD / 128, MROWS / 128), 256, 65536>>>(nullptr, nullptr);
    attn_kernel<<<BH * (SS / 64), 256, 55296>>>();
    gemm_kernel<1><<<dim3(DD / 128, MROWS / 128), 256, 65536>>>(bout, out);
}

// round 15
// speedup vs baseline: 2.7768x; 1.1180x over previous
#include <cuda_runtime.h>
#include <cuda_bf16.h>

#define BB 2
#define SS 2048
#define DD 1024
#define HH 16
#define HD 64
#define BH (BB * HH)        // 32
#define MROWS (BB * SS)     // 4096

// ---------------------------------------------------------------------------
// Device scratch: bf16 hi/lo planes + fp32 logit spill
// ---------------------------------------------------------------------------
__device__ unsigned short g_xh[MROWS * DD],  g_xl[MROWS * DD];        // X split
__device__ unsigned short g_wqh[3 * DD * DD], g_wql[3 * DD * DD];     // Wqkv split
__device__ unsigned short g_woh[DD * DD],    g_wol[DD * DD];          // Wout split
__device__ unsigned short g_qh[BH * SS * HD], g_ql[BH * SS * HD];
__device__ unsigned short g_kh[BH * SS * HD], g_kl[BH * SS * HD];
__device__ unsigned short g_vh[BH * SS * HD], g_vl[BH * SS * HD];
__device__ unsigned short g_aoh[(size_t)MROWS * DD], g_aol[(size_t)MROWS * DD];
__device__ float g_logits[(size_t)BH * SS * SS];                      // 512 MB

// ---------------------------------------------------------------------------
// Helpers
// ---------------------------------------------------------------------------
__device__ __forceinline__ void split2(float f, unsigned short& h, unsigned short& l) {
    __nv_bfloat16 hb = __float2bfloat16(f);
    float r = f - __bfloat162float(hb);
    __nv_bfloat16 lb = __float2bfloat16(r);
    h = __bfloat16_as_ushort(hb);
    l = __bfloat16_as_ushort(lb);
}

__device__ __forceinline__ unsigned split_pack(float f) {
    unsigned short h, l;
    split2(f, h, l);
    return (unsigned)h | ((unsigned)l << 16);
}

__device__ __forceinline__ void mma_bf16(float* c,
                                         unsigned a0, unsigned a1, unsigned a2, unsigned a3,
                                         unsigned b0, unsigned b1) {
    asm volatile(
        "mma.sync.aligned.m16n8k16.row.col.f32.bf16.bf16.f32 "
        "{%0,%1,%2,%3},{%4,%5,%6,%7},{%8,%9},{%0,%1,%2,%3};\n"
        : "+f"(c[0]), "+f"(c[1]), "+f"(c[2]), "+f"(c[3])
        : "r"(a0), "r"(a1), "r"(a2), "r"(a3), "r"(b0), "r"(b1));
}

__device__ __forceinline__ void ldsm4(unsigned& r0, unsigned& r1, unsigned& r2, unsigned& r3,
                                      const void* p) {
    unsigned a = (unsigned)__cvta_generic_to_shared(p);
    asm volatile("ldmatrix.sync.aligned.m8n8.x4.shared.b16 {%0,%1,%2,%3},[%4];\n"
                 : "=r"(r0), "=r"(r1), "=r"(r2), "=r"(r3) : "r"(a));
}

__device__ __forceinline__ void ldsm4t(unsigned& r0, unsigned& r1, unsigned& r2, unsigned& r3,
                                       const void* p) {
    unsigned a = (unsigned)__cvta_generic_to_shared(p);
    asm volatile("ldmatrix.sync.aligned.m8n8.x4.trans.shared.b16 {%0,%1,%2,%3},[%4];\n"
                 : "=r"(r0), "=r"(r1), "=r"(r2), "=r"(r3) : "r"(a));
}

__device__ __forceinline__ void cp16(void* dst, const void* src) {
    unsigned d = (unsigned)__cvta_generic_to_shared(dst);
    asm volatile("cp.async.cg.shared.global [%0],[%1],16;\n" :: "r"(d), "l"(src));
}
__device__ __forceinline__ void cp_commit() { asm volatile("cp.async.commit_group;\n"); }
template <int N>
__device__ __forceinline__ void cp_wait() { asm volatile("cp.async.wait_group %0;\n" :: "n"(N)); }

__device__ __forceinline__ float stablemax_s(float x) {
    if (x >= 0.f) {
        return 1.f + x * (1.f + 0.5f * x * (1.f + x * (1.f / 3.f)));
    } else {
        return 1.f / (1.f - x * (1.f - 0.5f * x * (1.f - x * (1.f / 3.f))));
    }
}

// ---------------------------------------------------------------------------
// One-time split of ALL fp32 inputs -> bf16 hi/lo planes, single launch.
// ---------------------------------------------------------------------------
__global__ void split_all_kernel(const float* __restrict__ x,
                                 const float* __restrict__ wqkv,
                                 const float* __restrict__ wout) {
    int i = blockIdx.x * blockDim.x + threadIdx.x;
    const float* src;
    unsigned short *hi, *lo;
    int j;
    if (i < 1048576) {
        src = x; hi = g_xh; lo = g_xl; j = i;
    } else if (i < 1048576 + 786432) {
        src = wqkv; hi = g_wqh; lo = g_wql; j = i - 1048576;
    } else if (i < 1048576 + 786432 + 262144) {
        src = wout; hi = g_woh; lo = g_wol; j = i - (1048576 + 786432);
    } else {
        return;
    }
    float4 v = ((const float4*)src)[j];
    unsigned short h0, h1, h2, h3, l0, l1, l2, l3;
    split2(v.x, h0, l0); split2(v.y, h1, l1);
    split2(v.z, h2, l2); split2(v.w, h3, l3);
    uint2 ph, pl;
    ph.x = (unsigned)h0 | ((unsigned)h1 << 16); ph.y = (unsigned)h2 | ((unsigned)h3 << 16);
    pl.x = (unsigned)l0 | ((unsigned)l1 << 16); pl.y = (unsigned)l2 | ((unsigned)l3 << 16);
    ((uint2*)hi)[j] = ph;
    ((uint2*)lo)[j] = pl;
}

// ---------------------------------------------------------------------------
// GEMM: C[m,n] = sum_k A[m,k]*B[n,k], pre-split bf16 planes, 2-stage cp.async.
// CTA tile 128x128, 256 threads, 8 warps (2m x 4n), warp tile 64x32.
// Epilogue stages accumulators through smem -> fully coalesced stores.
// EPI 0: scatter to q/k/v planes (Q pre-scaled 0.125). EPI 1: +bias -> Cout.
// ---------------------------------------------------------------------------
template <int EPI>
__global__ __launch_bounds__(256)
void gemm_kernel(const float* __restrict__ bias, float* __restrict__ Cout) {
    extern __shared__ unsigned char dynsm[];

    const int tid = threadIdx.x, lane = tid & 31, warp = tid >> 5;
    const int wm = warp >> 2, wn = warp & 3;
    const int m0 = blockIdx.y << 7, n0 = blockIdx.x << 7;

    const unsigned short* AH = (EPI == 0) ? g_xh : g_aoh;
    const unsigned short* AL = (EPI == 0) ? g_xl : g_aol;
    const unsigned short* BH_ = (EPI == 0) ? g_wqh : g_woh;
    const unsigned short* BL_ = (EPI == 0) ? g_wql : g_wol;

    const int lr = tid >> 1;            // 0..127
    const int cb = (tid & 1) * 2;       // chunk base 0 or 2
    const unsigned short* srcs[4] = {
        AH + (size_t)(m0 + lr) * DD, AL + (size_t)(m0 + lr) * DD,
        BH_ + (size_t)(n0 + lr) * DD, BL_ + (size_t)(n0 + lr) * DD };

    const int rsw = (lr >> 1) & 3;      // writer swizzle term

    float acc[4][4][4];
#pragma unroll
    for (int a = 0; a < 4; ++a)
#pragma unroll
        for (int b = 0; b < 4; ++b)
#pragma unroll
            for (int r = 0; r < 4; ++r) acc[a][b][r] = 0.f;

    auto issue = [&](int stage, int kt) {
        unsigned char* sb = dynsm + stage * 32768 + lr * 64;
#pragma unroll
        for (int p = 0; p < 4; ++p) {
            const unsigned short* s = srcs[p] + kt * 32;
#pragma unroll
            for (int cc = 0; cc < 2; ++cc) {
                const int c = cb + cc;
                cp16(sb + p * 8192 + ((c ^ rsw) << 4), s + c * 8);
            }
        }
    };

    const int NKT = DD / 32;  // 32
    issue(0, 0);
    cp_commit();

    for (int kt = 0; kt < NKT; ++kt) {
        if (kt + 1 < NKT) { issue((kt + 1) & 1, kt + 1); cp_commit(); }
        if (kt + 1 < NKT) cp_wait<1>(); else cp_wait<0>();
        __syncthreads();

        const unsigned char* sb = dynsm + (kt & 1) * 32768;
        auto frag_addr = [&](int plane, int r, int halfcol) -> const void* {
            const int chunk = halfcol >> 3;
            return (const void*)(sb + plane * 8192 + r * 64 +
                                 ((chunk ^ ((r >> 1) & 3)) << 4));
        };

#pragma unroll
        for (int kb = 0; kb < 2; ++kb) {
            unsigned ah[4][4], al[4][4];
#pragma unroll
            for (int mb = 0; mb < 4; ++mb) {
                const int r = wm * 64 + mb * 16 + (lane & 15);
                const int c = kb * 16 + ((lane >> 4) << 3);
                ldsm4(ah[mb][0], ah[mb][1], ah[mb][2], ah[mb][3], frag_addr(0, r, c));
                ldsm4(al[mb][0], al[mb][1], al[mb][2], al[mb][3], frag_addr(1, r, c));
            }
            unsigned bhf[2][4], blf[2][4];
#pragma unroll
            for (int pr = 0; pr < 2; ++pr) {
                const int r = wn * 32 + pr * 16 + (lane & 7) + ((lane >> 4) << 3);
                const int c = kb * 16 + (((lane >> 3) & 1) << 3);
                ldsm4(bhf[pr][0], bhf[pr][1], bhf[pr][2], bhf[pr][3], frag_addr(2, r, c));
                ldsm4(blf[pr][0], blf[pr][1], blf[pr][2], blf[pr][3], frag_addr(3, r, c));
            }
#pragma unroll
            for (int mb = 0; mb < 4; ++mb)
#pragma unroll
                for (int nb = 0; nb < 4; ++nb)
                    mma_bf16(acc[mb][nb], ah[mb][0], ah[mb][1], ah[mb][2], ah[mb][3],
                             bhf[nb >> 1][(nb & 1) * 2], bhf[nb >> 1][(nb & 1) * 2 + 1]);
#pragma unroll
            for (int mb = 0; mb < 4; ++mb)
#pragma unroll
                for (int nb = 0; nb < 4; ++nb)
                    mma_bf16(acc[mb][nb], ah[mb][0], ah[mb][1], ah[mb][2], ah[mb][3],
                             blf[nb >> 1][(nb & 1) * 2], blf[nb >> 1][(nb & 1) * 2 + 1]);
#pragma unroll
            for (int mb = 0; mb < 4; ++mb)
#pragma unroll
                for (int nb = 0; nb < 4; ++nb)
                    mma_bf16(acc[mb][nb], al[mb][0], al[mb][1], al[mb][2], al[mb][3],
                             bhf[nb >> 1][(nb & 1) * 2], bhf[nb >> 1][(nb & 1) * 2 + 1]);
        }
        __syncthreads();
    }

    // ----- Epilogue: stage through smem, coalesced writes -----
    const int g = lane >> 2, e = lane & 3;
    float* sf = (float*)dynsm;          // staging: 64 rows x 136 floats (34816 B)

#pragma unroll
    for (int half = 0; half < 2; ++half) {
        __syncthreads();
        if (wm == half) {
#pragma unroll
            for (int mb = 0; mb < 4; ++mb)
#pragma unroll
                for (int nb = 0; nb < 4; ++nb) {
                    const int rl = mb * 16 + g;
                    const int cc = wn * 32 + nb * 8 + 2 * e;
                    *(float2*)&sf[rl * 136 + cc] =
                        make_float2(acc[mb][nb][0], acc[mb][nb][1]);
                    *(float2*)&sf[(rl + 8) * 136 + cc] =
                        make_float2(acc[mb][nb][2], acc[mb][nb][3]);
                }
        }
        __syncthreads();

#pragma unroll
        for (int it = 0; it < 8; ++it) {
            const int idx = it * 256 + tid;
            const int r = idx >> 5;            // 0..63
            const int gc = idx & 31;           // col group (4 floats)
            const int m = m0 + half * 64 + r;
            const int n = n0 + gc * 4;
            float4 v = *(float4*)&sf[r * 136 + gc * 4];
            if (EPI == 1) {
                const float4 bv = *(const float4*)(bias + n);
                v.x += bv.x; v.y += bv.y; v.z += bv.z; v.w += bv.w;
                *(float4*)&Cout[(size_t)m * DD + n] = v;
            } else {
                const int which = n >> 10;
                const int h = (n >> 6) & 15;
                const int d = n & 63;
                const int b = m >> 11;
                const int s = m & 2047;
                const float sc = (which == 0) ? 0.125f : 1.0f;  // exact Q pre-scale
                v.x *= sc; v.y *= sc; v.z *= sc; v.w *= sc;
                unsigned short h0, h1, h2, h3, l0, l1, l2, l3;
                split2(v.x, h0, l0); split2(v.y, h1, l1);
                split2(v.z, h2, l2); split2(v.w, h3, l3);
                uint2 ph, pl;
                ph.x = (unsigned)h0 | ((unsigned)h1 << 16);
                ph.y = (unsigned)h2 | ((unsigned)h3 << 16);
                pl.x = (unsigned)l0 | ((unsigned)l1 << 16);
                pl.y = (unsigned)l2 | ((unsigned)l3 << 16);
                unsigned short* dh = (which == 0) ? g_qh : ((which == 1) ? g_kh : g_vh);
                unsigned short* dl = (which == 0) ? g_ql : ((which == 1) ? g_kl : g_vl);
                const size_t ix = (size_t)((b * HH + h) * SS + s) * HD + d;
                *(uint2*)(dh + ix) = ph;
                *(uint2*)(dl + ix) = pl;
            }
        }
    }
}

// ---------------------------------------------------------------------------
// Attention: one CTA per (bh, 64-query block), 8 warps (4 q-groups x 2 k-halves).
// K/V tiles stream through a 2-stage cp.async pipeline: ONE barrier/tile.
// Phase 1: QK^T (HMMA) -> fp32 spill + row max. Phase 2: s(), rowsum, P@V.
// Dynamic smem (55296 B): Qhi@0, Qlo@9216, stage s: hi@18432+s*18432, lo=+9216.
// ---------------------------------------------------------------------------
__global__ __launch_bounds__(256)
void attn_kernel() {
    extern __shared__ unsigned char dynsm[];
    __shared__ float redA[2][64];
    __shared__ float rowred[64];

    typedef unsigned short usrow[72];
    usrow* Qhi = (usrow*)(dynsm);
    usrow* Qlo = (usrow*)(dynsm + 9216);
    typedef float frow[68];
    frow* Osm = (frow*)(dynsm);             // overlaps dead Q region at the end

    const int tid = threadIdx.x, lane = tid & 31, warp = tid >> 5;
    const int wm = warp >> 1, wk = warp & 1;
    const int bh = blockIdx.x >> 5;
    const int q0 = (blockIdx.x & 31) << 6;

    const size_t qbase = ((size_t)bh * SS + q0) * HD;
    const size_t kbase = (size_t)bh * SS * HD;
    float* Ls = g_logits + (size_t)blockIdx.x * (64 * SS);

    const int prow = tid >> 2;              // 0..63
    const int pcol = (tid & 3) << 3;        // 0,8,16,24

    auto issueKV = [&](const unsigned short* baseH, const unsigned short* baseL,
                       int tile, int stage) {
        unsigned char* sb = dynsm + 18432 + stage * 18432;
        const unsigned short* sh = baseH + (size_t)(tile * 64 + prow) * HD + pcol;
        const unsigned short* sl = baseL + (size_t)(tile * 64 + prow) * HD + pcol;
        cp16(sb + prow * 144 + pcol * 2, sh);
        cp16(sb + prow * 144 + pcol * 2 + 64, sh + 32);
        cp16(sb + 9216 + prow * 144 + pcol * 2, sl);
        cp16(sb + 9216 + prow * 144 + pcol * 2 + 64, sl + 32);
    };

    {
        const unsigned short* sh = g_qh + qbase + (size_t)prow * HD + pcol;
        const unsigned short* sl = g_ql + qbase + (size_t)prow * HD + pcol;
        *(uint4*)&Qhi[prow][pcol]      = *(const uint4*)(sh);
        *(uint4*)&Qhi[prow][pcol + 32] = *(const uint4*)(sh + 32);
        *(uint4*)&Qlo[prow][pcol]      = *(const uint4*)(sl);
        *(uint4*)&Qlo[prow][pcol + 32] = *(const uint4*)(sl + 32);
    }
    issueKV(g_kh + kbase, g_kl + kbase, 0, 0); cp_commit();
    __syncthreads();

    unsigned qh[4][4], ql[4][4];
#pragma unroll
    for (int kb = 0; kb < 4; ++kb) {
        const int r = wm * 16 + (lane & 15);
        const int c = kb * 16 + ((lane >> 4) << 3);
        ldsm4(qh[kb][0], qh[kb][1], qh[kb][2], qh[kb][3], &Qhi[r][c]);
        ldsm4(ql[kb][0], ql[kb][1], ql[kb][2], ql[kb][3], &Qlo[r][c]);
    }

    float rm0 = -1e30f, rm1 = -1e30f;
    const int NT = SS / 64;  // 32

    // ----------------- Phase 1 -----------------
    for (int ct = 0; ct < NT; ++ct) {
        cp_wait<0>();
        __syncthreads();
        if (ct + 1 < NT) { issueKV(g_kh + kbase, g_kl + kbase, ct + 1, (ct + 1) & 1); cp_commit(); }

        usrow* KH = (usrow*)(dynsm + 18432 + (ct & 1) * 18432);
        usrow* KL = (usrow*)(dynsm + 18432 + (ct & 1) * 18432 + 9216);

        float c[4][4];
#pragma unroll
        for (int nb = 0; nb < 4; ++nb)
#pragma unroll
            for (int r = 0; r < 4; ++r) c[nb][r] = 0.f;

#pragma unroll
        for (int kb = 0; kb < 4; ++kb) {
            unsigned bhf[2][4], blf[2][4];
#pragma unroll
            for (int pr = 0; pr < 2; ++pr) {
                const int r = wk * 32 + pr * 16 + (lane & 7) + ((lane >> 4) << 3);
                const int cc = kb * 16 + (((lane >> 3) & 1) << 3);
                ldsm4(bhf[pr][0], bhf[pr][1], bhf[pr][2], bhf[pr][3], &KH[r][cc]);
                ldsm4(blf[pr][0], blf[pr][1], blf[pr][2], blf[pr][3], &KL[r][cc]);
            }
#pragma unroll
            for (int nb = 0; nb < 4; ++nb)
                mma_bf16(c[nb], qh[kb][0], qh[kb][1], qh[kb][2], qh[kb][3],
                         bhf[nb >> 1][(nb & 1) * 2], bhf[nb >> 1][(nb & 1) * 2 + 1]);
#pragma unroll
            for (int nb = 0; nb < 4; ++nb)
                mma_bf16(c[nb], qh[kb][0], qh[kb][1], qh[kb][2], qh[kb][3],
                         blf[nb >> 1][(nb & 1) * 2], blf[nb >> 1][(nb & 1) * 2 + 1]);
#pragma unroll
            for (int nb = 0; nb < 4; ++nb)
                mma_bf16(c[nb], ql[kb][0], ql[kb][1], ql[kb][2], ql[kb][3],
                         bhf[nb >> 1][(nb & 1) * 2], bhf[nb >> 1][(nb & 1) * 2 + 1]);
        }

        float* base = Ls + (size_t)ct * 4096 + warp * 512 + lane * 4;
#pragma unroll
        for (int nb = 0; nb < 4; ++nb) {
            float4 v;
            v.x = c[nb][0]; v.y = c[nb][1]; v.z = c[nb][2]; v.w = c[nb][3];
            __stcs((float4*)(base + nb * 128), v);
            rm0 = fmaxf(rm0, fmaxf(v.x, v.y));
            rm1 = fmaxf(rm1, fmaxf(v.z, v.w));
        }
    }

    issueKV(g_vh + kbase, g_vl + kbase, 0, 0); cp_commit();

    rm0 = fmaxf(rm0, __shfl_xor_sync(0xffffffffu, rm0, 1));
    rm0 = fmaxf(rm0, __shfl_xor_sync(0xffffffffu, rm0, 2));
    rm1 = fmaxf(rm1, __shfl_xor_sync(0xffffffffu, rm1, 1));
    rm1 = fmaxf(rm1, __shfl_xor_sync(0xffffffffu, rm1, 2));
    const int g = lane >> 2;
    if ((lane & 3) == 0) {
        redA[wk][wm * 16 + g] = rm0;
        redA[wk][wm * 16 + g + 8] = rm1;
    }
    __syncthreads();
    if (tid < 64) rowred[tid] = fmaxf(redA[0][tid], redA[1][tid]);
    __syncthreads();
    const float rx0 = rowred[wm * 16 + g];
    const float rx1 = rowred[wm * 16 + g + 8];

    // ----------------- Phase 2 -----------------
    float O[8][4];
#pragma unroll
    for (int nb = 0; nb < 8; ++nb)
#pragma unroll
        for (int r = 0; r < 4; ++r) O[nb][r] = 0.f;
    float rs0 = 0.f, rs1 = 0.f;

    for (int ct = 0; ct < NT; ++ct) {
        float4 L[4];
        const float* sb = Ls + (size_t)ct * 4096 + warp * 512 + lane * 4;
#pragma unroll
        for (int nb = 0; nb < 4; ++nb) L[nb] = __ldcs((const float4*)(sb + nb * 128));

        cp_wait<0>();
        __syncthreads();
        if (ct + 1 < NT) { issueKV(g_vh + kbase, g_vl + kbase, ct + 1, (ct + 1) & 1); cp_commit(); }

        usrow* VH = (usrow*)(dynsm + 18432 + (ct & 1) * 18432);
        usrow* VL = (usrow*)(dynsm + 18432 + (ct & 1) * 18432 + 9216);

        unsigned sh2[2][4], sl2[2][4];
#pragma unroll
        for (int nb = 0; nb < 4; ++nb) {
            const float s0 = stablemax_s(L[nb].x - rx0);
            const float s1 = stablemax_s(L[nb].y - rx0);
            const float s2 = stablemax_s(L[nb].z - rx1);
            const float s3 = stablemax_s(L[nb].w - rx1);
            rs0 += s0 + s1;
            rs1 += s2 + s3;
            const unsigned u0 = split_pack(s0), u1 = split_pack(s1);
            const unsigned u2 = split_pack(s2), u3 = split_pack(s3);
            const int kbp = nb >> 1, half = nb & 1;
            sh2[kbp][half * 2]     = (u0 & 0xffffu) | ((u1 & 0xffffu) << 16);
            sh2[kbp][half * 2 + 1] = (u2 & 0xffffu) | ((u3 & 0xffffu) << 16);
            sl2[kbp][half * 2]     = (u0 >> 16) | (u1 & 0xffff0000u);
            sl2[kbp][half * 2 + 1] = (u2 >> 16) | (u3 & 0xffff0000u);
        }

#pragma unroll
        for (int kbp = 0; kbp < 2; ++kbp) {
            const int rbase = wk * 32 + kbp * 16 + (lane & 15);
            const int cbv = ((lane >> 4) << 3);
#pragma unroll
            for (int npp = 0; npp < 4; npp += 2) {
                unsigned vh[2][4], vl[2][4];
#pragma unroll
                for (int pi = 0; pi < 2; ++pi) {
                    ldsm4t(vh[pi][0], vh[pi][1], vh[pi][2], vh[pi][3],
                           &VH[rbase][(npp + pi) * 16 + cbv]);
                    ldsm4t(vl[pi][0], vl[pi][1], vl[pi][2], vl[pi][3],
                           &VL[rbase][(npp + pi) * 16 + cbv]);
                }
#pragma unroll
                for (int pi = 0; pi < 2; ++pi)
#pragma unroll
                    for (int q2 = 0; q2 < 2; ++q2)
                        mma_bf16(O[(npp + pi) * 2 + q2],
                                 sh2[kbp][0], sh2[kbp][1], sh2[kbp][2], sh2[kbp][3],
                                 vh[pi][q2 * 2], vh[pi][q2 * 2 + 1]);
#pragma unroll
                for (int pi = 0; pi < 2; ++pi)
#pragma unroll
                    for (int q2 = 0; q2 < 2; ++q2)
                        mma_bf16(O[(npp + pi) * 2 + q2],
                                 sh2[kbp][0], sh2[kbp][1], sh2[kbp][2], sh2[kbp][3],
                                 vl[pi][q2 * 2], vl[pi][q2 * 2 + 1]);
#pragma unroll
                for (int pi = 0; pi < 2; ++pi)
#pragma unroll
                    for (int q2 = 0; q2 < 2; ++q2)
                        mma_bf16(O[(npp + pi) * 2 + q2],
                                 sl2[kbp][0], sl2[kbp][1], sl2[kbp][2], sl2[kbp][3],
                                 vh[pi][q2 * 2], vh[pi][q2 * 2 + 1]);
            }
        }
    }

    rs0 += __shfl_xor_sync(0xffffffffu, rs0, 1);
    rs0 += __shfl_xor_sync(0xffffffffu, rs0, 2);
    rs1 += __shfl_xor_sync(0xffffffffu, rs1, 1);
    rs1 += __shfl_xor_sync(0xffffffffu, rs1, 2);
    if ((lane & 3) == 0) {
        redA[wk][wm * 16 + g] = rs0;
        redA[wk][wm * 16 + g + 8] = rs1;
    }
    __syncthreads();
    if (tid < 64) rowred[tid] = redA[0][tid] + redA[1][tid];
    __syncthreads();

    const int e = lane & 3;
    if (wk == 0) {
#pragma unroll
        for (int nb = 0; nb < 8; ++nb)
#pragma unroll
            for (int r = 0; r < 4; ++r)
                Osm[wm * 16 + g + ((r >> 1) << 3)][nb * 8 + 2 * e + (r & 1)] = O[nb][r];
    }
    __syncthreads();
    if (wk == 1) {
#pragma unroll
        for (int nb = 0; nb < 8; ++nb)
#pragma unroll
            for (int r = 0; r < 4; ++r)
                Osm[wm * 16 + g + ((r >> 1) << 3)][nb * 8 + 2 * e + (r & 1)] += O[nb][r];
    }
    __syncthreads();

    const int b = bh >> 4;
    const int h = bh & 15;
    const int trow = tid >> 4;
    const int tcol = (tid & 15) << 2;
#pragma unroll
    for (int p = 0; p < 4; ++p) {
        const int q = p * 16 + trow;
        float4 v = *(float4*)&Osm[q][tcol];
        const float inv = 1.0f / rowred[q];
        v.x *= inv; v.y *= inv; v.z *= inv; v.w *= inv;
        unsigned short h0, h1, h2, h3, l0, l1, l2, l3;
        split2(v.x, h0, l0); split2(v.y, h1, l1);
        split2(v.z, h2, l2); split2(v.w, h3, l3);
        const size_t idx = (size_t)(b * SS + q0 + q) * DD + h * HD + tcol;
        uint2 ph, pl;
        ph.x = (unsigned)h0 | ((unsigned)h1 << 16); ph.y = (unsigned)h2 | ((unsigned)h3 << 16);
        pl.x = (unsigned)l0 | ((unsigned)l1 << 16); pl.y = (unsigned)l2 | ((unsigned)l3 << 16);
        *(uint2*)(g_aoh + idx) = ph;
        *(uint2*)(g_aol + idx) = pl;
    }
}

// ---------------------------------------------------------------------------
// Launch
// ---------------------------------------------------------------------------
extern "C" void kernel_launch(void* const* d_in, const int* in_sizes, int n_in,
                              void* d_out, int out_size) {
    (void)in_sizes; (void)n_in; (void)out_size;
    const float* x    = (const float*)d_in[0];
    const float* wqkv = (const float*)d_in[1];
    const float* wout = (const float*)d_in[2];
    const float* bout = (const float*)d_in[3];
    float* out = (float*)d_out;

    cudaFuncSetAttribute(gemm_kernel<0>, cudaFuncAttributeMaxDynamicSharedMemorySize, 65536);
    cudaFuncSetAttribute(gemm_kernel<1>, cudaFuncAttributeMaxDynamicSharedMemorySize, 65536);
    cudaFuncSetAttribute(attn_kernel, cudaFuncAttributeMaxDynamicSharedMemorySize, 55296);

    const int total4 = 1048576 + 786432 + 262144;   // 2,097,152 float4 elements
    split_all_kernel<<<(total4 + 255) / 256, 256>>>(x, wqkv, wout);

    gemm_kernel<0><<<dim3(3 * DD / 128, MROWS / 128), 256, 65536>>>(nullptr, nullptr);
    attn_kernel<<<BH * (SS / 64), 256, 55296>>>();
    gemm_kernel<1><<<dim3(DD / 128, MROWS / 128), 256, 65536>>>(bout, out);
}

// round 16
// speedup vs baseline: 2.7849x; 1.0029x over previous
#include <cuda_runtime.h>
#include <cuda_bf16.h>

#define BB 2
#define SS 2048
#define DD 1024
#define HH 16
#define HD 64
#define BH (BB * HH)        // 32
#define MROWS (BB * SS)     // 4096

// ---------------------------------------------------------------------------
// Device scratch: bf16 hi/lo planes + fp32 logit spill
// ---------------------------------------------------------------------------
__device__ unsigned short g_xh[MROWS * DD],  g_xl[MROWS * DD];        // X split
__device__ unsigned short g_wqh[3 * DD * DD], g_wql[3 * DD * DD];     // Wqkv split
__device__ unsigned short g_woh[DD * DD],    g_wol[DD * DD];          // Wout split
__device__ unsigned short g_qh[BH * SS * HD], g_ql[BH * SS * HD];
__device__ unsigned short g_kh[BH * SS * HD], g_kl[BH * SS * HD];
__device__ unsigned short g_vh[BH * SS * HD], g_vl[BH * SS * HD];
__device__ unsigned short g_aoh[(size_t)MROWS * DD], g_aol[(size_t)MROWS * DD];
__device__ float g_logits[(size_t)BH * SS * SS];                      // 512 MB

// ---------------------------------------------------------------------------
// Helpers
// ---------------------------------------------------------------------------
__device__ __forceinline__ void split2(float f, unsigned short& h, unsigned short& l) {
    __nv_bfloat16 hb = __float2bfloat16(f);
    float r = f - __bfloat162float(hb);
    __nv_bfloat16 lb = __float2bfloat16(r);
    h = __bfloat16_as_ushort(hb);
    l = __bfloat16_as_ushort(lb);
}

__device__ __forceinline__ unsigned split_pack(float f) {
    unsigned short h, l;
    split2(f, h, l);
    return (unsigned)h | ((unsigned)l << 16);
}

__device__ __forceinline__ void mma_bf16(float* c,
                                         unsigned a0, unsigned a1, unsigned a2, unsigned a3,
                                         unsigned b0, unsigned b1) {
    asm volatile(
        "mma.sync.aligned.m16n8k16.row.col.f32.bf16.bf16.f32 "
        "{%0,%1,%2,%3},{%4,%5,%6,%7},{%8,%9},{%0,%1,%2,%3};\n"
        : "+f"(c[0]), "+f"(c[1]), "+f"(c[2]), "+f"(c[3])
        : "r"(a0), "r"(a1), "r"(a2), "r"(a3), "r"(b0), "r"(b1));
}

__device__ __forceinline__ void ldsm4(unsigned& r0, unsigned& r1, unsigned& r2, unsigned& r3,
                                      const void* p) {
    unsigned a = (unsigned)__cvta_generic_to_shared(p);
    asm volatile("ldmatrix.sync.aligned.m8n8.x4.shared.b16 {%0,%1,%2,%3},[%4];\n"
                 : "=r"(r0), "=r"(r1), "=r"(r2), "=r"(r3) : "r"(a));
}

__device__ __forceinline__ void ldsm4t(unsigned& r0, unsigned& r1, unsigned& r2, unsigned& r3,
                                       const void* p) {
    unsigned a = (unsigned)__cvta_generic_to_shared(p);
    asm volatile("ldmatrix.sync.aligned.m8n8.x4.trans.shared.b16 {%0,%1,%2,%3},[%4];\n"
                 : "=r"(r0), "=r"(r1), "=r"(r2), "=r"(r3) : "r"(a));
}

__device__ __forceinline__ void cp16(void* dst, const void* src) {
    unsigned d = (unsigned)__cvta_generic_to_shared(dst);
    asm volatile("cp.async.cg.shared.global [%0],[%1],16;\n" :: "r"(d), "l"(src));
}
__device__ __forceinline__ void cp_commit() { asm volatile("cp.async.commit_group;\n"); }
template <int N>
__device__ __forceinline__ void cp_wait() { asm volatile("cp.async.wait_group %0;\n" :: "n"(N)); }

__device__ __forceinline__ float stablemax_s(float x) {
    if (x >= 0.f) {
        return 1.f + x * (1.f + 0.5f * x * (1.f + x * (1.f / 3.f)));
    } else {
        return 1.f / (1.f - x * (1.f - 0.5f * x * (1.f - x * (1.f / 3.f))));
    }
}

// ---------------------------------------------------------------------------
// One-time split of ALL fp32 inputs -> bf16 hi/lo planes, single launch.
// ---------------------------------------------------------------------------
__global__ void split_all_kernel(const float* __restrict__ x,
                                 const float* __restrict__ wqkv,
                                 const float* __restrict__ wout) {
    int i = blockIdx.x * blockDim.x + threadIdx.x;
    const float* src;
    unsigned short *hi, *lo;
    int j;
    if (i < 1048576) {
        src = x; hi = g_xh; lo = g_xl; j = i;
    } else if (i < 1048576 + 786432) {
        src = wqkv; hi = g_wqh; lo = g_wql; j = i - 1048576;
    } else if (i < 1048576 + 786432 + 262144) {
        src = wout; hi = g_woh; lo = g_wol; j = i - (1048576 + 786432);
    } else {
        return;
    }
    float4 v = ((const float4*)src)[j];
    unsigned short h0, h1, h2, h3, l0, l1, l2, l3;
    split2(v.x, h0, l0); split2(v.y, h1, l1);
    split2(v.z, h2, l2); split2(v.w, h3, l3);
    uint2 ph, pl;
    ph.x = (unsigned)h0 | ((unsigned)h1 << 16); ph.y = (unsigned)h2 | ((unsigned)h3 << 16);
    pl.x = (unsigned)l0 | ((unsigned)l1 << 16); pl.y = (unsigned)l2 | ((unsigned)l3 << 16);
    ((uint2*)hi)[j] = ph;
    ((uint2*)lo)[j] = pl;
}

// ---------------------------------------------------------------------------
// GEMM: C[m,n] = sum_k A[m,k]*B[n,k], pre-split bf16 planes, 2-stage cp.async.
// CTA tile 128x128, 256 threads, 8 warps (2m x 4n), warp tile 64x32.
// Epilogue stages accumulators through smem -> fully coalesced stores.
// EPI 0: scatter to q/k/v planes (Q pre-scaled 0.125). EPI 1: +bias -> Cout.
// ---------------------------------------------------------------------------
template <int EPI>
__global__ __launch_bounds__(256)
void gemm_kernel(const float* __restrict__ bias, float* __restrict__ Cout) {
    extern __shared__ unsigned char dynsm[];

    const int tid = threadIdx.x, lane = tid & 31, warp = tid >> 5;
    const int wm = warp >> 2, wn = warp & 3;
    const int m0 = blockIdx.y << 7, n0 = blockIdx.x << 7;

    const unsigned short* AH = (EPI == 0) ? g_xh : g_aoh;
    const unsigned short* AL = (EPI == 0) ? g_xl : g_aol;
    const unsigned short* BH_ = (EPI == 0) ? g_wqh : g_woh;
    const unsigned short* BL_ = (EPI == 0) ? g_wql : g_wol;

    const int lr = tid >> 1;            // 0..127
    const int cb = (tid & 1) * 2;       // chunk base 0 or 2
    const unsigned short* srcs[4] = {
        AH + (size_t)(m0 + lr) * DD, AL + (size_t)(m0 + lr) * DD,
        BH_ + (size_t)(n0 + lr) * DD, BL_ + (size_t)(n0 + lr) * DD };

    const int rsw = (lr >> 1) & 3;      // writer swizzle term

    float acc[4][4][4];
#pragma unroll
    for (int a = 0; a < 4; ++a)
#pragma unroll
        for (int b = 0; b < 4; ++b)
#pragma unroll
            for (int r = 0; r < 4; ++r) acc[a][b][r] = 0.f;

    auto issue = [&](int stage, int kt) {
        unsigned char* sb = dynsm + stage * 32768 + lr * 64;
#pragma unroll
        for (int p = 0; p < 4; ++p) {
            const unsigned short* s = srcs[p] + kt * 32;
#pragma unroll
            for (int cc = 0; cc < 2; ++cc) {
                const int c = cb + cc;
                cp16(sb + p * 8192 + ((c ^ rsw) << 4), s + c * 8);
            }
        }
    };

    const int NKT = DD / 32;  // 32
    issue(0, 0);
    cp_commit();

    for (int kt = 0; kt < NKT; ++kt) {
        if (kt + 1 < NKT) { issue((kt + 1) & 1, kt + 1); cp_commit(); }
        if (kt + 1 < NKT) cp_wait<1>(); else cp_wait<0>();
        __syncthreads();

        const unsigned char* sb = dynsm + (kt & 1) * 32768;
        auto frag_addr = [&](int plane, int r, int halfcol) -> const void* {
            const int chunk = halfcol >> 3;
            return (const void*)(sb + plane * 8192 + r * 64 +
                                 ((chunk ^ ((r >> 1) & 3)) << 4));
        };

#pragma unroll
        for (int kb = 0; kb < 2; ++kb) {
            unsigned ah[4][4], al[4][4];
#pragma unroll
            for (int mb = 0; mb < 4; ++mb) {
                const int r = wm * 64 + mb * 16 + (lane & 15);
                const int c = kb * 16 + ((lane >> 4) << 3);
                ldsm4(ah[mb][0], ah[mb][1], ah[mb][2], ah[mb][3], frag_addr(0, r, c));
                ldsm4(al[mb][0], al[mb][1], al[mb][2], al[mb][3], frag_addr(1, r, c));
            }
            unsigned bhf[2][4], blf[2][4];
#pragma unroll
            for (int pr = 0; pr < 2; ++pr) {
                const int r = wn * 32 + pr * 16 + (lane & 7) + ((lane >> 4) << 3);
                const int c = kb * 16 + (((lane >> 3) & 1) << 3);
                ldsm4(bhf[pr][0], bhf[pr][1], bhf[pr][2], bhf[pr][3], frag_addr(2, r, c));
                ldsm4(blf[pr][0], blf[pr][1], blf[pr][2], blf[pr][3], frag_addr(3, r, c));
            }
#pragma unroll
            for (int mb = 0; mb < 4; ++mb)
#pragma unroll
                for (int nb = 0; nb < 4; ++nb)
                    mma_bf16(acc[mb][nb], ah[mb][0], ah[mb][1], ah[mb][2], ah[mb][3],
                             bhf[nb >> 1][(nb & 1) * 2], bhf[nb >> 1][(nb & 1) * 2 + 1]);
#pragma unroll
            for (int mb = 0; mb < 4; ++mb)
#pragma unroll
                for (int nb = 0; nb < 4; ++nb)
                    mma_bf16(acc[mb][nb], ah[mb][0], ah[mb][1], ah[mb][2], ah[mb][3],
                             blf[nb >> 1][(nb & 1) * 2], blf[nb >> 1][(nb & 1) * 2 + 1]);
#pragma unroll
            for (int mb = 0; mb < 4; ++mb)
#pragma unroll
                for (int nb = 0; nb < 4; ++nb)
                    mma_bf16(acc[mb][nb], al[mb][0], al[mb][1], al[mb][2], al[mb][3],
                             bhf[nb >> 1][(nb & 1) * 2], bhf[nb >> 1][(nb & 1) * 2 + 1]);
        }
        __syncthreads();
    }

    // ----- Epilogue: stage through smem, coalesced writes -----
    const int g = lane >> 2, e = lane & 3;
    float* sf = (float*)dynsm;          // staging: 64 rows x 136 floats (34816 B)

#pragma unroll
    for (int half = 0; half < 2; ++half) {
        __syncthreads();
        if (wm == half) {
#pragma unroll
            for (int mb = 0; mb < 4; ++mb)
#pragma unroll
                for (int nb = 0; nb < 4; ++nb) {
                    const int rl = mb * 16 + g;
                    const int cc = wn * 32 + nb * 8 + 2 * e;
                    *(float2*)&sf[rl * 136 + cc] =
                        make_float2(acc[mb][nb][0], acc[mb][nb][1]);
                    *(float2*)&sf[(rl + 8) * 136 + cc] =
                        make_float2(acc[mb][nb][2], acc[mb][nb][3]);
                }
        }
        __syncthreads();

#pragma unroll
        for (int it = 0; it < 8; ++it) {
            const int idx = it * 256 + tid;
            const int r = idx >> 5;            // 0..63
            const int gc = idx & 31;           // col group (4 floats)
            const int m = m0 + half * 64 + r;
            const int n = n0 + gc * 4;
            float4 v = *(float4*)&sf[r * 136 + gc * 4];
            if (EPI == 1) {
                const float4 bv = *(const float4*)(bias + n);
                v.x += bv.x; v.y += bv.y; v.z += bv.z; v.w += bv.w;
                *(float4*)&Cout[(size_t)m * DD + n] = v;
            } else {
                const int which = n >> 10;
                const int h = (n >> 6) & 15;
                const int d = n & 63;
                const int b = m >> 11;
                const int s = m & 2047;
                const float sc = (which == 0) ? 0.125f : 1.0f;  // exact Q pre-scale
                v.x *= sc; v.y *= sc; v.z *= sc; v.w *= sc;
                unsigned short h0, h1, h2, h3, l0, l1, l2, l3;
                split2(v.x, h0, l0); split2(v.y, h1, l1);
                split2(v.z, h2, l2); split2(v.w, h3, l3);
                uint2 ph, pl;
                ph.x = (unsigned)h0 | ((unsigned)h1 << 16);
                ph.y = (unsigned)h2 | ((unsigned)h3 << 16);
                pl.x = (unsigned)l0 | ((unsigned)l1 << 16);
                pl.y = (unsigned)l2 | ((unsigned)l3 << 16);
                unsigned short* dh = (which == 0) ? g_qh : ((which == 1) ? g_kh : g_vh);
                unsigned short* dl = (which == 0) ? g_ql : ((which == 1) ? g_kl : g_vl);
                const size_t ix = (size_t)((b * HH + h) * SS + s) * HD + d;
                *(uint2*)(dh + ix) = ph;
                *(uint2*)(dl + ix) = pl;
            }
        }
    }
}

// ---------------------------------------------------------------------------
// Attention: one CTA per (bh, 64-query block), 8 warps (4 q-groups x 2 k-halves).
// K/V tiles stream through a 2-stage cp.async pipeline: ONE barrier/tile.
// Phase 1: QK^T (HMMA) -> fp32 spill + row max. Phase 2: s(), rowsum, P@V.
// Dynamic smem (55296 B): Qhi@0, Qlo@9216, stage s: hi@18432+s*18432, lo=+9216.
// ---------------------------------------------------------------------------
__global__ __launch_bounds__(256)
void attn_kernel() {
    extern __shared__ unsigned char dynsm[];
    __shared__ float redA[2][64];
    __shared__ float rowred[64];

    typedef unsigned short usrow[72];
    usrow* Qhi = (usrow*)(dynsm);
    usrow* Qlo = (usrow*)(dynsm + 9216);
    typedef float frow[68];
    frow* Osm = (frow*)(dynsm);             // overlaps dead Q region at the end

    const int tid = threadIdx.x, lane = tid & 31, warp = tid >> 5;
    const int wm = warp >> 1, wk = warp & 1;
    const int bh = blockIdx.x >> 5;
    const int q0 = (blockIdx.x & 31) << 6;

    const size_t qbase = ((size_t)bh * SS + q0) * HD;
    const size_t kbase = (size_t)bh * SS * HD;
    float* Ls = g_logits + (size_t)blockIdx.x * (64 * SS);

    const int prow = tid >> 2;              // 0..63
    const int pcol = (tid & 3) << 3;        // 0,8,16,24

    auto issueKV = [&](const unsigned short* baseH, const unsigned short* baseL,
                       int tile, int stage) {
        unsigned char* sb = dynsm + 18432 + stage * 18432;
        const unsigned short* sh = baseH + (size_t)(tile * 64 + prow) * HD + pcol;
        const unsigned short* sl = baseL + (size_t)(tile * 64 + prow) * HD + pcol;
        cp16(sb + prow * 144 + pcol * 2, sh);
        cp16(sb + prow * 144 + pcol * 2 + 64, sh + 32);
        cp16(sb + 9216 + prow * 144 + pcol * 2, sl);
        cp16(sb + 9216 + prow * 144 + pcol * 2 + 64, sl + 32);
    };

    {
        const unsigned short* sh = g_qh + qbase + (size_t)prow * HD + pcol;
        const unsigned short* sl = g_ql + qbase + (size_t)prow * HD + pcol;
        *(uint4*)&Qhi[prow][pcol]      = *(const uint4*)(sh);
        *(uint4*)&Qhi[prow][pcol + 32] = *(const uint4*)(sh + 32);
        *(uint4*)&Qlo[prow][pcol]      = *(const uint4*)(sl);
        *(uint4*)&Qlo[prow][pcol + 32] = *(const uint4*)(sl + 32);
    }
    issueKV(g_kh + kbase, g_kl + kbase, 0, 0); cp_commit();
    __syncthreads();

    unsigned qh[4][4], ql[4][4];
#pragma unroll
    for (int kb = 0; kb < 4; ++kb) {
        const int r = wm * 16 + (lane & 15);
        const int c = kb * 16 + ((lane >> 4) << 3);
        ldsm4(qh[kb][0], qh[kb][1], qh[kb][2], qh[kb][3], &Qhi[r][c]);
        ldsm4(ql[kb][0], ql[kb][1], ql[kb][2], ql[kb][3], &Qlo[r][c]);
    }

    float rm0 = -1e30f, rm1 = -1e30f;
    const int NT = SS / 64;  // 32

    // ----------------- Phase 1 -----------------
    for (int ct = 0; ct < NT; ++ct) {
        cp_wait<0>();
        __syncthreads();
        if (ct + 1 < NT) { issueKV(g_kh + kbase, g_kl + kbase, ct + 1, (ct + 1) & 1); cp_commit(); }

        usrow* KH = (usrow*)(dynsm + 18432 + (ct & 1) * 18432);
        usrow* KL = (usrow*)(dynsm + 18432 + (ct & 1) * 18432 + 9216);

        float c[4][4];
#pragma unroll
        for (int nb = 0; nb < 4; ++nb)
#pragma unroll
            for (int r = 0; r < 4; ++r) c[nb][r] = 0.f;

#pragma unroll
        for (int kb = 0; kb < 4; ++kb) {
            unsigned bhf[2][4], blf[2][4];
#pragma unroll
            for (int pr = 0; pr < 2; ++pr) {
                const int r = wk * 32 + pr * 16 + (lane & 7) + ((lane >> 4) << 3);
                const int cc = kb * 16 + (((lane >> 3) & 1) << 3);
                ldsm4(bhf[pr][0], bhf[pr][1], bhf[pr][2], bhf[pr][3], &KH[r][cc]);
                ldsm4(blf[pr][0], blf[pr][1], blf[pr][2], blf[pr][3], &KL[r][cc]);
            }
#pragma unroll
            for (int nb = 0; nb < 4; ++nb)
                mma_bf16(c[nb], qh[kb][0], qh[kb][1], qh[kb][2], qh[kb][3],
                         bhf[nb >> 1][(nb & 1) * 2], bhf[nb >> 1][(nb & 1) * 2 + 1]);
#pragma unroll
            for (int nb = 0; nb < 4; ++nb)
                mma_bf16(c[nb], qh[kb][0], qh[kb][1], qh[kb][2], qh[kb][3],
                         blf[nb >> 1][(nb & 1) * 2], blf[nb >> 1][(nb & 1) * 2 + 1]);
#pragma unroll
            for (int nb = 0; nb < 4; ++nb)
                mma_bf16(c[nb], ql[kb][0], ql[kb][1], ql[kb][2], ql[kb][3],
                         bhf[nb >> 1][(nb & 1) * 2], bhf[nb >> 1][(nb & 1) * 2 + 1]);
        }

        float* base = Ls + (size_t)ct * 4096 + warp * 512 + lane * 4;
#pragma unroll
        for (int nb = 0; nb < 4; ++nb) {
            float4 v;
            v.x = c[nb][0]; v.y = c[nb][1]; v.z = c[nb][2]; v.w = c[nb][3];
            __stcs((float4*)(base + nb * 128), v);
            rm0 = fmaxf(rm0, fmaxf(v.x, v.y));
            rm1 = fmaxf(rm1, fmaxf(v.z, v.w));
        }
    }

    issueKV(g_vh + kbase, g_vl + kbase, 0, 0); cp_commit();

    rm0 = fmaxf(rm0, __shfl_xor_sync(0xffffffffu, rm0, 1));
    rm0 = fmaxf(rm0, __shfl_xor_sync(0xffffffffu, rm0, 2));
    rm1 = fmaxf(rm1, __shfl_xor_sync(0xffffffffu, rm1, 1));
    rm1 = fmaxf(rm1, __shfl_xor_sync(0xffffffffu, rm1, 2));
    const int g = lane >> 2;
    if ((lane & 3) == 0) {
        redA[wk][wm * 16 + g] = rm0;
        redA[wk][wm * 16 + g + 8] = rm1;
    }
    __syncthreads();
    if (tid < 64) rowred[tid] = fmaxf(redA[0][tid], redA[1][tid]);
    __syncthreads();
    const float rx0 = rowred[wm * 16 + g];
    const float rx1 = rowred[wm * 16 + g + 8];

    // ----------------- Phase 2 -----------------
    float O[8][4];
#pragma unroll
    for (int nb = 0; nb < 8; ++nb)
#pragma unroll
        for (int r = 0; r < 4; ++r) O[nb][r] = 0.f;
    float rs0 = 0.f, rs1 = 0.f;

    for (int ct = 0; ct < NT; ++ct) {
        float4 L[4];
        const float* sb = Ls + (size_t)ct * 4096 + warp * 512 + lane * 4;
#pragma unroll
        for (int nb = 0; nb < 4; ++nb) L[nb] = __ldcs((const float4*)(sb + nb * 128));

        cp_wait<0>();
        __syncthreads();
        if (ct + 1 < NT) { issueKV(g_vh + kbase, g_vl + kbase, ct + 1, (ct + 1) & 1); cp_commit(); }

        usrow* VH = (usrow*)(dynsm + 18432 + (ct & 1) * 18432);
        usrow* VL = (usrow*)(dynsm + 18432 + (ct & 1) * 18432 + 9216);

        unsigned sh2[2][4], sl2[2][4];
#pragma unroll
        for (int nb = 0; nb < 4; ++nb) {
            const float s0 = stablemax_s(L[nb].x - rx0);
            const float s1 = stablemax_s(L[nb].y - rx0);
            const float s2 = stablemax_s(L[nb].z - rx1);
            const float s3 = stablemax_s(L[nb].w - rx1);
            rs0 += s0 + s1;
            rs1 += s2 + s3;
            const unsigned u0 = split_pack(s0), u1 = split_pack(s1);
            const unsigned u2 = split_pack(s2), u3 = split_pack(s3);
            const int kbp = nb >> 1, half = nb & 1;
            sh2[kbp][half * 2]     = (u0 & 0xffffu) | ((u1 & 0xffffu) << 16);
            sh2[kbp][half * 2 + 1] = (u2 & 0xffffu) | ((u3 & 0xffffu) << 16);
            sl2[kbp][half * 2]     = (u0 >> 16) | (u1 & 0xffff0000u);
            sl2[kbp][half * 2 + 1] = (u2 >> 16) | (u3 & 0xffff0000u);
        }

#pragma unroll
        for (int kbp = 0; kbp < 2; ++kbp) {
            const int rbase = wk * 32 + kbp * 16 + (lane & 15);
            const int cbv = ((lane >> 4) << 3);
#pragma unroll
            for (int npp = 0; npp < 4; npp += 2) {
                unsigned vh[2][4], vl[2][4];
#pragma unroll
                for (int pi = 0; pi < 2; ++pi) {
                    ldsm4t(vh[pi][0], vh[pi][1], vh[pi][2], vh[pi][3],
                           &VH[rbase][(npp + pi) * 16 + cbv]);
                    ldsm4t(vl[pi][0], vl[pi][1], vl[pi][2], vl[pi][3],
                           &VL[rbase][(npp + pi) * 16 + cbv]);
                }
#pragma unroll
                for (int pi = 0; pi < 2; ++pi)
#pragma unroll
                    for (int q2 = 0; q2 < 2; ++q2)
                        mma_bf16(O[(npp + pi) * 2 + q2],
                                 sh2[kbp][0], sh2[kbp][1], sh2[kbp][2], sh2[kbp][3],
                                 vh[pi][q2 * 2], vh[pi][q2 * 2 + 1]);
#pragma unroll
                for (int pi = 0; pi < 2; ++pi)
#pragma unroll
                    for (int q2 = 0; q2 < 2; ++q2)
                        mma_bf16(O[(npp + pi) * 2 + q2],
                                 sh2[kbp][0], sh2[kbp][1], sh2[kbp][2], sh2[kbp][3],
                                 vl[pi][q2 * 2], vl[pi][q2 * 2 + 1]);
#pragma unroll
                for (int pi = 0; pi < 2; ++pi)
#pragma unroll
                    for (int q2 = 0; q2 < 2; ++q2)
                        mma_bf16(O[(npp + pi) * 2 + q2],
                                 sl2[kbp][0], sl2[kbp][1], sl2[kbp][2], sl2[kbp][3],
                                 vh[pi][q2 * 2], vh[pi][q2 * 2 + 1]);
            }
        }
    }

    rs0 += __shfl_xor_sync(0xffffffffu, rs0, 1);
    rs0 += __shfl_xor_sync(0xffffffffu, rs0, 2);
    rs1 += __shfl_xor_sync(0xffffffffu, rs1, 1);
    rs1 += __shfl_xor_sync(0xffffffffu, rs1, 2);
    if ((lane & 3) == 0) {
        redA[wk][wm * 16 + g] = rs0;
        redA[wk][wm * 16 + g + 8] = rs1;
    }
    __syncthreads();
    if (tid < 64) rowred[tid] = redA[0][tid] + redA[1][tid];
    __syncthreads();

    const int e = lane & 3;
    if (wk == 0) {
#pragma unroll
        for (int nb = 0; nb < 8; ++nb)
#pragma unroll
            for (int r = 0; r < 4; ++r)
                Osm[wm * 16 + g + ((r >> 1) << 3)][nb * 8 + 2 * e + (r & 1)] = O[nb][r];
    }
    __syncthreads();
    if (wk == 1) {
#pragma unroll
        for (int nb = 0; nb < 8; ++nb)
#pragma unroll
            for (int r = 0; r < 4; ++r)
                Osm[wm * 16 + g + ((r >> 1) << 3)][nb * 8 + 2 * e + (r & 1)] += O[nb][r];
    }
    __syncthreads();

    const int b = bh >> 4;
    const int h = bh & 15;
    const int trow = tid >> 4;
    const int tcol = (tid & 15) << 2;
#pragma unroll
    for (int p = 0; p < 4; ++p) {
        const int q = p * 16 + trow;
        float4 v = *(float4*)&Osm[q][tcol];
        const float inv = 1.0f / rowred[q];
        v.x *= inv; v.y *= inv; v.z *= inv; v.w *= inv;
        unsigned short h0, h1, h2, h3, l0, l1, l2, l3;
        split2(v.x, h0, l0); split2(v.y, h1, l1);
        split2(v.z, h2, l2); split2(v.w, h3, l3);
        const size_t idx = (size_t)(b * SS + q0 + q) * DD + h * HD + tcol;
        uint2 ph, pl;
        ph.x = (unsigned)h0 | ((unsigned)h1 << 16); ph.y = (unsigned)h2 | ((unsigned)h3 << 16);
        pl.x = (unsigned)l0 | ((unsigned)l1 << 16); pl.y = (unsigned)l2 | ((unsigned)l3 << 16);
        *(uint2*)(g_aoh + idx) = ph;
        *(uint2*)(g_aol + idx) = pl;
    }
}

// ---------------------------------------------------------------------------
// Launch
// ---------------------------------------------------------------------------
extern "C" void kernel_launch(void* const* d_in, const int* in_sizes, int n_in,
                              void* d_out, int out_size) {
    (void)in_sizes; (void)n_in; (void)out_size;
    const float* x    = (const float*)d_in[0];
    const float* wqkv = (const float*)d_in[1];
    const float* wout = (const float*)d_in[2];
    const float* bout = (const float*)d_in[3];
    float* out = (float*)d_out;

    cudaFuncSetAttribute(gemm_kernel<0>, cudaFuncAttributeMaxDynamicSharedMemorySize, 65536);
    cudaFuncSetAttribute(gemm_kernel<1>, cudaFuncAttributeMaxDynamicSharedMemorySize, 65536);
    cudaFuncSetAttribute(attn_kernel, cudaFuncAttributeMaxDynamicSharedMemorySize, 55296);

    const int total4 = 1048576 + 786432 + 262144;   // 2,097,152 float4 elements
    split_all_kernel<<<(total4 + 255) / 256, 256>>>(x, wqkv, wout);

    gemm_kernel<0><<<dim3(3 * DD / 128, MROWS / 128), 256, 65536>>>(nullptr, nullptr);
    attn_kernel<<<BH * (SS / 64), 256, 55296>>>();
    gemm_kernel<1><<<dim3(DD / 128, MROWS / 128), 256, 65536>>>(bout, out);
}